// round 4
// baseline (speedup 1.0000x reference)
#include <cuda_runtime.h>

#define TPB    512
#define NPG    150      // nodes per graph
#define ROWP   152      // padded row length (multiple of 4, cols 150/151 zero)
#define HID    64
#define CL     25
#define CP     26       // padded cluster stride
#define NFEAT  128
#define NCLS   10
#define NTOT   9600

// ---- shared memory layout (float offsets) ----
#define OFF_AH    0                          // 150*152 = 22800  (A block + I, padded cols)
#define OFF_DIS   (OFF_AH   + NPG*ROWP)      // 152
#define OFF_BUFA  (OFF_DIS  + ROWP)          // 152*64 = 9728 (rows 150/151 zero)
#define OFF_BUFB  (OFF_BUFA + ROWP*HID)      // 150*64 = 9600 (also staging region)
#define OFF_SMAT  (OFF_BUFB + NPG*HID)       // 152*26 = 3952 (rows 150/151 zero)
#define OFF_ZP    (OFF_SMAT + ROWP*CP)       // 25*64  = 1600
#define OFF_AP    (OFF_ZP   + CL*HID)        // 25*26  = 650
#define OFF_DISP  (OFF_AP   + CL*CP)         // 32
#define OFF_GV    (OFF_DISP + 32)            // 64
#define SMEM_FLOATS (OFF_GV + 64)            // 48578 floats = 194312 B

// Aggregate out[i][h] = act(dis[i] * sum_j ah[i][j] * in[j][h] + bias[h])
// in must have rows 150/151 finite (zeroed); ah cols 150/151 are zero.
template<bool RELU>
__device__ __forceinline__ void agg_rows64(const float* AH, const float* DIS,
                                           const float* in, float* outp,
                                           const float* __restrict__ bias, int tid)
{
    const int h   = tid & (HID - 1);
    const int grp = tid >> 6;            // 0..7
#pragma unroll
    for (int o = 0; o < 3; ++o) {
        int i0 = o * 64 + grp * 8;
        if (i0 >= NPG) continue;
        int ao[8];
#pragma unroll
        for (int r = 0; r < 8; ++r) ao[r] = min(i0 + r, NPG - 1) * ROWP;
        float acc[8];
#pragma unroll
        for (int r = 0; r < 8; ++r) acc[r] = 0.f;
        for (int j = 0; j < ROWP; j += 4) {
            float z0 = in[(j + 0) * HID + h];
            float z1 = in[(j + 1) * HID + h];
            float z2 = in[(j + 2) * HID + h];
            float z3 = in[(j + 3) * HID + h];
#pragma unroll
            for (int r = 0; r < 8; ++r) {
                float4 av = *(const float4*)(AH + ao[r] + j);
                acc[r] += av.x * z0 + av.y * z1 + av.z * z2 + av.w * z3;
            }
        }
        float bh = bias[h];
#pragma unroll
        for (int r = 0; r < 8; ++r) {
            int i = i0 + r;
            if (i < NPG) {
                float v = DIS[i] * acc[r] + bh;
                outp[i * HID + h] = RELU ? fmaxf(v, 0.f) : v;
            }
        }
    }
}

__global__ void __launch_bounds__(TPB, 1)
gcn_diffpool(const float* __restrict__ x,  const float* __restrict__ a,
             const float* __restrict__ W1, const float* __restrict__ b1,
             const float* __restrict__ W2, const float* __restrict__ b2,
             const float* __restrict__ Wa, const float* __restrict__ ba,
             const float* __restrict__ Wp, const float* __restrict__ bp,
             const float* __restrict__ Wc, const float* __restrict__ bc,
             float* __restrict__ out)
{
    extern __shared__ float sm[];
    float* AH   = sm + OFF_AH;
    float* DIS  = sm + OFF_DIS;
    float* BA   = sm + OFF_BUFA;
    float* BB   = sm + OFF_BUFB;
    float* SMT  = sm + OFF_SMAT;
    float* ZP   = sm + OFF_ZP;
    float* AP   = sm + OFF_AP;
    float* DISP = sm + OFF_DISP;
    float* GV   = sm + OFF_GV;

    const int tid  = threadIdx.x;
    const int g    = blockIdx.x;
    const int base = g * NPG;
    const int h    = tid & (HID - 1);
    const int grp  = tid >> 6;   // 0..7
    const int c32  = tid & 31;
    const int g2   = tid >> 5;   // 0..15

    // ---------- Phase A: load adjacency block + I (padded), zero pads ----------
    for (int idx = tid; idx < NPG * ROWP; idx += TPB) {
        int i = idx / ROWP, j = idx - i * ROWP;
        float v = 0.f;
        if (j < NPG) {
            v = a[(size_t)(base + i) * NTOT + base + j];
            if (i == j) v += 1.0f;
        }
        AH[idx] = v;
    }
    if (tid < 2 * HID) BA[NPG * HID + tid] = 0.f;     // bufA pad rows
    if (tid < 2 * CP)  SMT[NPG * CP + tid] = 0.f;     // Smat pad rows
    __syncthreads();

    // degrees -> D^{-1/2}
    for (int i = tid; i < NPG; i += TPB) {
        float s = 0.f;
        const float* r = AH + i * ROWP;
        for (int j = 0; j < NPG; ++j) s += r[j];
        DIS[i] = rsqrtf(fmaxf(s, 1e-12f));
    }
    __syncthreads();

    // ---------- Phase B: bufA[j][h] = dis[j] * (x[j] . W1[:,h]), staged ----------
    {
        float acc[3][8];
#pragma unroll
        for (int o = 0; o < 3; ++o)
#pragma unroll
            for (int r = 0; r < 8; ++r) acc[o][r] = 0.f;
        float* xst = BB;              // 150*32
        float* wst = BB + NPG * 32;   // 32*64
        for (int kc = 0; kc < NFEAT; kc += 32) {
            __syncthreads();
            for (int idx = tid; idx < NPG * 32; idx += TPB) {
                int j = idx >> 5, kk = idx & 31;
                xst[idx] = x[(size_t)(base + j) * NFEAT + kc + kk];
            }
            for (int idx = tid; idx < 32 * HID; idx += TPB)
                wst[idx] = W1[(kc + (idx >> 6)) * HID + (idx & 63)];
            __syncthreads();
#pragma unroll
            for (int o = 0; o < 3; ++o) {
                int i0 = o * 64 + grp * 8;
                if (i0 >= NPG) continue;
                int rw[8];
#pragma unroll
                for (int r = 0; r < 8; ++r) rw[r] = min(i0 + r, NPG - 1) * 32;
                for (int kk = 0; kk < 32; kk += 4) {
                    float w0 = wst[(kk + 0) * HID + h];
                    float w1 = wst[(kk + 1) * HID + h];
                    float w2 = wst[(kk + 2) * HID + h];
                    float w3 = wst[(kk + 3) * HID + h];
#pragma unroll
                    for (int r = 0; r < 8; ++r) {
                        float4 xv = *(const float4*)(xst + rw[r] + kk);
                        acc[o][r] += xv.x * w0 + xv.y * w1 + xv.z * w2 + xv.w * w3;
                    }
                }
            }
        }
        __syncthreads();
#pragma unroll
        for (int o = 0; o < 3; ++o) {
            int i0 = o * 64 + grp * 8;
#pragma unroll
            for (int r = 0; r < 8; ++r) {
                int j = i0 + r;
                if (j < NPG) BA[j * HID + h] = acc[o][r] * DIS[j];
            }
        }
    }
    __syncthreads();

    // ---------- Phase C1: Z1 = relu(D^-1/2 Ah D^-1/2 (XW1) + b1) -> bufB ----------
    agg_rows64<true>(AH, DIS, BA, BB, b1, tid);
    __syncthreads();

    // ---------- Phase D: bufA[j][h] = dis[j] * (Z1[j] . W2[:,h]) ----------
    {
        float acc[3][8];
#pragma unroll
        for (int o = 0; o < 3; ++o)
#pragma unroll
            for (int r = 0; r < 8; ++r) acc[o][r] = 0.f;
        float* wst = SMT;   // stage W2 chunks (2048 floats, leaves pad rows untouched)
        for (int kc = 0; kc < HID; kc += 32) {
            __syncthreads();
            for (int idx = tid; idx < 32 * HID; idx += TPB)
                wst[idx] = W2[(kc + (idx >> 6)) * HID + (idx & 63)];
            __syncthreads();
#pragma unroll
            for (int o = 0; o < 3; ++o) {
                int i0 = o * 64 + grp * 8;
                if (i0 >= NPG) continue;
                int rw[8];
#pragma unroll
                for (int r = 0; r < 8; ++r) rw[r] = min(i0 + r, NPG - 1) * HID;
                for (int kk = 0; kk < 32; kk += 4) {
                    float w0 = wst[(kk + 0) * HID + h];
                    float w1 = wst[(kk + 1) * HID + h];
                    float w2 = wst[(kk + 2) * HID + h];
                    float w3 = wst[(kk + 3) * HID + h];
#pragma unroll
                    for (int r = 0; r < 8; ++r) {
                        float4 zv = *(const float4*)(BB + rw[r] + kc + kk);
                        acc[o][r] += zv.x * w0 + zv.y * w1 + zv.z * w2 + zv.w * w3;
                    }
                }
            }
        }
        __syncthreads();
#pragma unroll
        for (int o = 0; o < 3; ++o) {
            int i0 = o * 64 + grp * 8;
#pragma unroll
            for (int r = 0; r < 8; ++r) {
                int j = i0 + r;
                if (j < NPG) BA[j * HID + h] = acc[o][r] * DIS[j];
            }
        }
    }
    __syncthreads();

    // ---------- Phase C2: Z2 = relu(...) -> bufB ----------
    agg_rows64<true>(AH, DIS, BA, BB, b2, tid);
    __syncthreads();

    // ---------- Phase E: tmpS[j][c] = dis[j]*(Z2[j] . Wa[:,c]) -> SMT ----------
    for (int idx = tid; idx < HID * CL; idx += TPB) ZP[idx] = Wa[idx];  // stage Wa
    __syncthreads();
    {
#pragma unroll
        for (int o = 0; o < 3; ++o) {
            int j0 = o * 64 + g2 * 4;
            if (j0 >= NPG) continue;
            int rw[4];
#pragma unroll
            for (int r = 0; r < 4; ++r) rw[r] = min(j0 + r, NPG - 1) * HID;
            float acc[4] = {0.f, 0.f, 0.f, 0.f};
            for (int k = 0; k < HID; k += 4) {
                float w0 = ZP[(k + 0) * CL + c32];
                float w1 = ZP[(k + 1) * CL + c32];
                float w2 = ZP[(k + 2) * CL + c32];
                float w3 = ZP[(k + 3) * CL + c32];
#pragma unroll
                for (int r = 0; r < 4; ++r) {
                    float4 zv = *(const float4*)(BB + rw[r] + k);
                    acc[r] += zv.x * w0 + zv.y * w1 + zv.z * w2 + zv.w * w3;
                }
            }
            if (c32 < CL) {
#pragma unroll
                for (int r = 0; r < 4; ++r) {
                    int j = j0 + r;
                    if (j < NPG) SMT[j * CP + c32] = acc[r] * DIS[j];
                }
            }
        }
    }
    __syncthreads();

    // ---------- Phase F: assignment logits -> bufA[i][c] ----------
    {
#pragma unroll
        for (int o = 0; o < 3; ++o) {
            int i0 = o * 64 + g2 * 4;
            if (i0 >= NPG) continue;
            int ao[4];
#pragma unroll
            for (int r = 0; r < 4; ++r) ao[r] = min(i0 + r, NPG - 1) * ROWP;
            float acc[4] = {0.f, 0.f, 0.f, 0.f};
            for (int j = 0; j < ROWP; j += 4) {
                float s0 = SMT[(j + 0) * CP + c32];
                float s1 = SMT[(j + 1) * CP + c32];
                float s2 = SMT[(j + 2) * CP + c32];
                float s3 = SMT[(j + 3) * CP + c32];
#pragma unroll
                for (int r = 0; r < 4; ++r) {
                    float4 av = *(const float4*)(AH + ao[r] + j);
                    acc[r] += av.x * s0 + av.y * s1 + av.z * s2 + av.w * s3;
                }
            }
            if (c32 < CL) {
                float bac = ba[c32];
#pragma unroll
                for (int r = 0; r < 4; ++r) {
                    int i = i0 + r;
                    if (i < NPG) BA[i * HID + c32] = DIS[i] * acc[r] + bac;
                }
            }
        }
    }
    __syncthreads();

    // ---------- Phase G: row softmax -> SMT (the assignment S) ----------
    if (tid < NPG) {
        const float* lr = BA + tid * HID;
        float m = lr[0];
#pragma unroll
        for (int c = 1; c < CL; ++c) m = fmaxf(m, lr[c]);
        float e[CL], s = 0.f;
#pragma unroll
        for (int c = 0; c < CL; ++c) { e[c] = expf(lr[c] - m); s += e[c]; }
        float inv = 1.f / s;
#pragma unroll
        for (int c = 0; c < CL; ++c) SMT[tid * CP + c] = e[c] * inv;
    }
    __syncthreads();

    // ---------- Phase H: Zp[c][h] = sum_j S[j][c] * Z2[j][h] ----------
    {
        float acc[4] = {0.f, 0.f, 0.f, 0.f};
        for (int j = 0; j < NPG; ++j) {
            float z = BB[j * HID + h];
#pragma unroll
            for (int o = 0; o < 4; ++o)
                acc[o] += SMT[j * CP + (grp + 8 * o)] * z;
        }
#pragma unroll
        for (int o = 0; o < 4; ++o) {
            int c = grp + 8 * o;
            if (c < CL) ZP[c * HID + h] = acc[o];
        }
    }
    __syncthreads();

    // ---------- Phase I: AS[i][c] = (a @ S)[i][c] = (ah @ S) - S -> bufA ----------
    {
#pragma unroll
        for (int o = 0; o < 3; ++o) {
            int i0 = o * 64 + g2 * 4;
            if (i0 >= NPG) continue;
            int ao[4];
#pragma unroll
            for (int r = 0; r < 4; ++r) ao[r] = min(i0 + r, NPG - 1) * ROWP;
            float acc[4] = {0.f, 0.f, 0.f, 0.f};
            for (int j = 0; j < ROWP; j += 4) {
                float s0 = SMT[(j + 0) * CP + c32];
                float s1 = SMT[(j + 1) * CP + c32];
                float s2 = SMT[(j + 2) * CP + c32];
                float s3 = SMT[(j + 3) * CP + c32];
#pragma unroll
                for (int r = 0; r < 4; ++r) {
                    float4 av = *(const float4*)(AH + ao[r] + j);
                    acc[r] += av.x * s0 + av.y * s1 + av.z * s2 + av.w * s3;
                }
            }
            if (c32 < CL) {
#pragma unroll
                for (int r = 0; r < 4; ++r) {
                    int i = i0 + r;
                    if (i < NPG) BA[i * HID + c32] = acc[r] - SMT[i * CP + c32];
                }
            }
        }
    }
    __syncthreads();

    // ---------- Phase J: Ap[c][d] = sum_j S[j][c] * AS[j][d] ----------
    for (int idx = tid; idx < CL * CL; idx += TPB) {
        int cc = idx / CL, d = idx - cc * CL;
        float acc = 0.f;
        for (int j = 0; j < NPG; ++j)
            acc += SMT[j * CP + cc] * BA[j * HID + d];
        AP[cc * CP + d] = acc;
    }
    __syncthreads();

    // ---------- Phase K: pooled degrees ----------
    if (tid < CL) {
        float s = 1.0f;   // + self loop
        for (int d = 0; d < CL; ++d) s += AP[tid * CP + d];
        DISP[tid] = rsqrtf(fmaxf(s, 1e-12f));
    }
    __syncthreads();

    // ---------- Phase L: bufA[c][h] = disp[c]*(Zp[c] . Wp[:,h]) ----------
    for (int idx = tid; idx < HID * HID; idx += TPB) BB[idx] = Wp[idx];  // stage Wp
    __syncthreads();
    for (int idx = tid; idx < CL * HID; idx += TPB) {
        int cc = idx >> 6, hh = idx & 63;
        float acc = 0.f;
        for (int k = 0; k < HID; k += 4) {
            float4 zv = *(const float4*)(ZP + cc * HID + k);
            acc += zv.x * BB[(k + 0) * HID + hh] + zv.y * BB[(k + 1) * HID + hh]
                 + zv.z * BB[(k + 2) * HID + hh] + zv.w * BB[(k + 3) * HID + hh];
        }
        BA[cc * HID + hh] = acc * DISP[cc];
    }
    __syncthreads();

    // ---------- Phase M: H = relu(disp[i]*sum_c (Ap+I)[i][c]*bufA[c][h] + bp) -> ZP ----------
    for (int idx = tid; idx < CL * HID; idx += TPB) {
        int i = idx >> 6, hh = idx & 63;
        float acc = 0.f;
#pragma unroll
        for (int cc = 0; cc < CL; ++cc) {
            float av = AP[i * CP + cc] + ((i == cc) ? 1.f : 0.f);
            acc += av * BA[cc * HID + hh];
        }
        ZP[i * HID + hh] = fmaxf(DISP[i] * acc + bp[hh], 0.f);
    }
    __syncthreads();

    // ---------- Phase N: readout sum over pooled nodes ----------
    if (tid < HID) {
        float s = 0.f;
#pragma unroll
        for (int i = 0; i < CL; ++i) s += ZP[i * HID + tid];
        GV[tid] = s;
    }
    __syncthreads();

    // ---------- Phase O: logits ----------
    if (tid < NCLS) {
        float acc = bc[tid];
#pragma unroll
        for (int k = 0; k < HID; ++k) acc += GV[k] * Wc[k * NCLS + tid];
        out[g * NCLS + tid] = acc;
    }
}

extern "C" void kernel_launch(void* const* d_in, const int* in_sizes, int n_in,
                              void* d_out, int out_size)
{
    const float* x  = (const float*)d_in[0];
    const float* a  = (const float*)d_in[1];
    // d_in[2] = seg_ids (contiguous repeat, implied by layout), d_in[3] = num_graphs
    const float* W1 = (const float*)d_in[4];
    const float* b1 = (const float*)d_in[5];
    const float* W2 = (const float*)d_in[6];
    const float* b2 = (const float*)d_in[7];
    const float* Wa = (const float*)d_in[8];
    const float* ba = (const float*)d_in[9];
    const float* Wp = (const float*)d_in[10];
    const float* bp = (const float*)d_in[11];
    const float* Wc = (const float*)d_in[12];
    const float* bc = (const float*)d_in[13];
    float* out = (float*)d_out;

    int B = out_size / NCLS;   // 64 graphs
    size_t smem = (size_t)SMEM_FLOATS * sizeof(float);
    cudaFuncSetAttribute(gcn_diffpool, cudaFuncAttributeMaxDynamicSharedMemorySize, (int)smem);
    gcn_diffpool<<<B, TPB, smem>>>(x, a, W1, b1, W2, b2, Wa, ba, Wp, bp, Wc, bc, out);
}

// round 6
// speedup vs baseline: 1.3905x; 1.3905x over previous
#include <cuda_runtime.h>
#include <cstdint>

#define TPB    512
#define NPG    150      // nodes per graph
#define ROWP   152      // padded row length
#define HALF   75       // rows per CTA (2 CTAs per graph)
#define HID    64
#define CL     25
#define CP     26       // padded cluster stride
#define NFEAT  128
#define NCLS   10
#define NTOT   9600

// ---- shared memory layout (float offsets) ----
#define OFF_AHL   0                          // 75*152 = 11400 (own half of A+I, padded cols)
#define OFF_DIS   (OFF_AHL + HALF*ROWP)      // 80  (own rows' D^-1/2)
#define OFF_BUFA  (OFF_DIS  + 80)            // 152*64 = 9728 (full, pad rows zero)
#define OFF_BUFB  (OFF_BUFA + ROWP*HID)      // 152*64 = 9728 (full, also staging)
#define OFF_SMT   (OFF_BUFB + ROWP*HID)      // 152*26 = 3952 (full, pad rows zero)
#define OFF_ZP    (OFF_SMT  + ROWP*CP)       // 25*64 = 1600 (Wa staging, then Zp, then H)
#define OFF_AP    (OFF_ZP   + CL*HID)        // 25*26 = 650
#define OFF_DISP  (OFF_AP   + CL*CP)         // 32
#define OFF_GV    (OFF_DISP + 32)            // 64
#define SMEM_FLOATS (OFF_GV + 64)            // 37234 floats = 148936 B

#define CLUSTER_SYNC() do { \
    asm volatile("barrier.cluster.arrive.aligned;" ::: "memory"); \
    asm volatile("barrier.cluster.wait.aligned;"   ::: "memory"); } while (0)

__device__ __forceinline__ unsigned int smem_u32(const void* p) {
    unsigned int a;
    asm("{ .reg .u64 t; cvta.to.shared.u64 t, %1; cvt.u32.u64 %0, t; }"
        : "=r"(a) : "l"(p));
    return a;
}
__device__ __forceinline__ void st_rem(unsigned int addr, float v) {
    asm volatile("st.shared::cluster.f32 [%0], %1;" :: "r"(addr), "f"(v));
}

// agg: out[i][h] = act(dis[i] * sum_j ahl[l][j]*in[j][h] + bias[h]) for own rows,
// written to local AND peer smem copies.
template<bool RELU>
__device__ __forceinline__ void agg_half(float* sm, const float* AHL, const float* DISL,
                                         const float* in, int out_off,
                                         const float* __restrict__ bias,
                                         int tid, int row0, unsigned int rbase)
{
    const int h = tid & 63, grp = tid >> 6;   // 8 groups x 10 rows
    int lrow[10];
#pragma unroll
    for (int r = 0; r < 10; ++r) lrow[r] = min(grp * 10 + r, HALF - 1) * ROWP;
    float acc[10];
#pragma unroll
    for (int r = 0; r < 10; ++r) acc[r] = 0.f;
    for (int j = 0; j < ROWP; j += 4) {
        float z0 = in[(j + 0) * HID + h];
        float z1 = in[(j + 1) * HID + h];
        float z2 = in[(j + 2) * HID + h];
        float z3 = in[(j + 3) * HID + h];
#pragma unroll
        for (int r = 0; r < 10; ++r) {
            float4 av = *(const float4*)(AHL + lrow[r] + j);
            acc[r] += av.x * z0 + av.y * z1 + av.z * z2 + av.w * z3;
        }
    }
    float bh = bias[h];
#pragma unroll
    for (int r = 0; r < 10; ++r) {
        int l = grp * 10 + r;
        if (l < HALF) {
            float v = DISL[l] * acc[r] + bh;
            if (RELU) v = fmaxf(v, 0.f);
            int fo = out_off + (row0 + l) * HID + h;
            sm[fo] = v;
            st_rem(rbase + 4u * (unsigned int)fo, v);
        }
    }
}

__global__ void __launch_bounds__(TPB, 1) __cluster_dims__(2, 1, 1)
gcn_diffpool(const float* __restrict__ x,  const float* __restrict__ a,
             const float* __restrict__ W1, const float* __restrict__ b1,
             const float* __restrict__ W2, const float* __restrict__ b2,
             const float* __restrict__ Wa, const float* __restrict__ ba,
             const float* __restrict__ Wp, const float* __restrict__ bp,
             const float* __restrict__ Wc, const float* __restrict__ bc,
             float* __restrict__ out)
{
    extern __shared__ float sm[];
    float* AHL  = sm + OFF_AHL;
    float* DISL = sm + OFF_DIS;
    float* BA   = sm + OFF_BUFA;
    float* BB   = sm + OFF_BUFB;
    float* SMT  = sm + OFF_SMT;
    float* ZP   = sm + OFF_ZP;
    float* AP   = sm + OFF_AP;
    float* DISP = sm + OFF_DISP;
    float* GV   = sm + OFF_GV;

    const int tid  = threadIdx.x;
    const int g    = blockIdx.x >> 1;
    const int base = g * NPG;
    const int h    = tid & 63;
    const int grp  = tid >> 6;              // 0..7
    const int c32  = tid & 31;
    const int g2   = tid >> 5;              // 0..15
    const int cidx = min(c32, CL - 1);

    unsigned int rank;
    asm("mov.u32 %0, %%cluster_ctarank;" : "=r"(rank));
    const int row0 = (int)rank * HALF;
    unsigned int rbase;
    {
        unsigned int lbase = smem_u32(sm);
        unsigned int peer = rank ^ 1u;
        asm("mapa.shared::cluster.u32 %0, %1, %2;" : "=r"(rbase) : "r"(lbase), "r"(peer));
    }

    // ---------- Phase A: load own half of A+I, zero pads ----------
    for (int idx = tid; idx < HALF * ROWP; idx += TPB) {
        int l = idx / ROWP, j = idx - l * ROWP;
        float v = 0.f;
        if (j < NPG) {
            v = a[(size_t)(base + row0 + l) * NTOT + base + j];
            if (row0 + l == j) v += 1.0f;
        }
        AHL[idx] = v;
    }
    if (tid < 2 * HID) { BA[NPG * HID + tid] = 0.f; BB[NPG * HID + tid] = 0.f; }
    if (tid < 2 * CP)  SMT[NPG * CP + tid] = 0.f;
    __syncthreads();

    if (tid < HALF) {
        float s = 0.f;
        const float* r = AHL + tid * ROWP;
        for (int j = 0; j < NPG; ++j) s += r[j];
        DISL[tid] = rsqrtf(fmaxf(s, 1e-12f));
    }

    // ---------- Phase B: BA[j][h] = dis[j]*(x[j].W1[:,h]) for own j (staged) ----------
    {
        int lc[10];
#pragma unroll
        for (int r = 0; r < 10; ++r) lc[r] = min(grp * 10 + r, HALF - 1) * 32;
        float acc[10];
#pragma unroll
        for (int r = 0; r < 10; ++r) acc[r] = 0.f;
        float* xst = BB;               // 75*32 = 2400
        float* wst = BB + HALF * 32;   // 32*64 = 2048  (< BB pad rows)
        for (int kc = 0; kc < NFEAT; kc += 32) {
            __syncthreads();
            for (int idx = tid; idx < HALF * 32; idx += TPB)
                xst[idx] = x[(size_t)(base + row0 + (idx >> 5)) * NFEAT + kc + (idx & 31)];
            for (int idx = tid; idx < 32 * HID; idx += TPB)
                wst[idx] = W1[(kc + (idx >> 6)) * HID + (idx & 63)];
            __syncthreads();
            for (int kk = 0; kk < 32; kk += 4) {
                float w0 = wst[(kk + 0) * HID + h];
                float w1 = wst[(kk + 1) * HID + h];
                float w2 = wst[(kk + 2) * HID + h];
                float w3 = wst[(kk + 3) * HID + h];
#pragma unroll
                for (int r = 0; r < 10; ++r) {
                    float4 xv = *(const float4*)(xst + lc[r] + kk);
                    acc[r] += xv.x * w0 + xv.y * w1 + xv.z * w2 + xv.w * w3;
                }
            }
        }
        __syncthreads();
#pragma unroll
        for (int r = 0; r < 10; ++r) {
            int l = grp * 10 + r;
            if (l < HALF) {
                float v = acc[r] * DISL[l];
                int fo = OFF_BUFA + (row0 + l) * HID + h;
                sm[fo] = v;
                st_rem(rbase + 4u * (unsigned int)fo, v);
            }
        }
    }
    CLUSTER_SYNC();

    // ---------- Phase C1: Z1 = relu(agg(BA)) -> BB (both copies) ----------
    agg_half<true>(sm, AHL, DISL, BA, OFF_BUFB, b1, tid, row0, rbase);
    CLUSTER_SYNC();

    // ---------- Phase D: BA[j][h] = dis[j]*(Z1[j].W2[:,h]) for own j ----------
    {
        int lz[10];
#pragma unroll
        for (int r = 0; r < 10; ++r) lz[r] = (row0 + min(grp * 10 + r, HALF - 1)) * HID;
        float acc[10];
#pragma unroll
        for (int r = 0; r < 10; ++r) acc[r] = 0.f;
        float* wst = SMT;   // 2048 floats staging (rows < 79, rewritten by E)
        for (int kc = 0; kc < HID; kc += 32) {
            __syncthreads();
            for (int idx = tid; idx < 32 * HID; idx += TPB)
                wst[idx] = W2[(kc + (idx >> 6)) * HID + (idx & 63)];
            __syncthreads();
            for (int kk = 0; kk < 32; kk += 4) {
                float w0 = wst[(kk + 0) * HID + h];
                float w1 = wst[(kk + 1) * HID + h];
                float w2 = wst[(kk + 2) * HID + h];
                float w3 = wst[(kk + 3) * HID + h];
#pragma unroll
                for (int r = 0; r < 10; ++r) {
                    float4 zv = *(const float4*)(BB + lz[r] + kc + kk);
                    acc[r] += zv.x * w0 + zv.y * w1 + zv.z * w2 + zv.w * w3;
                }
            }
        }
        __syncthreads();
#pragma unroll
        for (int r = 0; r < 10; ++r) {
            int l = grp * 10 + r;
            if (l < HALF) {
                float v = acc[r] * DISL[l];
                int fo = OFF_BUFA + (row0 + l) * HID + h;
                sm[fo] = v;
                st_rem(rbase + 4u * (unsigned int)fo, v);
            }
        }
    }
    CLUSTER_SYNC();

    // ---------- Phase C2: Z2 = relu(agg(BA)) -> BB (both copies) ----------
    agg_half<true>(sm, AHL, DISL, BA, OFF_BUFB, b2, tid, row0, rbase);
    CLUSTER_SYNC();

    // ---------- Phase E: tmpS[j][c] = dis[j]*(Z2[j].Wa[:,c]) own rows -> SMT both ----------
    for (int idx = tid; idx < HID * CL; idx += TPB) ZP[idx] = Wa[idx];
    __syncthreads();
    {
        int lz[5];
#pragma unroll
        for (int r = 0; r < 5; ++r) lz[r] = (row0 + min(g2 * 5 + r, HALF - 1)) * HID;
        float acc[5] = {0.f, 0.f, 0.f, 0.f, 0.f};
        for (int k = 0; k < HID; k += 4) {
            float w0 = ZP[(k + 0) * CL + cidx];
            float w1 = ZP[(k + 1) * CL + cidx];
            float w2 = ZP[(k + 2) * CL + cidx];
            float w3 = ZP[(k + 3) * CL + cidx];
#pragma unroll
            for (int r = 0; r < 5; ++r) {
                float4 zv = *(const float4*)(BB + lz[r] + k);
                acc[r] += zv.x * w0 + zv.y * w1 + zv.z * w2 + zv.w * w3;
            }
        }
        if (c32 < CL) {
#pragma unroll
            for (int r = 0; r < 5; ++r) {
                int l = g2 * 5 + r;
                if (l < HALF) {
                    float v = acc[r] * DISL[l];
                    int fo = OFF_SMT + (row0 + l) * CP + c32;
                    sm[fo] = v;
                    st_rem(rbase + 4u * (unsigned int)fo, v);
                }
            }
        }
    }
    CLUSTER_SYNC();

    // ---------- Phase F: assignment logits own rows -> BA (local only) ----------
    {
        int lr[5];
#pragma unroll
        for (int r = 0; r < 5; ++r) lr[r] = min(g2 * 5 + r, HALF - 1) * ROWP;
        float acc[5] = {0.f, 0.f, 0.f, 0.f, 0.f};
        for (int j = 0; j < ROWP; j += 4) {
            float s0 = SMT[(j + 0) * CP + cidx];
            float s1 = SMT[(j + 1) * CP + cidx];
            float s2 = SMT[(j + 2) * CP + cidx];
            float s3 = SMT[(j + 3) * CP + cidx];
#pragma unroll
            for (int r = 0; r < 5; ++r) {
                float4 av = *(const float4*)(AHL + lr[r] + j);
                acc[r] += av.x * s0 + av.y * s1 + av.z * s2 + av.w * s3;
            }
        }
        if (c32 < CL) {
            float bac = ba[c32];
#pragma unroll
            for (int r = 0; r < 5; ++r) {
                int l = g2 * 5 + r;
                if (l < HALF)
                    BA[(row0 + l) * HID + c32] = DISL[l] * acc[r] + bac;
            }
        }
    }
    CLUSTER_SYNC();   // peers must finish reading SMT(tmpS) before G overwrites it

    // ---------- Phase G: row softmax own rows -> SMT both (the assignment S) ----------
    if (tid < HALF) {
        const float* lr = BA + (row0 + tid) * HID;
        float m = lr[0];
#pragma unroll
        for (int c = 1; c < CL; ++c) m = fmaxf(m, lr[c]);
        float e[CL], s = 0.f;
#pragma unroll
        for (int c = 0; c < CL; ++c) { e[c] = expf(lr[c] - m); s += e[c]; }
        float inv = 1.f / s;
#pragma unroll
        for (int c = 0; c < CL; ++c) {
            float v = e[c] * inv;
            int fo = OFF_SMT + (row0 + tid) * CP + c;
            sm[fo] = v;
            st_rem(rbase + 4u * (unsigned int)fo, v);
        }
    }
    CLUSTER_SYNC();

    // ---------- Phase H (redundant): Zp[c][h] = sum_j S[j][c]*Z2[j][h] -> ZP ----------
    {
        float acc[4] = {0.f, 0.f, 0.f, 0.f};
        for (int j = 0; j < NPG; ++j) {
            float z = BB[j * HID + h];
#pragma unroll
            for (int o = 0; o < 4; ++o)
                acc[o] += SMT[j * CP + grp + 8 * o] * z;
        }
#pragma unroll
        for (int o = 0; o < 4; ++o) {
            int c = grp + 8 * o;
            if (c < CL) ZP[c * HID + h] = acc[o];
        }
    }
    __syncthreads();

    // ---------- Phase I: AS[i][c] = (ah@S) - S own rows -> BA both ----------
    {
        int lr[5];
#pragma unroll
        for (int r = 0; r < 5; ++r) lr[r] = min(g2 * 5 + r, HALF - 1) * ROWP;
        float acc[5] = {0.f, 0.f, 0.f, 0.f, 0.f};
        for (int j = 0; j < ROWP; j += 4) {
            float s0 = SMT[(j + 0) * CP + cidx];
            float s1 = SMT[(j + 1) * CP + cidx];
            float s2 = SMT[(j + 2) * CP + cidx];
            float s3 = SMT[(j + 3) * CP + cidx];
#pragma unroll
            for (int r = 0; r < 5; ++r) {
                float4 av = *(const float4*)(AHL + lr[r] + j);
                acc[r] += av.x * s0 + av.y * s1 + av.z * s2 + av.w * s3;
            }
        }
        if (c32 < CL) {
#pragma unroll
            for (int r = 0; r < 5; ++r) {
                int l = g2 * 5 + r;
                if (l < HALF) {
                    int gi = row0 + l;
                    float v = acc[r] - SMT[gi * CP + c32];
                    int fo = OFF_BUFA + gi * HID + c32;
                    sm[fo] = v;
                    st_rem(rbase + 4u * (unsigned int)fo, v);
                }
            }
        }
    }
    CLUSTER_SYNC();

    // ---------- Phase J (redundant): Ap[c][d] = sum_j S[j][c]*AS[j][d] ----------
    for (int idx = tid; idx < CL * CL; idx += TPB) {
        int cc = idx / CL, d = idx - cc * CL;
        float acc = 0.f;
        for (int j = 0; j < NPG; ++j)
            acc += SMT[j * CP + cc] * BA[j * HID + d];
        AP[cc * CP + d] = acc;
    }
    __syncthreads();

    // ---------- Phase K: pooled degrees ----------
    if (tid < CL) {
        float s = 1.0f;   // self loop
        for (int d = 0; d < CL; ++d) s += AP[tid * CP + d];
        DISP[tid] = rsqrtf(fmaxf(s, 1e-12f));
    }
    __syncthreads();

    // ---------- Phase L: BA[c][h] = disp[c]*(Zp[c].Wp[:,h]) ----------
    for (int idx = tid; idx < HID * HID; idx += TPB) BB[idx] = Wp[idx];  // BB dead, stage Wp
    __syncthreads();
    for (int idx = tid; idx < CL * HID; idx += TPB) {
        int cc = idx >> 6, hh = idx & 63;
        float acc = 0.f;
        for (int k = 0; k < HID; k += 4) {
            float4 zv = *(const float4*)(ZP + cc * HID + k);
            acc += zv.x * BB[(k + 0) * HID + hh] + zv.y * BB[(k + 1) * HID + hh]
                 + zv.z * BB[(k + 2) * HID + hh] + zv.w * BB[(k + 3) * HID + hh];
        }
        BA[cc * HID + hh] = acc * DISP[cc];
    }
    __syncthreads();

    // ---------- Phase M: H = relu(disp[i]*sum_c (Ap+I)[i][c]*BA[c][h] + bp) -> ZP ----------
    for (int idx = tid; idx < CL * HID; idx += TPB) {
        int i = idx >> 6, hh = idx & 63;
        float acc = 0.f;
#pragma unroll
        for (int cc = 0; cc < CL; ++cc) {
            float av = AP[i * CP + cc] + ((i == cc) ? 1.f : 0.f);
            acc += av * BA[cc * HID + hh];
        }
        ZP[i * HID + hh] = fmaxf(DISP[i] * acc + bp[hh], 0.f);
    }
    __syncthreads();

    // ---------- Phase N: readout ----------
    if (tid < HID) {
        float s = 0.f;
#pragma unroll
        for (int i = 0; i < CL; ++i) s += ZP[i * HID + tid];
        GV[tid] = s;
    }
    __syncthreads();

    // ---------- Phase O: logits (rank 0 writes) ----------
    if (rank == 0 && tid < NCLS) {
        float acc = bc[tid];
#pragma unroll
        for (int k = 0; k < HID; ++k) acc += GV[k] * Wc[k * NCLS + tid];
        out[g * NCLS + tid] = acc;
    }
}

extern "C" void kernel_launch(void* const* d_in, const int* in_sizes, int n_in,
                              void* d_out, int out_size)
{
    const float* x  = (const float*)d_in[0];
    const float* a  = (const float*)d_in[1];
    const float* W1 = (const float*)d_in[4];
    const float* b1 = (const float*)d_in[5];
    const float* W2 = (const float*)d_in[6];
    const float* b2 = (const float*)d_in[7];
    const float* Wa = (const float*)d_in[8];
    const float* ba = (const float*)d_in[9];
    const float* Wp = (const float*)d_in[10];
    const float* bp = (const float*)d_in[11];
    const float* Wc = (const float*)d_in[12];
    const float* bc = (const float*)d_in[13];
    float* out = (float*)d_out;

    int B = out_size / NCLS;   // 64 graphs
    size_t smem = (size_t)SMEM_FLOATS * sizeof(float);
    cudaFuncSetAttribute(gcn_diffpool, cudaFuncAttributeMaxDynamicSharedMemorySize, (int)smem);
    gcn_diffpool<<<B * 2, TPB, smem>>>(x, a, W1, b1, W2, b2, Wa, ba, Wp, bp, Wc, bc, out);
}

// round 7
// speedup vs baseline: 1.8899x; 1.3592x over previous
#include <cuda_runtime.h>
#include <cstdint>

#define TPB    512
#define NPG    150      // nodes per graph
#define HALF   75       // rows per CTA (2 CTAs per graph)
#define HID    64
#define CL     25
#define CP     26       // padded cluster stride
#define NFEAT  128
#define NCLS   10
#define NTOT   9600
#define MAXC   44       // max neighbors+self per row (mean ~15.5, safe bound)

// ---- shared memory layout (float offsets) ----
#define OFF_COLS  0                          // 75*44 ints = 3300
#define OFF_WKM   (OFF_COLS + HALF*MAXC)     // 16 ints (per-warp kmax)
#define OFF_DIS   (OFF_WKM + 16)             // 80 floats (own rows' D^-1/2), pad
#define OFF_BUFA  (OFF_DIS + 80)             // 152*64 = 9728 (full, pad rows 150/151 zero)
#define OFF_BUFB  (OFF_BUFA + 152*HID)       // 152*64 = 9728 (full, also staging)
#define OFF_SMT   (OFF_BUFB + 152*HID)       // 152*26 = 3952 (full, pad rows zero)
#define OFF_ST    (OFF_SMT + 152*CP)         // 25*152 = 3800 (S transposed, pad cols zero)
#define OFF_ZP    (OFF_ST + CL*152)          // 25*64 = 1600 (Wa staging, then Zp, then H)
#define OFF_AP    (OFF_ZP + CL*HID)          // 25*26 = 650
#define OFF_DISP  (OFF_AP + CL*CP + 6)       // 32
#define OFF_GV    (OFF_DISP + 32)            // 64
#define SMEM_FLOATS (OFF_GV + 64)            // ~32960 floats = ~131.8 KB

#define CLUSTER_SYNC() do { \
    asm volatile("barrier.cluster.arrive.aligned;" ::: "memory"); \
    asm volatile("barrier.cluster.wait.aligned;"   ::: "memory"); } while (0)

__device__ __forceinline__ unsigned int smem_u32(const void* p) {
    unsigned int a;
    asm("{ .reg .u64 t; cvta.to.shared.u64 t, %1; cvt.u32.u64 %0, t; }"
        : "=r"(a) : "l"(p));
    return a;
}
__device__ __forceinline__ void st_rem(unsigned int addr, float v) {
    asm volatile("st.shared::cluster.f32 [%0], %1;" :: "r"(addr), "f"(v));
}

// Sparse aggregate, 64-wide: out[i][h] = act(dis[i]*sum_{c in cols[i]} in[c][h] + bias[h])
// in rows pre-scaled by dis[j]; dummy col = 150 points at a zeroed pad row.
// Writes own rows into local AND peer smem copies.
template<bool RELU>
__device__ __forceinline__ void agg_sp64(float* sm, const int* COLS, const int* WKM,
                                         const float* DISL, int in_off, int out_off,
                                         const float* __restrict__ bias,
                                         int tid, int row0, unsigned int rbase)
{
    const int lane = tid & 31, w = tid >> 5;
    const int kmax = WKM[w];
    int rl[5];
#pragma unroll
    for (int r = 0; r < 5; ++r) rl[r] = min(w + 16 * r, HALF - 1);
    float2 acc[5];
#pragma unroll
    for (int r = 0; r < 5; ++r) acc[r] = make_float2(0.f, 0.f);
    const float2* IN2 = (const float2*)(sm + in_off);
    for (int k = 0; k < kmax; ++k) {
#pragma unroll
        for (int r = 0; r < 5; ++r) {
            int c = COLS[rl[r] * MAXC + k];
            float2 v = IN2[c * 32 + lane];
            acc[r].x += v.x; acc[r].y += v.y;
        }
    }
    float bx = bias[2 * lane], by = bias[2 * lane + 1];
#pragma unroll
    for (int r = 0; r < 5; ++r) {
        int l = w + 16 * r;
        if (l < HALF) {
            float d = DISL[l];
            float vx = d * acc[r].x + bx;
            float vy = d * acc[r].y + by;
            if (RELU) { vx = fmaxf(vx, 0.f); vy = fmaxf(vy, 0.f); }
            int fo = out_off + (row0 + l) * HID + 2 * lane;
            sm[fo] = vx; sm[fo + 1] = vy;
            st_rem(rbase + 4u * (unsigned int)fo, vx);
            st_rem(rbase + 4u * (unsigned int)(fo + 1), vy);
        }
    }
}

__global__ void __launch_bounds__(TPB, 1) __cluster_dims__(2, 1, 1)
gcn_diffpool(const float* __restrict__ x,  const float* __restrict__ a,
             const float* __restrict__ W1, const float* __restrict__ b1,
             const float* __restrict__ W2, const float* __restrict__ b2,
             const float* __restrict__ Wa, const float* __restrict__ ba,
             const float* __restrict__ Wp, const float* __restrict__ bp,
             const float* __restrict__ Wc, const float* __restrict__ bc,
             float* __restrict__ out)
{
    extern __shared__ float sm[];
    int*   COLS = (int*)(sm + OFF_COLS);
    int*   WKM  = (int*)(sm + OFF_WKM);
    float* DISL = sm + OFF_DIS;
    float* BA   = sm + OFF_BUFA;
    float* BB   = sm + OFF_BUFB;
    float* SMT  = sm + OFF_SMT;
    float* ST   = sm + OFF_ST;
    float* ZP   = sm + OFF_ZP;
    float* AP   = sm + OFF_AP;
    float* DISP = sm + OFF_DISP;
    float* GV   = sm + OFF_GV;

    const int tid  = threadIdx.x;
    const int g    = blockIdx.x >> 1;
    const int base = g * NPG;
    const int h    = tid & 63;
    const int grp  = tid >> 6;              // 0..7
    const int lane = tid & 31;
    const int w    = tid >> 5;              // 0..15
    const int c32  = lane;

    unsigned int rank;
    asm("mov.u32 %0, %%cluster_ctarank;" : "=r"(rank));
    const int row0 = (int)rank * HALF;
    unsigned int rbase;
    {
        unsigned int lbase = smem_u32(sm);
        unsigned int peer = rank ^ 1u;
        asm("mapa.shared::cluster.u32 %0, %1, %2;" : "=r"(rbase) : "r"(lbase), "r"(peer));
    }

    // ---------- Phase A: build CSR (neighbors + self) from gmem, degrees ----------
    {
        // prefetch all 25 adjacency values (5 rows x 5 chunks) for MLP
        float vv[5][5];
#pragma unroll
        for (int r = 0; r < 5; ++r) {
            int l = min(w + 16 * r, HALF - 1);
            const float* arow = a + (size_t)(base + row0 + l) * NTOT + base;
#pragma unroll
            for (int ch = 0; ch < 5; ++ch) {
                int col = ch * 32 + lane;
                vv[r][ch] = (col < NPG) ? arow[col] : 0.f;
            }
        }
        int wkm = 0;
#pragma unroll
        for (int r = 0; r < 5; ++r) {
            int l = w + 16 * r;
            if (l < HALF) {
                int self = row0 + l;
                int cnt = 0;
#pragma unroll
                for (int ch = 0; ch < 5; ++ch) {
                    int col = ch * 32 + lane;
                    bool nz = (col < NPG) && (vv[r][ch] != 0.f || col == self);
                    unsigned m = __ballot_sync(0xffffffffu, nz);
                    if (nz) {
                        int p = cnt + __popc(m & ((1u << lane) - 1u));
                        if (p < MAXC) COLS[l * MAXC + p] = col;
                    }
                    cnt += __popc(m);
                }
                int cc = min(cnt, MAXC);
                for (int kk = cc + lane; kk < MAXC; kk += 32) COLS[l * MAXC + kk] = NPG;
                if (lane == 0) DISL[l] = rsqrtf((float)cnt);
                wkm = max(wkm, cc);
            }
        }
        if (lane == 0) WKM[w] = wkm;
    }
    // zero pad rows/cols (dummy col = 150 reads these)
    if (tid < 128) { BA[NPG * HID + tid] = 0.f; BB[NPG * HID + tid] = 0.f; }
    if (tid < 2 * CP) SMT[NPG * CP + tid] = 0.f;
    if (tid < 2 * CL) ST[(tid >> 1) * 152 + NPG + (tid & 1)] = 0.f;
    __syncthreads();

    // ---------- Phase B: BA[j][h] = dis[j]*(x[j].W1[:,h]) own rows (staged, dense) ----------
    {
        int lc[10];
#pragma unroll
        for (int r = 0; r < 10; ++r) lc[r] = min(grp * 10 + r, HALF - 1) * 32;
        float acc[10];
#pragma unroll
        for (int r = 0; r < 10; ++r) acc[r] = 0.f;
        float* xst = BB;               // 75*32 = 2400
        float* wst = BB + HALF * 32;   // 32*64 = 2048
        for (int kc = 0; kc < NFEAT; kc += 32) {
            __syncthreads();
            for (int idx = tid; idx < HALF * 32; idx += TPB)
                xst[idx] = x[(size_t)(base + row0 + (idx >> 5)) * NFEAT + kc + (idx & 31)];
            for (int idx = tid; idx < 32 * HID; idx += TPB)
                wst[idx] = W1[(kc + (idx >> 6)) * HID + (idx & 63)];
            __syncthreads();
            for (int kk = 0; kk < 32; kk += 4) {
                float w0 = wst[(kk + 0) * HID + h];
                float w1 = wst[(kk + 1) * HID + h];
                float w2 = wst[(kk + 2) * HID + h];
                float w3 = wst[(kk + 3) * HID + h];
#pragma unroll
                for (int r = 0; r < 10; ++r) {
                    float4 xv = *(const float4*)(xst + lc[r] + kk);
                    acc[r] += xv.x * w0 + xv.y * w1 + xv.z * w2 + xv.w * w3;
                }
            }
        }
        __syncthreads();
#pragma unroll
        for (int r = 0; r < 10; ++r) {
            int l = grp * 10 + r;
            if (l < HALF) {
                float v = acc[r] * DISL[l];
                int fo = OFF_BUFA + (row0 + l) * HID + h;
                sm[fo] = v;
                st_rem(rbase + 4u * (unsigned int)fo, v);
            }
        }
    }
    CLUSTER_SYNC();

    // ---------- Phase C1: Z1 = relu(sparse agg(BA)) -> BB both ----------
    agg_sp64<true>(sm, COLS, WKM, DISL, OFF_BUFA, OFF_BUFB, b1, tid, row0, rbase);
    CLUSTER_SYNC();

    // ---------- Phase D: BA[j][h] = dis[j]*(Z1[j].W2[:,h]) own rows (dense) ----------
    {
        int lz[10];
#pragma unroll
        for (int r = 0; r < 10; ++r) lz[r] = (row0 + min(grp * 10 + r, HALF - 1)) * HID;
        float acc[10];
#pragma unroll
        for (int r = 0; r < 10; ++r) acc[r] = 0.f;
        float* wst = SMT;   // 2048 floats staging (rows 0..78, pads at 150 safe)
        for (int kc = 0; kc < HID; kc += 32) {
            __syncthreads();
            for (int idx = tid; idx < 32 * HID; idx += TPB)
                wst[idx] = W2[(kc + (idx >> 6)) * HID + (idx & 63)];
            __syncthreads();
            for (int kk = 0; kk < 32; kk += 4) {
                float w0 = wst[(kk + 0) * HID + h];
                float w1 = wst[(kk + 1) * HID + h];
                float w2 = wst[(kk + 2) * HID + h];
                float w3 = wst[(kk + 3) * HID + h];
#pragma unroll
                for (int r = 0; r < 10; ++r) {
                    float4 zv = *(const float4*)(BB + lz[r] + kc + kk);
                    acc[r] += zv.x * w0 + zv.y * w1 + zv.z * w2 + zv.w * w3;
                }
            }
        }
        __syncthreads();
#pragma unroll
        for (int r = 0; r < 10; ++r) {
            int l = grp * 10 + r;
            if (l < HALF) {
                float v = acc[r] * DISL[l];
                int fo = OFF_BUFA + (row0 + l) * HID + h;
                sm[fo] = v;
                st_rem(rbase + 4u * (unsigned int)fo, v);
            }
        }
    }
    CLUSTER_SYNC();

    // ---------- Phase C2: Z2 = relu(sparse agg(BA)) -> BB both ----------
    agg_sp64<true>(sm, COLS, WKM, DISL, OFF_BUFA, OFF_BUFB, b2, tid, row0, rbase);
    CLUSTER_SYNC();

    // ---------- Phase E: tmpS[j][c] = dis[j]*(Z2[j].Wa[:,c]) own rows -> SMT both ----------
    for (int idx = tid; idx < HID * CL; idx += TPB) ZP[idx] = Wa[idx];
    __syncthreads();
    {
        const int cidx = min(c32, CL - 1);
        int lz[5];
#pragma unroll
        for (int r = 0; r < 5; ++r) lz[r] = (row0 + min(w + 16 * r, HALF - 1)) * HID;
        float acc[5] = {0.f, 0.f, 0.f, 0.f, 0.f};
        for (int k = 0; k < HID; k += 4) {
            float w0 = ZP[(k + 0) * CL + cidx];
            float w1 = ZP[(k + 1) * CL + cidx];
            float w2 = ZP[(k + 2) * CL + cidx];
            float w3 = ZP[(k + 3) * CL + cidx];
#pragma unroll
            for (int r = 0; r < 5; ++r) {
                float4 zv = *(const float4*)(BB + lz[r] + k);
                acc[r] += zv.x * w0 + zv.y * w1 + zv.z * w2 + zv.w * w3;
            }
        }
        if (c32 < CL) {
#pragma unroll
            for (int r = 0; r < 5; ++r) {
                int l = w + 16 * r;
                if (l < HALF) {
                    float v = acc[r] * DISL[l];
                    int fo = OFF_SMT + (row0 + l) * CP + c32;
                    sm[fo] = v;
                    st_rem(rbase + 4u * (unsigned int)fo, v);
                }
            }
        }
    }
    CLUSTER_SYNC();

    // ---------- Phase F: logits[i][c] = dis[i]*sum_cols tmpS[col][c] + ba (sparse, local) ----------
    {
        const int kmax = WKM[w];
        int rl[5];
#pragma unroll
        for (int r = 0; r < 5; ++r) rl[r] = min(w + 16 * r, HALF - 1);
        float acc[5] = {0.f, 0.f, 0.f, 0.f, 0.f};
        for (int k = 0; k < kmax; ++k) {
#pragma unroll
            for (int r = 0; r < 5; ++r) {
                int c = COLS[rl[r] * MAXC + k];
                acc[r] += SMT[c * CP + c32];
            }
        }
        if (c32 < CL) {
            float bac = ba[c32];
#pragma unroll
            for (int r = 0; r < 5; ++r) {
                int l = w + 16 * r;
                if (l < HALF)
                    BA[(row0 + l) * HID + c32] = DISL[l] * acc[r] + bac;
            }
        }
    }
    CLUSTER_SYNC();   // peers must finish reading SMT(tmpS) before G overwrites it

    // ---------- Phase G: row softmax own rows -> SMT both + ST (transposed) both ----------
    if (tid < HALF) {
        const int gi = row0 + tid;
        const float* lr = BA + gi * HID;
        float m = lr[0];
#pragma unroll
        for (int c = 1; c < CL; ++c) m = fmaxf(m, lr[c]);
        float e[CL], s = 0.f;
#pragma unroll
        for (int c = 0; c < CL; ++c) { e[c] = expf(lr[c] - m); s += e[c]; }
        float inv = 1.f / s;
#pragma unroll
        for (int c = 0; c < CL; ++c) {
            float v = e[c] * inv;
            int fo = OFF_SMT + gi * CP + c;
            sm[fo] = v;
            st_rem(rbase + 4u * (unsigned int)fo, v);
            int ft = OFF_ST + c * 152 + gi;
            sm[ft] = v;
            st_rem(rbase + 4u * (unsigned int)ft, v);
        }
    }
    CLUSTER_SYNC();

    // ---------- Phase I: AS[i][c] = sum_cols S[col][c] - S[i][c] (sparse) -> BA both ----------
    {
        const int kmax = WKM[w];
        int rl[5];
#pragma unroll
        for (int r = 0; r < 5; ++r) rl[r] = min(w + 16 * r, HALF - 1);
        float acc[5] = {0.f, 0.f, 0.f, 0.f, 0.f};
        for (int k = 0; k < kmax; ++k) {
#pragma unroll
            for (int r = 0; r < 5; ++r) {
                int c = COLS[rl[r] * MAXC + k];
                acc[r] += SMT[c * CP + c32];
            }
        }
        if (c32 < CL) {
#pragma unroll
            for (int r = 0; r < 5; ++r) {
                int l = w + 16 * r;
                if (l < HALF) {
                    int gi = row0 + l;
                    float v = acc[r] - SMT[gi * CP + c32];
                    int fo = OFF_BUFA + gi * HID + c32;
                    sm[fo] = v;
                    st_rem(rbase + 4u * (unsigned int)fo, v);
                }
            }
        }
    }
    CLUSTER_SYNC();

    // ---------- Phase H/J task-split across cluster ----------
    if (rank == 0) {
        // H: Zp[c][h] = sum_j S_T[c][j] * Z2[j][h]  -> ZP local + remote
        int co[4];
#pragma unroll
        for (int o = 0; o < 4; ++o) co[o] = min(grp + 8 * o, CL - 1);
        float acc[4] = {0.f, 0.f, 0.f, 0.f};
        for (int j = 0; j < 152; j += 4) {
            float4 s0 = *(const float4*)(ST + co[0] * 152 + j);
            float4 s1 = *(const float4*)(ST + co[1] * 152 + j);
            float4 s2 = *(const float4*)(ST + co[2] * 152 + j);
            float4 s3 = *(const float4*)(ST + co[3] * 152 + j);
            float z0 = BB[(j + 0) * HID + h];
            float z1 = BB[(j + 1) * HID + h];
            float z2 = BB[(j + 2) * HID + h];
            float z3 = BB[(j + 3) * HID + h];
            acc[0] += s0.x * z0 + s0.y * z1 + s0.z * z2 + s0.w * z3;
            acc[1] += s1.x * z0 + s1.y * z1 + s1.z * z2 + s1.w * z3;
            acc[2] += s2.x * z0 + s2.y * z1 + s2.z * z2 + s2.w * z3;
            acc[3] += s3.x * z0 + s3.y * z1 + s3.z * z2 + s3.w * z3;
        }
#pragma unroll
        for (int o = 0; o < 4; ++o) {
            int c = grp + 8 * o;
            if (c < CL) {
                int fo = OFF_ZP + c * HID + h;
                sm[fo] = acc[o];
                st_rem(rbase + 4u * (unsigned int)fo, acc[o]);
            }
        }
    } else {
        // J: Ap[cc][d] = sum_j S_T[cc][j] * AS[j][d]  -> AP local + remote
        for (int idx = tid; idx < CL * CL; idx += TPB) {
            int cc = idx / CL, d = idx - cc * CL;
            float acc = 0.f;
            for (int j = 0; j < 152; j += 4) {
                float4 s = *(const float4*)(ST + cc * 152 + j);
                acc += s.x * BA[(j + 0) * HID + d] + s.y * BA[(j + 1) * HID + d]
                     + s.z * BA[(j + 2) * HID + d] + s.w * BA[(j + 3) * HID + d];
            }
            int fo = OFF_AP + cc * CP + d;
            sm[fo] = acc;
            st_rem(rbase + 4u * (unsigned int)fo, acc);
        }
    }
    CLUSTER_SYNC();

    // ---------- Phase K: pooled degrees (redundant) ----------
    if (tid < CL) {
        float s = 1.0f;   // self loop
        for (int d = 0; d < CL; ++d) s += AP[tid * CP + d];
        DISP[tid] = rsqrtf(fmaxf(s, 1e-12f));
    }
    __syncthreads();

    // ---------- Phase L: BA[c][h] = disp[c]*(Zp[c].Wp[:,h]) (redundant) ----------
    for (int idx = tid; idx < HID * HID; idx += TPB) BB[idx] = Wp[idx];  // BB dead, stage Wp
    __syncthreads();
    for (int idx = tid; idx < CL * HID; idx += TPB) {
        int cc = idx >> 6, hh = idx & 63;
        float acc = 0.f;
        for (int k = 0; k < HID; k += 4) {
            float4 zv = *(const float4*)(ZP + cc * HID + k);
            acc += zv.x * BB[(k + 0) * HID + hh] + zv.y * BB[(k + 1) * HID + hh]
                 + zv.z * BB[(k + 2) * HID + hh] + zv.w * BB[(k + 3) * HID + hh];
        }
        BA[cc * HID + hh] = acc * DISP[cc];
    }
    __syncthreads();

    // ---------- Phase M: Hp = relu(disp[i]*sum_c (Ap+I)[i][c]*BA[c][h] + bp) -> ZP ----------
    for (int idx = tid; idx < CL * HID; idx += TPB) {
        int i = idx >> 6, hh = idx & 63;
        float acc = 0.f;
#pragma unroll
        for (int cc = 0; cc < CL; ++cc) {
            float av = AP[i * CP + cc] + ((i == cc) ? 1.f : 0.f);
            acc += av * BA[cc * HID + hh];
        }
        ZP[i * HID + hh] = fmaxf(DISP[i] * acc + bp[hh], 0.f);
    }
    __syncthreads();

    // ---------- Phase N: readout ----------
    if (tid < HID) {
        float s = 0.f;
#pragma unroll
        for (int i = 0; i < CL; ++i) s += ZP[i * HID + tid];
        GV[tid] = s;
    }
    __syncthreads();

    // ---------- Phase O: logits (rank 0 writes) ----------
    if (rank == 0 && tid < NCLS) {
        float acc = bc[tid];
#pragma unroll
        for (int k = 0; k < HID; ++k) acc += GV[k] * Wc[k * NCLS + tid];
        out[g * NCLS + tid] = acc;
    }
}

extern "C" void kernel_launch(void* const* d_in, const int* in_sizes, int n_in,
                              void* d_out, int out_size)
{
    const float* x  = (const float*)d_in[0];
    const float* a  = (const float*)d_in[1];
    const float* W1 = (const float*)d_in[4];
    const float* b1 = (const float*)d_in[5];
    const float* W2 = (const float*)d_in[6];
    const float* b2 = (const float*)d_in[7];
    const float* Wa = (const float*)d_in[8];
    const float* ba = (const float*)d_in[9];
    const float* Wp = (const float*)d_in[10];
    const float* bp = (const float*)d_in[11];
    const float* Wc = (const float*)d_in[12];
    const float* bc = (const float*)d_in[13];
    float* out = (float*)d_out;

    int B = out_size / NCLS;   // 64 graphs
    size_t smem = (size_t)SMEM_FLOATS * sizeof(float);
    cudaFuncSetAttribute(gcn_diffpool, cudaFuncAttributeMaxDynamicSharedMemorySize, (int)smem);
    gcn_diffpool<<<B * 2, TPB, smem>>>(x, a, W1, b1, W2, b2, Wa, ba, Wp, bp, Wc, bc, out);
}

// round 8
// speedup vs baseline: 2.0548x; 1.0872x over previous
#include <cuda_runtime.h>
#include <cstdint>

#define TPB    1024
#define NPG    150      // nodes per graph
#define HALF   75       // rows per CTA (2 CTAs per graph)
#define HID    64
#define CL     25
#define CP     26       // padded cluster stride
#define NFEAT  128
#define NCLS   10
#define NTOT   9600
#define MAXC   44       // max neighbors+self per row

// ---- shared memory layout (float offsets) ----
#define OFF_COLS  0                          // 75*44 ints = 3300
#define OFF_WKM   (OFF_COLS + HALF*MAXC)     // 32 ints (per-warp kmax)
#define OFF_DIS   (OFF_WKM + 32)             // 80 floats
#define OFF_BUFA  (OFF_DIS + 80)             // 152*64 = 9728 (full, pad rows zero)
#define OFF_BUFB  (OFF_BUFA + 152*HID)       // 152*64 = 9728 (full, W1 staging)
#define OFF_SMT   (OFF_BUFB + 152*HID)       // 152*26 = 3952 (+ST used as flat scratch)
#define OFF_ST    (OFF_SMT + 152*CP)         // 25*152 = 3800 (S transposed)
#define OFF_ZP    (OFF_ST + CL*152)          // 25*64 = 1600
#define OFF_AP    (OFF_ZP + CL*HID)          // 25*26+6 = 656
#define OFF_DISP  (OFF_AP + CL*CP + 6)       // 32
#define OFF_GV    (OFF_DISP + 32)            // 64
#define SMEM_FLOATS (OFF_GV + 64)            // 32972 floats = 131888 B

#define CLUSTER_SYNC() do { \
    asm volatile("barrier.cluster.arrive.aligned;" ::: "memory"); \
    asm volatile("barrier.cluster.wait.aligned;"   ::: "memory"); } while (0)

__device__ __forceinline__ unsigned int smem_u32(const void* p) {
    unsigned int a;
    asm("{ .reg .u64 t; cvta.to.shared.u64 t, %1; cvt.u32.u64 %0, t; }"
        : "=r"(a) : "l"(p));
    return a;
}
__device__ __forceinline__ void st_rem(unsigned int addr, float v) {
    asm volatile("st.shared::cluster.f32 [%0], %1;" :: "r"(addr), "f"(v));
}
__device__ __forceinline__ void st_rem2(unsigned int addr, float vx, float vy) {
    unsigned long long p;
    asm("mov.b64 %0, {%1,%2};" : "=l"(p) : "f"(vx), "f"(vy));
    asm volatile("st.shared::cluster.b64 [%0], %1;" :: "r"(addr), "l"(p));
}

// Sparse aggregate: out[i][h] = act(dis[i]*sum_{c in cols[i]} in[c][h] + bias[h]).
// 32 warps x 3 rows, float2 per lane. Writes own rows to local AND peer smem.
template<bool RELU>
__device__ __forceinline__ void agg_sp(float* sm, const int* COLS, const int* WKM,
                                       const float* DISL, int in_off, int out_off,
                                       const float* __restrict__ bias,
                                       int tid, int row0, unsigned int rbase)
{
    const int lane = tid & 31, w = tid >> 5;
    const int kmax = WKM[w];
    int rl[3];
#pragma unroll
    for (int r = 0; r < 3; ++r) rl[r] = min(w + 32 * r, HALF - 1);
    float2 acc[3];
#pragma unroll
    for (int r = 0; r < 3; ++r) acc[r] = make_float2(0.f, 0.f);
    const float2* IN2 = (const float2*)(sm + in_off);
    for (int k = 0; k < kmax; ++k) {
#pragma unroll
        for (int r = 0; r < 3; ++r) {
            int c = COLS[rl[r] * MAXC + k];
            float2 v = IN2[c * 32 + lane];
            acc[r].x += v.x; acc[r].y += v.y;
        }
    }
    float2 bv = *(const float2*)(bias + 2 * lane);
#pragma unroll
    for (int r = 0; r < 3; ++r) {
        int l = w + 32 * r;
        if (l < HALF) {
            float d = DISL[l];
            float vx = d * acc[r].x + bv.x;
            float vy = d * acc[r].y + bv.y;
            if (RELU) { vx = fmaxf(vx, 0.f); vy = fmaxf(vy, 0.f); }
            int fo = out_off + (row0 + l) * HID + 2 * lane;
            *(float2*)(sm + fo) = make_float2(vx, vy);
            st_rem2(rbase + 4u * (unsigned int)fo, vx, vy);
        }
    }
}

__global__ void __launch_bounds__(TPB, 1) __cluster_dims__(2, 1, 1)
gcn_diffpool(const float* __restrict__ x,  const float* __restrict__ a,
             const float* __restrict__ W1, const float* __restrict__ b1,
             const float* __restrict__ W2, const float* __restrict__ b2,
             const float* __restrict__ Wa, const float* __restrict__ ba,
             const float* __restrict__ Wp, const float* __restrict__ bp,
             const float* __restrict__ Wc, const float* __restrict__ bc,
             float* __restrict__ out)
{
    extern __shared__ float sm[];
    int*   COLS = (int*)(sm + OFF_COLS);
    int*   WKM  = (int*)(sm + OFF_WKM);
    float* DISL = sm + OFF_DIS;
    float* BA   = sm + OFF_BUFA;
    float* BB   = sm + OFF_BUFB;
    float* SMT  = sm + OFF_SMT;
    float* ST   = sm + OFF_ST;
    float* ZP   = sm + OFF_ZP;
    float* AP   = sm + OFF_AP;
    float* DISP = sm + OFF_DISP;
    float* GV   = sm + OFF_GV;

    const int tid  = threadIdx.x;
    const int g    = blockIdx.x >> 1;
    const int base = g * NPG;
    const int h    = tid & 63;
    const int grp  = tid >> 6;              // 0..15
    const int lane = tid & 31;
    const int w    = tid >> 5;              // 0..31
    const int c32  = lane;

    unsigned int rank;
    asm("mov.u32 %0, %%cluster_ctarank;" : "=r"(rank));
    const int row0 = (int)rank * HALF;
    unsigned int rbase;
    {
        unsigned int lbase = smem_u32(sm);
        unsigned int peer = rank ^ 1u;
        asm("mapa.shared::cluster.u32 %0, %1, %2;" : "=r"(rbase) : "r"(lbase), "r"(peer));
    }

    // ---------- Phase A: build CSR (neighbors + self), degrees; 3 rows/warp ----------
    {
        float vv[3][5];
#pragma unroll
        for (int r = 0; r < 3; ++r) {
            int l = min(w + 32 * r, HALF - 1);
            const float* arow = a + (size_t)(base + row0 + l) * NTOT + base;
#pragma unroll
            for (int ch = 0; ch < 5; ++ch) {
                int col = ch * 32 + lane;
                vv[r][ch] = (col < NPG) ? arow[col] : 0.f;
            }
        }
        int wkm = 0;
#pragma unroll
        for (int r = 0; r < 3; ++r) {
            int l = w + 32 * r;
            if (l < HALF) {
                int self = row0 + l;
                int cnt = 0;
#pragma unroll
                for (int ch = 0; ch < 5; ++ch) {
                    int col = ch * 32 + lane;
                    bool nz = (col < NPG) && (vv[r][ch] != 0.f || col == self);
                    unsigned m = __ballot_sync(0xffffffffu, nz);
                    if (nz) {
                        int p = cnt + __popc(m & ((1u << lane) - 1u));
                        if (p < MAXC) COLS[l * MAXC + p] = col;
                    }
                    cnt += __popc(m);
                }
                int cc = min(cnt, MAXC);
                for (int kk = cc + lane; kk < MAXC; kk += 32) COLS[l * MAXC + kk] = NPG;
                if (lane == 0) DISL[l] = rsqrtf((float)cnt);
                wkm = max(wkm, cc);
            }
        }
        if (lane == 0) WKM[w] = wkm;
    }
    // zero pad rows (dummy col = 150 reads these)
    if (tid < 128) { BA[NPG * HID + tid] = 0.f; BB[NPG * HID + tid] = 0.f; }
    __syncthreads();

    // ---------- Phase B: BA[j][h] = dis[j]*(x[j].W1[:,h]) own rows ----------
    // W1 full staged in BUFB; x staged in two 64-col chunks in SMT/ST scratch.
    {
        float* wst = BB;            // 128*64 = 8192 (pads at 9600+ untouched)
        float* xs  = sm + OFF_SMT;  // 75*64 = 4800 (SMT+ST scratch)
        for (int idx = tid; idx < NFEAT * HID; idx += TPB) wst[idx] = W1[idx];
        for (int idx = tid; idx < HALF * 64; idx += TPB)
            xs[idx] = x[(size_t)(base + row0 + (idx >> 6)) * NFEAT + (idx & 63)];
        __syncthreads();

        int lc[5];
#pragma unroll
        for (int r = 0; r < 5; ++r) lc[r] = min(grp + 16 * r, HALF - 1) * 64;
        float acc[5];
#pragma unroll
        for (int r = 0; r < 5; ++r) acc[r] = 0.f;

        for (int k = 0; k < 64; k += 4) {
            float w0 = wst[(k + 0) * HID + h];
            float w1 = wst[(k + 1) * HID + h];
            float w2 = wst[(k + 2) * HID + h];
            float w3 = wst[(k + 3) * HID + h];
#pragma unroll
            for (int r = 0; r < 5; ++r) {
                float4 xv = *(const float4*)(xs + lc[r] + k);
                acc[r] += xv.x * w0 + xv.y * w1 + xv.z * w2 + xv.w * w3;
            }
        }
        __syncthreads();
        for (int idx = tid; idx < HALF * 64; idx += TPB)
            xs[idx] = x[(size_t)(base + row0 + (idx >> 6)) * NFEAT + 64 + (idx & 63)];
        __syncthreads();
        for (int k = 0; k < 64; k += 4) {
            float w0 = wst[(64 + k + 0) * HID + h];
            float w1 = wst[(64 + k + 1) * HID + h];
            float w2 = wst[(64 + k + 2) * HID + h];
            float w3 = wst[(64 + k + 3) * HID + h];
#pragma unroll
            for (int r = 0; r < 5; ++r) {
                float4 xv = *(const float4*)(xs + lc[r] + k);
                acc[r] += xv.x * w0 + xv.y * w1 + xv.z * w2 + xv.w * w3;
            }
        }
#pragma unroll
        for (int r = 0; r < 5; ++r) {
            int l = grp + 16 * r;
            if (l < HALF) {
                float v = acc[r] * DISL[l];
                int fo = OFF_BUFA + (row0 + l) * HID + h;
                sm[fo] = v;
                st_rem(rbase + 4u * (unsigned int)fo, v);
            }
        }
    }
    CLUSTER_SYNC();

    // ---------- Phase C1: Z1 = relu(sparse agg(BA)) -> BB both ----------
    agg_sp<true>(sm, COLS, WKM, DISL, OFF_BUFA, OFF_BUFB, b1, tid, row0, rbase);
    __syncthreads();   // D reads BB own rows (written locally)

    // ---------- Phase D: BA[j][h] = dis[j]*(Z1[j].W2[:,h]) own rows ----------
    {
        float* wfl = sm + OFF_SMT;  // W2 full 64*64 = 4096 in SMT+ST scratch
        for (int idx = tid; idx < HID * HID; idx += TPB) wfl[idx] = W2[idx];
        __syncthreads();

        int lz[5];
#pragma unroll
        for (int r = 0; r < 5; ++r) lz[r] = (row0 + min(grp + 16 * r, HALF - 1)) * HID;
        float acc[5];
#pragma unroll
        for (int r = 0; r < 5; ++r) acc[r] = 0.f;
        for (int k = 0; k < 64; k += 4) {
            float w0 = wfl[(k + 0) * HID + h];
            float w1 = wfl[(k + 1) * HID + h];
            float w2 = wfl[(k + 2) * HID + h];
            float w3 = wfl[(k + 3) * HID + h];
#pragma unroll
            for (int r = 0; r < 5; ++r) {
                float4 zv = *(const float4*)(BB + lz[r] + k);
                acc[r] += zv.x * w0 + zv.y * w1 + zv.z * w2 + zv.w * w3;
            }
        }
#pragma unroll
        for (int r = 0; r < 5; ++r) {
            int l = grp + 16 * r;
            if (l < HALF) {
                float v = acc[r] * DISL[l];
                int fo = OFF_BUFA + (row0 + l) * HID + h;
                sm[fo] = v;
                st_rem(rbase + 4u * (unsigned int)fo, v);
            }
        }
    }
    CLUSTER_SYNC();

    // ---------- Phase C2: Z2 = relu(sparse agg(BA)) -> BB both ----------
    agg_sp<true>(sm, COLS, WKM, DISL, OFF_BUFA, OFF_BUFB, b2, tid, row0, rbase);
    __syncthreads();   // E reads BB own rows (written locally)

    // ---------- Phase E: tmpS[j][c] = dis[j]*(Z2[j].Wa[:,c]) own rows -> SMT both ----------
    // re-zero SMT/ST pads (clobbered by B/D staging) + stage Wa
    if (tid < 2 * CP) SMT[NPG * CP + tid] = 0.f;
    if (tid < 2 * CL) ST[(tid >> 1) * 152 + NPG + (tid & 1)] = 0.f;
    for (int idx = tid; idx < HID * CL; idx += TPB) ZP[idx] = Wa[idx];
    __syncthreads();
    {
        const int cidx = min(c32, CL - 1);
        int lz[3];
#pragma unroll
        for (int r = 0; r < 3; ++r) lz[r] = (row0 + min(w + 32 * r, HALF - 1)) * HID;
        float acc[3] = {0.f, 0.f, 0.f};
        for (int k = 0; k < HID; k += 4) {
            float w0 = ZP[(k + 0) * CL + cidx];
            float w1 = ZP[(k + 1) * CL + cidx];
            float w2 = ZP[(k + 2) * CL + cidx];
            float w3 = ZP[(k + 3) * CL + cidx];
#pragma unroll
            for (int r = 0; r < 3; ++r) {
                float4 zv = *(const float4*)(BB + lz[r] + k);
                acc[r] += zv.x * w0 + zv.y * w1 + zv.z * w2 + zv.w * w3;
            }
        }
        if (c32 < CL) {
#pragma unroll
            for (int r = 0; r < 3; ++r) {
                int l = w + 32 * r;
                if (l < HALF) {
                    float v = acc[r] * DISL[l];
                    int fo = OFF_SMT + (row0 + l) * CP + c32;
                    sm[fo] = v;
                    st_rem(rbase + 4u * (unsigned int)fo, v);
                }
            }
        }
    }
    CLUSTER_SYNC();

    // ---------- Phase F: logits[i][c] = dis[i]*sum_cols tmpS[col][c] + ba (local) ----------
    {
        const int kmax = WKM[w];
        int rl[3];
#pragma unroll
        for (int r = 0; r < 3; ++r) rl[r] = min(w + 32 * r, HALF - 1);
        float acc[3] = {0.f, 0.f, 0.f};
        for (int k = 0; k < kmax; ++k) {
#pragma unroll
            for (int r = 0; r < 3; ++r) {
                int c = COLS[rl[r] * MAXC + k];
                acc[r] += SMT[c * CP + c32];
            }
        }
        if (c32 < CL) {
            float bac = ba[c32];
#pragma unroll
            for (int r = 0; r < 3; ++r) {
                int l = w + 32 * r;
                if (l < HALF)
                    BA[(row0 + l) * HID + c32] = DISL[l] * acc[r] + bac;
            }
        }
    }
    CLUSTER_SYNC();   // peers must finish reading SMT(tmpS) before G overwrites it

    // ---------- Phase G: row softmax own rows -> SMT both + ST transposed both ----------
    if (tid < HALF) {
        const int gi = row0 + tid;
        const float* lr = BA + gi * HID;
        float m = lr[0];
#pragma unroll
        for (int c = 1; c < CL; ++c) m = fmaxf(m, lr[c]);
        float e[CL], s = 0.f;
#pragma unroll
        for (int c = 0; c < CL; ++c) { e[c] = expf(lr[c] - m); s += e[c]; }
        float inv = 1.f / s;
#pragma unroll
        for (int c = 0; c < CL; ++c) {
            float v = e[c] * inv;
            int fo = OFF_SMT + gi * CP + c;
            sm[fo] = v;
            st_rem(rbase + 4u * (unsigned int)fo, v);
            int ft = OFF_ST + c * 152 + gi;
            sm[ft] = v;
            st_rem(rbase + 4u * (unsigned int)ft, v);
        }
    }
    CLUSTER_SYNC();

    // ---------- Phase I: AS[i][c] = sum_cols S[col][c] - S[i][c] -> BA both ----------
    {
        const int kmax = WKM[w];
        int rl[3];
#pragma unroll
        for (int r = 0; r < 3; ++r) rl[r] = min(w + 32 * r, HALF - 1);
        float acc[3] = {0.f, 0.f, 0.f};
        for (int k = 0; k < kmax; ++k) {
#pragma unroll
            for (int r = 0; r < 3; ++r) {
                int c = COLS[rl[r] * MAXC + k];
                acc[r] += SMT[c * CP + c32];
            }
        }
        if (c32 < CL) {
#pragma unroll
            for (int r = 0; r < 3; ++r) {
                int l = w + 32 * r;
                if (l < HALF) {
                    int gi = row0 + l;
                    float v = acc[r] - SMT[gi * CP + c32];
                    int fo = OFF_BUFA + gi * HID + c32;
                    sm[fo] = v;
                    st_rem(rbase + 4u * (unsigned int)fo, v);
                }
            }
        }
    }
    CLUSTER_SYNC();

    // ---------- Phase H/J task-split across cluster ----------
    if (rank == 0) {
        // H: Zp[c][h] = sum_j S_T[c][j] * Z2[j][h]
        int co[2];
        co[0] = min(grp, CL - 1);
        co[1] = min(grp + 16, CL - 1);
        float acc[2] = {0.f, 0.f};
        for (int j = 0; j < 152; j += 4) {
            float4 s0 = *(const float4*)(ST + co[0] * 152 + j);
            float4 s1 = *(const float4*)(ST + co[1] * 152 + j);
            float z0 = BB[(j + 0) * HID + h];
            float z1 = BB[(j + 1) * HID + h];
            float z2 = BB[(j + 2) * HID + h];
            float z3 = BB[(j + 3) * HID + h];
            acc[0] += s0.x * z0 + s0.y * z1 + s0.z * z2 + s0.w * z3;
            acc[1] += s1.x * z0 + s1.y * z1 + s1.z * z2 + s1.w * z3;
        }
#pragma unroll
        for (int o = 0; o < 2; ++o) {
            int c = grp + 16 * o;
            if (c < CL) {
                int fo = OFF_ZP + c * HID + h;
                sm[fo] = acc[o];
                st_rem(rbase + 4u * (unsigned int)fo, acc[o]);
            }
        }
    } else {
        // J: Ap[cc][d] = sum_j S_T[cc][j] * AS[j][d]
        if (tid < CL * CL) {
            int cc = tid / CL, d = tid - cc * CL;
            float acc = 0.f;
            for (int j = 0; j < 152; j += 4) {
                float4 s = *(const float4*)(ST + cc * 152 + j);
                acc += s.x * BA[(j + 0) * HID + d] + s.y * BA[(j + 1) * HID + d]
                     + s.z * BA[(j + 2) * HID + d] + s.w * BA[(j + 3) * HID + d];
            }
            int fo = OFF_AP + cc * CP + d;
            sm[fo] = acc;
            st_rem(rbase + 4u * (unsigned int)fo, acc);
        }
    }
    CLUSTER_SYNC();

    // ---------- Phase K: pooled degrees (redundant) ----------
    if (tid < CL) {
        float s = 1.0f;   // self loop
        for (int d = 0; d < CL; ++d) s += AP[tid * CP + d];
        DISP[tid] = rsqrtf(fmaxf(s, 1e-12f));
    }
    __syncthreads();

    // ---------- Phase L: BA[c][h] = disp[c]*(Zp[c].Wp[:,h]) (redundant) ----------
    for (int idx = tid; idx < HID * HID; idx += TPB) BB[idx] = Wp[idx];  // BB dead, stage Wp
    __syncthreads();
    for (int idx = tid; idx < CL * HID; idx += TPB) {
        int cc = idx >> 6, hh = idx & 63;
        float acc = 0.f;
        for (int k = 0; k < HID; k += 4) {
            float4 zv = *(const float4*)(ZP + cc * HID + k);
            acc += zv.x * BB[(k + 0) * HID + hh] + zv.y * BB[(k + 1) * HID + hh]
                 + zv.z * BB[(k + 2) * HID + hh] + zv.w * BB[(k + 3) * HID + hh];
        }
        BA[cc * HID + hh] = acc * DISP[cc];
    }
    __syncthreads();

    // ---------- Phase M: Hp = relu(disp[i]*sum_c (Ap+I)[i][c]*BA[c][h] + bp) -> ZP ----------
    for (int idx = tid; idx < CL * HID; idx += TPB) {
        int i = idx >> 6, hh = idx & 63;
        float acc = 0.f;
#pragma unroll
        for (int cc = 0; cc < CL; ++cc) {
            float av = AP[i * CP + cc] + ((i == cc) ? 1.f : 0.f);
            acc += av * BA[cc * HID + hh];
        }
        ZP[i * HID + hh] = fmaxf(DISP[i] * acc + bp[hh], 0.f);
    }
    __syncthreads();

    // ---------- Phase N: readout ----------
    if (tid < HID) {
        float s = 0.f;
#pragma unroll
        for (int i = 0; i < CL; ++i) s += ZP[i * HID + tid];
        GV[tid] = s;
    }
    __syncthreads();

    // ---------- Phase O: logits (rank 0 writes) ----------
    if (rank == 0 && tid < NCLS) {
        float acc = bc[tid];
#pragma unroll
        for (int k = 0; k < HID; ++k) acc += GV[k] * Wc[k * NCLS + tid];
        out[g * NCLS + tid] = acc;
    }
}

extern "C" void kernel_launch(void* const* d_in, const int* in_sizes, int n_in,
                              void* d_out, int out_size)
{
    const float* x  = (const float*)d_in[0];
    const float* a  = (const float*)d_in[1];
    const float* W1 = (const float*)d_in[4];
    const float* b1 = (const float*)d_in[5];
    const float* W2 = (const float*)d_in[6];
    const float* b2 = (const float*)d_in[7];
    const float* Wa = (const float*)d_in[8];
    const float* ba = (const float*)d_in[9];
    const float* Wp = (const float*)d_in[10];
    const float* bp = (const float*)d_in[11];
    const float* Wc = (const float*)d_in[12];
    const float* bc = (const float*)d_in[13];
    float* out = (float*)d_out;

    int B = out_size / NCLS;   // 64 graphs
    size_t smem = (size_t)SMEM_FLOATS * sizeof(float);
    cudaFuncSetAttribute(gcn_diffpool, cudaFuncAttributeMaxDynamicSharedMemorySize, (int)smem);
    gcn_diffpool<<<B * 2, TPB, smem>>>(x, a, W1, b1, W2, b2, Wa, ba, Wp, bp, Wc, bc, out);
}

// round 9
// speedup vs baseline: 2.1132x; 1.0285x over previous
#include <cuda_runtime.h>
#include <cstdint>

#define TPB    1024
#define NPG    150      // nodes per graph
#define HALF   75       // rows per CTA (2 CTAs per graph)
#define HID    64
#define CL     25
#define CP     26       // padded cluster stride
#define NFEAT  128
#define NCLS   10
#define NTOT   9600
#define MAXC   48       // max neighbors+self per row (multiple of 4 for int4 reads)

// ---- shared memory layout (float offsets) ----
#define OFF_COLS  0                          // 75*48 ints = 3600
#define OFF_WKM   (OFF_COLS + HALF*MAXC)     // 32 ints (per-warp kmax)
#define OFF_DIS   (OFF_WKM + 32)             // 80 floats
#define OFF_BUFA  (OFF_DIS + 80)             // 152*64 = 9728 (pad rows zero)
#define OFF_BUFB  (OFF_BUFA + 152*HID)       // 152*64 = 9728 (x staging in B)
#define OFF_SMT   (OFF_BUFB + 152*HID)       // 152*26 = 3952 (W1/W2 scratch too)
#define OFF_ST    (OFF_SMT + 152*CP)         // 25*152 = 3800 (S transposed)
#define OFF_ZP    (OFF_ST + CL*152)          // 25*64 = 1600
#define OFF_AP    (OFF_ZP + CL*HID)          // 25*26+6 = 656
#define OFF_DISP  (OFF_AP + CL*CP + 6)       // 32
#define OFF_GV    (OFF_DISP + 32)            // 64
#define SMEM_FLOATS (OFF_GV + 64)            // 33272 floats = 133088 B

#define CLUSTER_SYNC() do { \
    asm volatile("barrier.cluster.arrive.aligned;" ::: "memory"); \
    asm volatile("barrier.cluster.wait.aligned;"   ::: "memory"); } while (0)

__device__ __forceinline__ unsigned int smem_u32(const void* p) {
    unsigned int a;
    asm("{ .reg .u64 t; cvta.to.shared.u64 t, %1; cvt.u32.u64 %0, t; }"
        : "=r"(a) : "l"(p));
    return a;
}
__device__ __forceinline__ void st_rem(unsigned int addr, float v) {
    asm volatile("st.shared::cluster.f32 [%0], %1;" :: "r"(addr), "f"(v));
}
__device__ __forceinline__ void st_rem2(unsigned int addr, float vx, float vy) {
    unsigned long long p;
    asm("mov.b64 %0, {%1,%2};" : "=l"(p) : "f"(vx), "f"(vy));
    asm volatile("st.shared::cluster.b64 [%0], %1;" :: "r"(addr), "l"(p));
}

// Sparse aggregate: out[i][h] = act(dis[i]*sum_{c in cols[i]} in[c][h] + bias[h]).
// 32 warps x 3 rows, float2 per lane, int4 column reads. Writes to local+peer smem.
template<bool RELU>
__device__ __forceinline__ void agg_sp(float* sm, const int* COLS, const int* WKM,
                                       const float* DISL, int in_off, int out_off,
                                       const float* __restrict__ bias,
                                       int tid, int row0, unsigned int rbase)
{
    const int lane = tid & 31, w = tid >> 5;
    const int kmax = WKM[w];                       // multiple of 1; loop rounds to 4
    int rl[3];
#pragma unroll
    for (int r = 0; r < 3; ++r) rl[r] = min(w + 32 * r, HALF - 1) * MAXC;
    float2 acc[3];
#pragma unroll
    for (int r = 0; r < 3; ++r) acc[r] = make_float2(0.f, 0.f);
    const float2* IN2 = (const float2*)(sm + in_off);
    for (int k = 0; k < kmax; k += 4) {
        int4 c0 = *(const int4*)(COLS + rl[0] + k);
        int4 c1 = *(const int4*)(COLS + rl[1] + k);
        int4 c2 = *(const int4*)(COLS + rl[2] + k);
        float2 v;
        v = IN2[c0.x * 32 + lane]; acc[0].x += v.x; acc[0].y += v.y;
        v = IN2[c0.y * 32 + lane]; acc[0].x += v.x; acc[0].y += v.y;
        v = IN2[c0.z * 32 + lane]; acc[0].x += v.x; acc[0].y += v.y;
        v = IN2[c0.w * 32 + lane]; acc[0].x += v.x; acc[0].y += v.y;
        v = IN2[c1.x * 32 + lane]; acc[1].x += v.x; acc[1].y += v.y;
        v = IN2[c1.y * 32 + lane]; acc[1].x += v.x; acc[1].y += v.y;
        v = IN2[c1.z * 32 + lane]; acc[1].x += v.x; acc[1].y += v.y;
        v = IN2[c1.w * 32 + lane]; acc[1].x += v.x; acc[1].y += v.y;
        v = IN2[c2.x * 32 + lane]; acc[2].x += v.x; acc[2].y += v.y;
        v = IN2[c2.y * 32 + lane]; acc[2].x += v.x; acc[2].y += v.y;
        v = IN2[c2.z * 32 + lane]; acc[2].x += v.x; acc[2].y += v.y;
        v = IN2[c2.w * 32 + lane]; acc[2].x += v.x; acc[2].y += v.y;
    }
    float2 bv = *(const float2*)(bias + 2 * lane);
#pragma unroll
    for (int r = 0; r < 3; ++r) {
        int l = w + 32 * r;
        if (l < HALF) {
            float d = DISL[l];
            float vx = d * acc[r].x + bv.x;
            float vy = d * acc[r].y + bv.y;
            if (RELU) { vx = fmaxf(vx, 0.f); vy = fmaxf(vy, 0.f); }
            int fo = out_off + (row0 + l) * HID + 2 * lane;
            *(float2*)(sm + fo) = make_float2(vx, vy);
            st_rem2(rbase + 4u * (unsigned int)fo, vx, vy);
        }
    }
}

__global__ void __launch_bounds__(TPB, 1) __cluster_dims__(2, 1, 1)
gcn_diffpool(const float* __restrict__ x,  const float* __restrict__ a,
             const float* __restrict__ W1, const float* __restrict__ b1,
             const float* __restrict__ W2, const float* __restrict__ b2,
             const float* __restrict__ Wa, const float* __restrict__ ba,
             const float* __restrict__ Wp, const float* __restrict__ bp,
             const float* __restrict__ Wc, const float* __restrict__ bc,
             float* __restrict__ out)
{
    extern __shared__ float sm[];
    int*   COLS = (int*)(sm + OFF_COLS);
    int*   WKM  = (int*)(sm + OFF_WKM);
    float* DISL = sm + OFF_DIS;
    float* BA   = sm + OFF_BUFA;
    float* BB   = sm + OFF_BUFB;
    float* SMT  = sm + OFF_SMT;
    float* ST   = sm + OFF_ST;
    float* ZP   = sm + OFF_ZP;
    float* AP   = sm + OFF_AP;
    float* DISP = sm + OFF_DISP;
    float* GV   = sm + OFF_GV;

    const int tid  = threadIdx.x;
    const int g    = blockIdx.x >> 1;
    const int base = g * NPG;
    const int h    = tid & 63;
    const int grp  = tid >> 6;              // 0..15
    const int lane = tid & 31;
    const int w    = tid >> 5;              // 0..31
    const int c32  = lane;

    unsigned int rank;
    asm("mov.u32 %0, %%cluster_ctarank;" : "=r"(rank));
    const int row0 = (int)rank * HALF;
    unsigned int rbase;
    {
        unsigned int lbase = smem_u32(sm);
        unsigned int peer = rank ^ 1u;
        asm("mapa.shared::cluster.u32 %0, %1, %2;" : "=r"(rbase) : "r"(lbase), "r"(peer));
    }

    // ---------- Phase A: build CSR (neighbors + self), degrees; 3 rows/warp ----------
    {
        float vv[3][5];
#pragma unroll
        for (int r = 0; r < 3; ++r) {
            int l = min(w + 32 * r, HALF - 1);
            const float* arow = a + (size_t)(base + row0 + l) * NTOT + base;
#pragma unroll
            for (int ch = 0; ch < 5; ++ch) {
                int col = ch * 32 + lane;
                vv[r][ch] = (col < NPG) ? arow[col] : 0.f;
            }
        }
        int wkm = 0;
#pragma unroll
        for (int r = 0; r < 3; ++r) {
            int l = w + 32 * r;
            if (l < HALF) {
                int self = row0 + l;
                int cnt = 0;
#pragma unroll
                for (int ch = 0; ch < 5; ++ch) {
                    int col = ch * 32 + lane;
                    bool nz = (col < NPG) && (vv[r][ch] != 0.f || col == self);
                    unsigned m = __ballot_sync(0xffffffffu, nz);
                    if (nz) {
                        int p = cnt + __popc(m & ((1u << lane) - 1u));
                        if (p < MAXC) COLS[l * MAXC + p] = col;
                    }
                    cnt += __popc(m);
                }
                int cc = min(cnt, MAXC);
                for (int kk = cc + lane; kk < MAXC; kk += 32) COLS[l * MAXC + kk] = NPG;
                if (lane == 0) DISL[l] = rsqrtf((float)cnt);
                wkm = max(wkm, cc);
            }
        }
        if (lane == 0) WKM[w] = wkm;
    }
    // zero pad rows (dummy col = 150 reads these)
    if (tid < 128) { BA[NPG * HID + tid] = 0.f; BB[NPG * HID + tid] = 0.f; }
    __syncthreads();

    // ---------- Phase B: BA[j][h] = dis[j]*(x[j].W1[:,h]) own rows ----------
    // W1 (128x64) staged in SMT/ST/ZP scratch; x (75x128) staged in BUFB; out -> BUFA.
    {
        float* wst = sm + OFF_SMT;  // 8192 floats (SMT+ST+440 of ZP)
        float* xs  = BB;            // 75*128 = 9600
        for (int idx = tid; idx < NFEAT * HID; idx += TPB) wst[idx] = W1[idx];
        for (int idx = tid; idx < HALF * NFEAT; idx += TPB)
            xs[idx] = x[(size_t)(base + row0 + (idx >> 7)) * NFEAT + (idx & 127)];
        __syncthreads();

        int lc[5];
#pragma unroll
        for (int r = 0; r < 5; ++r) lc[r] = min(grp + 16 * r, HALF - 1) * NFEAT;
        float acc[5];
#pragma unroll
        for (int r = 0; r < 5; ++r) acc[r] = 0.f;

        for (int k = 0; k < NFEAT; k += 4) {
            float w0 = wst[(k + 0) * HID + h];
            float w1 = wst[(k + 1) * HID + h];
            float w2 = wst[(k + 2) * HID + h];
            float w3 = wst[(k + 3) * HID + h];
#pragma unroll
            for (int r = 0; r < 5; ++r) {
                float4 xv = *(const float4*)(xs + lc[r] + k);
                acc[r] += xv.x * w0 + xv.y * w1 + xv.z * w2 + xv.w * w3;
            }
        }
#pragma unroll
        for (int r = 0; r < 5; ++r) {
            int l = grp + 16 * r;
            if (l < HALF) {
                float v = acc[r] * DISL[l];
                int fo = OFF_BUFA + (row0 + l) * HID + h;
                sm[fo] = v;
                st_rem(rbase + 4u * (unsigned int)fo, v);
            }
        }
    }
    CLUSTER_SYNC();

    // ---------- Phase C1: Z1 = relu(sparse agg(BA)) -> BB both ----------
    agg_sp<true>(sm, COLS, WKM, DISL, OFF_BUFA, OFF_BUFB, b1, tid, row0, rbase);
    __syncthreads();   // D reads BB own rows (written locally)

    // ---------- Phase D: BA[j][h] = dis[j]*(Z1[j].W2[:,h]) own rows ----------
    {
        float* wfl = sm + OFF_SMT;  // W2 full 64*64 = 4096
        for (int idx = tid; idx < HID * HID; idx += TPB) wfl[idx] = W2[idx];
        __syncthreads();

        int lz[5];
#pragma unroll
        for (int r = 0; r < 5; ++r) lz[r] = (row0 + min(grp + 16 * r, HALF - 1)) * HID;
        float acc[5];
#pragma unroll
        for (int r = 0; r < 5; ++r) acc[r] = 0.f;
        for (int k = 0; k < 64; k += 4) {
            float w0 = wfl[(k + 0) * HID + h];
            float w1 = wfl[(k + 1) * HID + h];
            float w2 = wfl[(k + 2) * HID + h];
            float w3 = wfl[(k + 3) * HID + h];
#pragma unroll
            for (int r = 0; r < 5; ++r) {
                float4 zv = *(const float4*)(BB + lz[r] + k);
                acc[r] += zv.x * w0 + zv.y * w1 + zv.z * w2 + zv.w * w3;
            }
        }
#pragma unroll
        for (int r = 0; r < 5; ++r) {
            int l = grp + 16 * r;
            if (l < HALF) {
                float v = acc[r] * DISL[l];
                int fo = OFF_BUFA + (row0 + l) * HID + h;
                sm[fo] = v;
                st_rem(rbase + 4u * (unsigned int)fo, v);
            }
        }
    }
    CLUSTER_SYNC();

    // ---------- Phase C2: Z2 = relu(sparse agg(BA)) -> BB both ----------
    agg_sp<true>(sm, COLS, WKM, DISL, OFF_BUFA, OFF_BUFB, b2, tid, row0, rbase);
    __syncthreads();   // E reads BB own rows (written locally)

    // ---------- Phase E: tmpS[j][c] = dis[j]*(Z2[j].Wa[:,c]) own rows -> SMT both ----------
    // re-zero SMT/ST pads (clobbered by B/D staging) + stage Wa
    if (tid < 2 * CP) SMT[NPG * CP + tid] = 0.f;
    if (tid < 2 * CL) ST[(tid >> 1) * 152 + NPG + (tid & 1)] = 0.f;
    for (int idx = tid; idx < HID * CL; idx += TPB) ZP[idx] = Wa[idx];
    __syncthreads();
    {
        const int cidx = min(c32, CL - 1);
        int lz[3];
#pragma unroll
        for (int r = 0; r < 3; ++r) lz[r] = (row0 + min(w + 32 * r, HALF - 1)) * HID;
        float acc[3] = {0.f, 0.f, 0.f};
        for (int k = 0; k < HID; k += 4) {
            float w0 = ZP[(k + 0) * CL + cidx];
            float w1 = ZP[(k + 1) * CL + cidx];
            float w2 = ZP[(k + 2) * CL + cidx];
            float w3 = ZP[(k + 3) * CL + cidx];
#pragma unroll
            for (int r = 0; r < 3; ++r) {
                float4 zv = *(const float4*)(BB + lz[r] + k);
                acc[r] += zv.x * w0 + zv.y * w1 + zv.z * w2 + zv.w * w3;
            }
        }
        if (c32 < CL) {
#pragma unroll
            for (int r = 0; r < 3; ++r) {
                int l = w + 32 * r;
                if (l < HALF) {
                    float v = acc[r] * DISL[l];
                    int fo = OFF_SMT + (row0 + l) * CP + c32;
                    sm[fo] = v;
                    st_rem(rbase + 4u * (unsigned int)fo, v);
                }
            }
        }
    }
    CLUSTER_SYNC();

    // ---------- Phase F: logits[i][c] = dis[i]*sum_cols tmpS[col][c] + ba (local) ----------
    {
        const int kmax = WKM[w];
        int rl[3];
#pragma unroll
        for (int r = 0; r < 3; ++r) rl[r] = min(w + 32 * r, HALF - 1) * MAXC;
        float acc[3] = {0.f, 0.f, 0.f};
        for (int k = 0; k < kmax; k += 4) {
#pragma unroll
            for (int r = 0; r < 3; ++r) {
                int4 c4 = *(const int4*)(COLS + rl[r] + k);
                acc[r] += SMT[c4.x * CP + c32] + SMT[c4.y * CP + c32]
                        + SMT[c4.z * CP + c32] + SMT[c4.w * CP + c32];
            }
        }
        if (c32 < CL) {
            float bac = ba[c32];
#pragma unroll
            for (int r = 0; r < 3; ++r) {
                int l = w + 32 * r;
                if (l < HALF)
                    BA[(row0 + l) * HID + c32] = DISL[l] * acc[r] + bac;
            }
        }
    }
    CLUSTER_SYNC();   // peers must finish reading SMT(tmpS) before G overwrites it

    // ---------- Phase G: row softmax own rows -> SMT both + ST transposed both ----------
    if (tid < HALF) {
        const int gi = row0 + tid;
        const float* lr = BA + gi * HID;
        float m = lr[0];
#pragma unroll
        for (int c = 1; c < CL; ++c) m = fmaxf(m, lr[c]);
        float e[CL], s = 0.f;
#pragma unroll
        for (int c = 0; c < CL; ++c) { e[c] = expf(lr[c] - m); s += e[c]; }
        float inv = 1.f / s;
#pragma unroll
        for (int c = 0; c < CL; ++c) {
            float v = e[c] * inv;
            int fo = OFF_SMT + gi * CP + c;
            sm[fo] = v;
            st_rem(rbase + 4u * (unsigned int)fo, v);
            int ft = OFF_ST + c * 152 + gi;
            sm[ft] = v;
            st_rem(rbase + 4u * (unsigned int)ft, v);
        }
    }
    CLUSTER_SYNC();

    // ---------- Phase I: AS[i][c] = sum_cols S[col][c] - S[i][c] -> BA both ----------
    {
        const int kmax = WKM[w];
        int rl[3];
#pragma unroll
        for (int r = 0; r < 3; ++r) rl[r] = min(w + 32 * r, HALF - 1) * MAXC;
        float acc[3] = {0.f, 0.f, 0.f};
        for (int k = 0; k < kmax; k += 4) {
#pragma unroll
            for (int r = 0; r < 3; ++r) {
                int4 c4 = *(const int4*)(COLS + rl[r] + k);
                acc[r] += SMT[c4.x * CP + c32] + SMT[c4.y * CP + c32]
                        + SMT[c4.z * CP + c32] + SMT[c4.w * CP + c32];
            }
        }
        if (c32 < CL) {
#pragma unroll
            for (int r = 0; r < 3; ++r) {
                int l = w + 32 * r;
                if (l < HALF) {
                    int gi = row0 + l;
                    float v = acc[r] - SMT[gi * CP + c32];
                    int fo = OFF_BUFA + gi * HID + c32;
                    sm[fo] = v;
                    st_rem(rbase + 4u * (unsigned int)fo, v);
                }
            }
        }
    }
    CLUSTER_SYNC();

    // ---------- Phase H/J task-split across cluster ----------
    if (rank == 0) {
        // H: Zp[c][h] = sum_j S_T[c][j] * Z2[j][h].  14 warps: (c-group of 4) x (h-half).
        if (w < 14) {
            const int hh = (w & 1) * 32 + lane;       // this lane's h
            const int cb = (w >> 1) * 4;              // c base (0,4,...,24)
            float acc[4] = {0.f, 0.f, 0.f, 0.f};
            for (int j = 0; j < 152; j += 4) {
                float z0 = BB[(j + 0) * HID + hh];
                float z1 = BB[(j + 1) * HID + hh];
                float z2 = BB[(j + 2) * HID + hh];
                float z3 = BB[(j + 3) * HID + hh];
#pragma unroll
                for (int o = 0; o < 4; ++o) {
                    int c = cb + o;
                    if (c < CL) {
                        float4 s = *(const float4*)(ST + c * 152 + j);
                        acc[o] += s.x * z0 + s.y * z1 + s.z * z2 + s.w * z3;
                    }
                }
            }
#pragma unroll
            for (int o = 0; o < 4; ++o) {
                int c = cb + o;
                if (c < CL) {
                    int fo = OFF_ZP + c * HID + hh;
                    sm[fo] = acc[o];
                    st_rem(rbase + 4u * (unsigned int)fo, acc[o]);
                }
            }
        }
    } else {
        // J: Ap[cc][d] = sum_j S_T[cc][j] * AS[j][d]
        if (tid < CL * CL) {
            int cc = tid / CL, d = tid - cc * CL;
            float acc = 0.f;
            for (int j = 0; j < 152; j += 4) {
                float4 s = *(const float4*)(ST + cc * 152 + j);
                acc += s.x * BA[(j + 0) * HID + d] + s.y * BA[(j + 1) * HID + d]
                     + s.z * BA[(j + 2) * HID + d] + s.w * BA[(j + 3) * HID + d];
            }
            int fo = OFF_AP + cc * CP + d;
            sm[fo] = acc;
            st_rem(rbase + 4u * (unsigned int)fo, acc);
        }
    }
    CLUSTER_SYNC();

    // ---------- Phase K: pooled degrees (redundant) ----------
    if (tid < CL) {
        float s = 1.0f;   // self loop
        for (int d = 0; d < CL; ++d) s += AP[tid * CP + d];
        DISP[tid] = rsqrtf(fmaxf(s, 1e-12f));
    }
    __syncthreads();

    // ---------- Phase L: BA[c][h] = disp[c]*(Zp[c].Wp[:,h]) (redundant) ----------
    for (int idx = tid; idx < HID * HID; idx += TPB) BB[idx] = Wp[idx];  // BB dead, stage Wp
    __syncthreads();
    for (int idx = tid; idx < CL * HID; idx += TPB) {
        int cc = idx >> 6, hh = idx & 63;
        float acc = 0.f;
        for (int k = 0; k < HID; k += 4) {
            float4 zv = *(const float4*)(ZP + cc * HID + k);
            acc += zv.x * BB[(k + 0) * HID + hh] + zv.y * BB[(k + 1) * HID + hh]
                 + zv.z * BB[(k + 2) * HID + hh] + zv.w * BB[(k + 3) * HID + hh];
        }
        BA[cc * HID + hh] = acc * DISP[cc];
    }
    __syncthreads();

    // ---------- Phase M: Hp = relu(disp[i]*sum_c (Ap+I)[i][c]*BA[c][h] + bp) -> ZP ----------
    for (int idx = tid; idx < CL * HID; idx += TPB) {
        int i = idx >> 6, hh = idx & 63;
        float acc = 0.f;
#pragma unroll
        for (int cc = 0; cc < CL; ++cc) {
            float av = AP[i * CP + cc] + ((i == cc) ? 1.f : 0.f);
            acc += av * BA[cc * HID + hh];
        }
        ZP[i * HID + hh] = fmaxf(DISP[i] * acc + bp[hh], 0.f);
    }
    __syncthreads();

    // ---------- Phase N: readout ----------
    if (tid < HID) {
        float s = 0.f;
#pragma unroll
        for (int i = 0; i < CL; ++i) s += ZP[i * HID + tid];
        GV[tid] = s;
    }
    __syncthreads();

    // ---------- Phase O: logits (rank 0 writes) ----------
    if (rank == 0 && tid < NCLS) {
        float acc = bc[tid];
#pragma unroll
        for (int k = 0; k < HID; ++k) acc += GV[k] * Wc[k * NCLS + tid];
        out[g * NCLS + tid] = acc;
    }
}

extern "C" void kernel_launch(void* const* d_in, const int* in_sizes, int n_in,
                              void* d_out, int out_size)
{
    const float* x  = (const float*)d_in[0];
    const float* a  = (const float*)d_in[1];
    const float* W1 = (const float*)d_in[4];
    const float* b1 = (const float*)d_in[5];
    const float* W2 = (const float*)d_in[6];
    const float* b2 = (const float*)d_in[7];
    const float* Wa = (const float*)d_in[8];
    const float* ba = (const float*)d_in[9];
    const float* Wp = (const float*)d_in[10];
    const float* bp = (const float*)d_in[11];
    const float* Wc = (const float*)d_in[12];
    const float* bc = (const float*)d_in[13];
    float* out = (float*)d_out;

    int B = out_size / NCLS;   // 64 graphs
    size_t smem = (size_t)SMEM_FLOATS * sizeof(float);
    cudaFuncSetAttribute(gcn_diffpool, cudaFuncAttributeMaxDynamicSharedMemorySize, (int)smem);
    gcn_diffpool<<<B * 2, TPB, smem>>>(x, a, W1, b1, W2, b2, Wa, ba, Wp, bp, Wc, bc, out);
}

// round 10
// speedup vs baseline: 2.2966x; 1.0868x over previous
#include <cuda_runtime.h>
#include <cstdint>

#define TPB    1024
#define NPG    150      // nodes per graph
#define HALF   75       // rows per CTA (2 CTAs per graph)
#define HID    64
#define CL     25
#define CP     26       // padded cluster stride
#define NFEAT  128
#define NCLS   10
#define NTOT   9600
#define MAXC   48       // max neighbors+self per row (multiple of 4 for int4 reads)

// ---- shared memory layout (float offsets) ----
#define OFF_COLS  0                          // 75*48 ints = 3600
#define OFF_WKM   (OFF_COLS + HALF*MAXC)     // 32 ints (per-warp kmax)
#define OFF_DIS   (OFF_WKM + 32)             // 80 floats
#define OFF_BUFA  (OFF_DIS + 80)             // 152*64 = 9728 (pad rows zero)
#define OFF_BUFB  (OFF_BUFA + 152*HID)       // 152*64 = 9728 (x staging in B)
#define OFF_SMT   (OFF_BUFB + 152*HID)       // 152*26 = 3952 (scratch with ST/ZP)
#define OFF_ST    (OFF_SMT + 152*CP)         // 25*152 = 3800 (S transposed)
#define OFF_ZP    (OFF_ST + CL*152)          // 25*64 = 1600
#define OFF_AP    (OFF_ZP + CL*HID)          // 25*26+6 = 656
#define OFF_DISP  (OFF_AP + CL*CP + 6)       // 32
#define OFF_GV    (OFF_DISP + 32)            // 64
#define SMEM_FLOATS (OFF_GV + 64)            // 33272 floats = 133088 B

#define CLUSTER_SYNC() do { \
    asm volatile("barrier.cluster.arrive.aligned;" ::: "memory"); \
    asm volatile("barrier.cluster.wait.aligned;"   ::: "memory"); } while (0)

__device__ __forceinline__ unsigned int smem_u32(const void* p) {
    unsigned int a;
    asm("{ .reg .u64 t; cvta.to.shared.u64 t, %1; cvt.u32.u64 %0, t; }"
        : "=r"(a) : "l"(p));
    return a;
}
__device__ __forceinline__ void st_rem(unsigned int addr, float v) {
    asm volatile("st.shared::cluster.f32 [%0], %1;" :: "r"(addr), "f"(v));
}
__device__ __forceinline__ void st_rem2(unsigned int addr, float vx, float vy) {
    unsigned long long p;
    asm("mov.b64 %0, {%1,%2};" : "=l"(p) : "f"(vx), "f"(vy));
    asm volatile("st.shared::cluster.b64 [%0], %1;" :: "r"(addr), "l"(p));
}

// Sparse aggregate: out[i][h] = act(dis[i]*sum_{c in cols[i]} in[c][h] + bias[h]).
// 32 warps x 3 rows, float2 per lane, int4 column reads.
template<bool RELU, bool REMOTE>
__device__ __forceinline__ void agg_sp(float* sm, const int* COLS, const int* WKM,
                                       const float* DISL, int in_off, int out_off,
                                       const float* __restrict__ bias,
                                       int tid, int row0, unsigned int rbase)
{
    const int lane = tid & 31, w = tid >> 5;
    const int kmax = WKM[w];
    int rl[3];
#pragma unroll
    for (int r = 0; r < 3; ++r) rl[r] = min(w + 32 * r, HALF - 1) * MAXC;
    float2 acc[3];
#pragma unroll
    for (int r = 0; r < 3; ++r) acc[r] = make_float2(0.f, 0.f);
    const float2* IN2 = (const float2*)(sm + in_off);
    for (int k = 0; k < kmax; k += 4) {
        int4 c0 = *(const int4*)(COLS + rl[0] + k);
        int4 c1 = *(const int4*)(COLS + rl[1] + k);
        int4 c2 = *(const int4*)(COLS + rl[2] + k);
        float2 v;
        v = IN2[c0.x * 32 + lane]; acc[0].x += v.x; acc[0].y += v.y;
        v = IN2[c0.y * 32 + lane]; acc[0].x += v.x; acc[0].y += v.y;
        v = IN2[c0.z * 32 + lane]; acc[0].x += v.x; acc[0].y += v.y;
        v = IN2[c0.w * 32 + lane]; acc[0].x += v.x; acc[0].y += v.y;
        v = IN2[c1.x * 32 + lane]; acc[1].x += v.x; acc[1].y += v.y;
        v = IN2[c1.y * 32 + lane]; acc[1].x += v.x; acc[1].y += v.y;
        v = IN2[c1.z * 32 + lane]; acc[1].x += v.x; acc[1].y += v.y;
        v = IN2[c1.w * 32 + lane]; acc[1].x += v.x; acc[1].y += v.y;
        v = IN2[c2.x * 32 + lane]; acc[2].x += v.x; acc[2].y += v.y;
        v = IN2[c2.y * 32 + lane]; acc[2].x += v.x; acc[2].y += v.y;
        v = IN2[c2.z * 32 + lane]; acc[2].x += v.x; acc[2].y += v.y;
        v = IN2[c2.w * 32 + lane]; acc[2].x += v.x; acc[2].y += v.y;
    }
    float2 bv = *(const float2*)(bias + 2 * lane);
#pragma unroll
    for (int r = 0; r < 3; ++r) {
        int l = w + 32 * r;
        if (l < HALF) {
            float d = DISL[l];
            float vx = d * acc[r].x + bv.x;
            float vy = d * acc[r].y + bv.y;
            if (RELU) { vx = fmaxf(vx, 0.f); vy = fmaxf(vy, 0.f); }
            int fo = out_off + (row0 + l) * HID + 2 * lane;
            *(float2*)(sm + fo) = make_float2(vx, vy);
            if (REMOTE) st_rem2(rbase + 4u * (unsigned int)fo, vx, vy);
        }
    }
}

__global__ void __launch_bounds__(TPB, 1) __cluster_dims__(2, 1, 1)
gcn_diffpool(const float* __restrict__ x,  const float* __restrict__ a,
             const float* __restrict__ W1, const float* __restrict__ b1,
             const float* __restrict__ W2, const float* __restrict__ b2,
             const float* __restrict__ Wa, const float* __restrict__ ba,
             const float* __restrict__ Wp, const float* __restrict__ bp,
             const float* __restrict__ Wc, const float* __restrict__ bc,
             float* __restrict__ out)
{
    extern __shared__ float sm[];
    int*   COLS = (int*)(sm + OFF_COLS);
    int*   WKM  = (int*)(sm + OFF_WKM);
    float* DISL = sm + OFF_DIS;
    float* BA   = sm + OFF_BUFA;
    float* BB   = sm + OFF_BUFB;
    float* SMT  = sm + OFF_SMT;
    float* ST   = sm + OFF_ST;
    float* ZP   = sm + OFF_ZP;
    float* AP   = sm + OFF_AP;
    float* DISP = sm + OFF_DISP;
    float* GV   = sm + OFF_GV;

    const int tid  = threadIdx.x;
    const int g    = blockIdx.x >> 1;
    const int base = g * NPG;
    const int lane = tid & 31;
    const int w    = tid >> 5;              // 0..31
    const int c32  = lane;

    unsigned int rank;
    asm("mov.u32 %0, %%cluster_ctarank;" : "=r"(rank));
    const int row0 = (int)rank * HALF;
    unsigned int rbase;
    {
        unsigned int lbase = smem_u32(sm);
        unsigned int peer = rank ^ 1u;
        asm("mapa.shared::cluster.u32 %0, %1, %2;" : "=r"(rbase) : "r"(lbase), "r"(peer));
    }

    // ---------- Phase A: build CSR (neighbors + self), degrees; 3 rows/warp ----------
    {
        float vv[3][5];
#pragma unroll
        for (int r = 0; r < 3; ++r) {
            int l = min(w + 32 * r, HALF - 1);
            const float* arow = a + (size_t)(base + row0 + l) * NTOT + base;
#pragma unroll
            for (int ch = 0; ch < 5; ++ch) {
                int col = ch * 32 + lane;
                vv[r][ch] = (col < NPG) ? arow[col] : 0.f;
            }
        }
        int wkm = 0;
#pragma unroll
        for (int r = 0; r < 3; ++r) {
            int l = w + 32 * r;
            if (l < HALF) {
                int self = row0 + l;
                int cnt = 0;
#pragma unroll
                for (int ch = 0; ch < 5; ++ch) {
                    int col = ch * 32 + lane;
                    bool nz = (col < NPG) && (vv[r][ch] != 0.f || col == self);
                    unsigned m = __ballot_sync(0xffffffffu, nz);
                    if (nz) {
                        int p = cnt + __popc(m & ((1u << lane) - 1u));
                        if (p < MAXC) COLS[l * MAXC + p] = col;
                    }
                    cnt += __popc(m);
                }
                int cc = min(cnt, MAXC);
                for (int kk = cc + lane; kk < MAXC; kk += 32) COLS[l * MAXC + kk] = NPG;
                if (lane == 0) DISL[l] = rsqrtf((float)cnt);
                wkm = max(wkm, cc);
            }
        }
        if (lane == 0) WKM[w] = wkm;
    }
    if (tid < 128) { BA[NPG * HID + tid] = 0.f; BB[NPG * HID + tid] = 0.f; }
    __syncthreads();

    // ---------- Phase B: BA[j][h] = dis[j]*(x[j].W1[:,h]) own rows ----------
    // W1 (128x64) in SMT..ZP scratch; x (75x128) in BUFB; k split across 2 warp groups.
    {
        float* wst = sm + OFF_SMT;  // 8192 floats
        float* xs  = BB;            // 9600 floats
        for (int idx = tid; idx < NFEAT * HID; idx += TPB) wst[idx] = W1[idx];
        for (int idx = tid; idx < HALF * NFEAT; idx += TPB)
            xs[idx] = x[(size_t)(base + row0 + (idx >> 7)) * NFEAT + (idx & 127)];
        __syncthreads();

        const int kg = w >> 4;        // k-group 0/1
        const int wl = w & 15;        // 0..15
        const bool act = (wl < 15);
        const int r0 = wl * 5;
        float2 acc[5];
#pragma unroll
        for (int r = 0; r < 5; ++r) acc[r] = make_float2(0.f, 0.f);
        if (act) {
            const int k0 = kg * 64;
            for (int kk = 0; kk < 64; kk += 4) {
                int k = k0 + kk;
                float2 w0 = *(const float2*)(wst + (k + 0) * HID + 2 * lane);
                float2 w1 = *(const float2*)(wst + (k + 1) * HID + 2 * lane);
                float2 w2 = *(const float2*)(wst + (k + 2) * HID + 2 * lane);
                float2 w3 = *(const float2*)(wst + (k + 3) * HID + 2 * lane);
#pragma unroll
                for (int r = 0; r < 5; ++r) {
                    float4 xv = *(const float4*)(xs + (r0 + r) * NFEAT + k);
                    acc[r].x += xv.x * w0.x + xv.y * w1.x + xv.z * w2.x + xv.w * w3.x;
                    acc[r].y += xv.x * w0.y + xv.y * w1.y + xv.z * w2.y + xv.w * w3.y;
                }
            }
        }
        __syncthreads();   // W1 scratch dead
        float* P1 = sm + OFF_SMT;   // 75*64 partials
        if (act && kg == 1) {
#pragma unroll
            for (int r = 0; r < 5; ++r)
                *(float2*)(P1 + (r0 + r) * 64 + 2 * lane) = acc[r];
        }
        __syncthreads();
        if (act && kg == 0) {
#pragma unroll
            for (int r = 0; r < 5; ++r) {
                int l = r0 + r;
                float2 p = *(const float2*)(P1 + l * 64 + 2 * lane);
                float d = DISL[l];
                float vx = (acc[r].x + p.x) * d;
                float vy = (acc[r].y + p.y) * d;
                int fo = OFF_BUFA + (row0 + l) * HID + 2 * lane;
                *(float2*)(sm + fo) = make_float2(vx, vy);
                st_rem2(rbase + 4u * (unsigned int)fo, vx, vy);
            }
        }
    }
    CLUSTER_SYNC();

    // ---------- Phase C1: Z1 = relu(sparse agg(BA)) -> BB (LOCAL only; D is row-local) ----------
    agg_sp<true, false>(sm, COLS, WKM, DISL, OFF_BUFA, OFF_BUFB, b1, tid, row0, rbase);
    __syncthreads();

    // ---------- Phase D: BA[j][h] = dis[j]*(Z1[j].W2[:,h]) own rows, k-split ----------
    {
        float* wfl = sm + OFF_SMT;          // W2 64*64 = 4096
        float* P1  = sm + OFF_SMT + 4096;   // 75*64 partials (disjoint)
        for (int idx = tid; idx < HID * HID; idx += TPB) wfl[idx] = W2[idx];
        __syncthreads();

        const int kg = w >> 4;
        const int wl = w & 15;
        const bool act = (wl < 15);
        const int r0 = wl * 5;
        float2 acc[5];
#pragma unroll
        for (int r = 0; r < 5; ++r) acc[r] = make_float2(0.f, 0.f);
        if (act) {
            const int k0 = kg * 32;
            for (int kk = 0; kk < 32; kk += 4) {
                int k = k0 + kk;
                float2 w0 = *(const float2*)(wfl + (k + 0) * HID + 2 * lane);
                float2 w1 = *(const float2*)(wfl + (k + 1) * HID + 2 * lane);
                float2 w2 = *(const float2*)(wfl + (k + 2) * HID + 2 * lane);
                float2 w3 = *(const float2*)(wfl + (k + 3) * HID + 2 * lane);
#pragma unroll
                for (int r = 0; r < 5; ++r) {
                    float4 zv = *(const float4*)(BB + (row0 + r0 + r) * HID + k);
                    acc[r].x += zv.x * w0.x + zv.y * w1.x + zv.z * w2.x + zv.w * w3.x;
                    acc[r].y += zv.x * w0.y + zv.y * w1.y + zv.z * w2.y + zv.w * w3.y;
                }
            }
            if (kg == 1) {
#pragma unroll
                for (int r = 0; r < 5; ++r)
                    *(float2*)(P1 + (r0 + r) * 64 + 2 * lane) = acc[r];
            }
        }
        __syncthreads();
        if (act && kg == 0) {
#pragma unroll
            for (int r = 0; r < 5; ++r) {
                int l = r0 + r;
                float2 p = *(const float2*)(P1 + l * 64 + 2 * lane);
                float d = DISL[l];
                float vx = (acc[r].x + p.x) * d;
                float vy = (acc[r].y + p.y) * d;
                int fo = OFF_BUFA + (row0 + l) * HID + 2 * lane;
                *(float2*)(sm + fo) = make_float2(vx, vy);
                st_rem2(rbase + 4u * (unsigned int)fo, vx, vy);
            }
        }
    }
    CLUSTER_SYNC();

    // ---------- Phase C2: Z2 = relu(sparse agg(BA)) -> BB both (H needs full Z2) ----------
    agg_sp<true, true>(sm, COLS, WKM, DISL, OFF_BUFA, OFF_BUFB, b2, tid, row0, rbase);
    __syncthreads();

    // ---------- Phase E: tmpS[j][c] = dis[j]*(Z2[j].Wa[:,c]) own rows -> SMT both ----------
    // re-zero SMT/ST pads (clobbered by B/D scratch) + stage Wa
    if (tid < 2 * CP) SMT[NPG * CP + tid] = 0.f;
    if (tid < 2 * CL) ST[(tid >> 1) * 152 + NPG + (tid & 1)] = 0.f;
    for (int idx = tid; idx < HID * CL; idx += TPB) ZP[idx] = Wa[idx];
    __syncthreads();
    {
        const int cidx = min(c32, CL - 1);
        int lz[3];
#pragma unroll
        for (int r = 0; r < 3; ++r) lz[r] = (row0 + min(w + 32 * r, HALF - 1)) * HID;
        float acc[3] = {0.f, 0.f, 0.f};
        for (int k = 0; k < HID; k += 4) {
            float w0 = ZP[(k + 0) * CL + cidx];
            float w1 = ZP[(k + 1) * CL + cidx];
            float w2 = ZP[(k + 2) * CL + cidx];
            float w3 = ZP[(k + 3) * CL + cidx];
#pragma unroll
            for (int r = 0; r < 3; ++r) {
                float4 zv = *(const float4*)(BB + lz[r] + k);
                acc[r] += zv.x * w0 + zv.y * w1 + zv.z * w2 + zv.w * w3;
            }
        }
        if (c32 < CL) {
#pragma unroll
            for (int r = 0; r < 3; ++r) {
                int l = w + 32 * r;
                if (l < HALF) {
                    float v = acc[r] * DISL[l];
                    int fo = OFF_SMT + (row0 + l) * CP + c32;
                    sm[fo] = v;
                    st_rem(rbase + 4u * (unsigned int)fo, v);
                }
            }
        }
    }
    CLUSTER_SYNC();

    // ---------- Phase F+G: logits (sparse over tmpS) + warp softmax -> S into BA both + ST both ----------
    {
        const int kmax = WKM[w];
        const int cidx = min(c32, CL - 1);
        int lrow[3], rl[3];
#pragma unroll
        for (int r = 0; r < 3; ++r) {
            lrow[r] = w + 32 * r;
            rl[r] = min(lrow[r], HALF - 1) * MAXC;
        }
        float acc[3] = {0.f, 0.f, 0.f};
        for (int k = 0; k < kmax; k += 4) {
#pragma unroll
            for (int r = 0; r < 3; ++r) {
                int4 c4 = *(const int4*)(COLS + rl[r] + k);
                acc[r] += SMT[c4.x * CP + c32] + SMT[c4.y * CP + c32]
                        + SMT[c4.z * CP + c32] + SMT[c4.w * CP + c32];
            }
        }
        float bac = ba[cidx];
#pragma unroll
        for (int r = 0; r < 3; ++r) {
            int lc = min(lrow[r], HALF - 1);
            float logit = DISL[lc] * acc[r] + bac;
            float mv = (c32 < CL) ? logit : -3.0e38f;
#pragma unroll
            for (int off = 16; off; off >>= 1)
                mv = fmaxf(mv, __shfl_xor_sync(0xffffffffu, mv, off));
            float e = (c32 < CL) ? expf(logit - mv) : 0.f;
            float s = e;
#pragma unroll
            for (int off = 16; off; off >>= 1)
                s += __shfl_xor_sync(0xffffffffu, s, off);
            float sv = e * (1.f / s);
            if (lrow[r] < HALF && c32 < CL) {
                int gi = row0 + lrow[r];
                int fo = OFF_BUFA + gi * HID + c32;
                sm[fo] = sv;
                st_rem(rbase + 4u * (unsigned int)fo, sv);
                int ft = OFF_ST + c32 * 152 + gi;
                sm[ft] = sv;
                st_rem(rbase + 4u * (unsigned int)ft, sv);
            }
        }
    }
    CLUSTER_SYNC();

    // ---------- Phase I: AS[i][c] = sum_cols S[col][c] - S[i][c] (S in BA) -> SMT both ----------
    {
        const int kmax = WKM[w];
        int rl[3];
#pragma unroll
        for (int r = 0; r < 3; ++r) rl[r] = min(w + 32 * r, HALF - 1) * MAXC;
        float acc[3] = {0.f, 0.f, 0.f};
        for (int k = 0; k < kmax; k += 4) {
#pragma unroll
            for (int r = 0; r < 3; ++r) {
                int4 c4 = *(const int4*)(COLS + rl[r] + k);
                acc[r] += BA[c4.x * HID + c32] + BA[c4.y * HID + c32]
                        + BA[c4.z * HID + c32] + BA[c4.w * HID + c32];
            }
        }
        if (c32 < CL) {
#pragma unroll
            for (int r = 0; r < 3; ++r) {
                int l = w + 32 * r;
                if (l < HALF) {
                    int gi = row0 + l;
                    float v = acc[r] - BA[gi * HID + c32];
                    int fo = OFF_SMT + gi * CP + c32;
                    sm[fo] = v;
                    st_rem(rbase + 4u * (unsigned int)fo, v);
                }
            }
        }
    }
    CLUSTER_SYNC();

    // ---------- Phase H (split by cluster) / J ----------
    if (rank == 0) {
        // H part 1: c = 0..15
        if (w < 8) {
            const int hh = (w & 1) * 32 + lane;
            const int cb = (w >> 1) * 4;
            float acc[4] = {0.f, 0.f, 0.f, 0.f};
            for (int j = 0; j < 152; j += 4) {
                float z0 = BB[(j + 0) * HID + hh];
                float z1 = BB[(j + 1) * HID + hh];
                float z2 = BB[(j + 2) * HID + hh];
                float z3 = BB[(j + 3) * HID + hh];
#pragma unroll
                for (int o = 0; o < 4; ++o) {
                    float4 s = *(const float4*)(ST + (cb + o) * 152 + j);
                    acc[o] += s.x * z0 + s.y * z1 + s.z * z2 + s.w * z3;
                }
            }
#pragma unroll
            for (int o = 0; o < 4; ++o) {
                int fo = OFF_ZP + (cb + o) * HID + hh;
                sm[fo] = acc[o];
                st_rem(rbase + 4u * (unsigned int)fo, acc[o]);
            }
        }
    } else {
        // H part 2: c = 16..24
        if (w < 6) {
            const int hh = (w & 1) * 32 + lane;
            const int cb = 16 + (w >> 1) * 4;
            float acc[4] = {0.f, 0.f, 0.f, 0.f};
            for (int j = 0; j < 152; j += 4) {
                float z0 = BB[(j + 0) * HID + hh];
                float z1 = BB[(j + 1) * HID + hh];
                float z2 = BB[(j + 2) * HID + hh];
                float z3 = BB[(j + 3) * HID + hh];
#pragma unroll
                for (int o = 0; o < 4; ++o) {
                    int c = cb + o;
                    if (c < CL) {
                        float4 s = *(const float4*)(ST + c * 152 + j);
                        acc[o] += s.x * z0 + s.y * z1 + s.z * z2 + s.w * z3;
                    }
                }
            }
#pragma unroll
            for (int o = 0; o < 4; ++o) {
                int c = cb + o;
                if (c < CL) {
                    int fo = OFF_ZP + c * HID + hh;
                    sm[fo] = acc[o];
                    st_rem(rbase + 4u * (unsigned int)fo, acc[o]);
                }
            }
        } else {
            // J: Ap[cc][d] = sum_j S_T[cc][j] * AS[j][d]  (AS in SMT)
            int jt = tid - 192;
            if (jt < CL * CL) {
                int cc = jt / CL, d = jt - cc * CL;
                float acc = 0.f;
                for (int j = 0; j < 152; j += 4) {
                    float4 s = *(const float4*)(ST + cc * 152 + j);
                    acc += s.x * SMT[(j + 0) * CP + d] + s.y * SMT[(j + 1) * CP + d]
                         + s.z * SMT[(j + 2) * CP + d] + s.w * SMT[(j + 3) * CP + d];
                }
                int fo = OFF_AP + cc * CP + d;
                sm[fo] = acc;
                st_rem(rbase + 4u * (unsigned int)fo, acc);
            }
        }
    }
    CLUSTER_SYNC();

    // ---------- Phase K: pooled degrees (redundant) ----------
    if (tid < CL) {
        float s = 1.0f;
        for (int d = 0; d < CL; ++d) s += AP[tid * CP + d];
        DISP[tid] = rsqrtf(fmaxf(s, 1e-12f));
    }
    __syncthreads();

    // ---------- Phase L: BA[c][h] = disp[c]*(Zp[c].Wp[:,h]) (redundant) ----------
    for (int idx = tid; idx < HID * HID; idx += TPB) BB[idx] = Wp[idx];
    __syncthreads();
    for (int idx = tid; idx < CL * HID; idx += TPB) {
        int cc = idx >> 6, hh = idx & 63;
        float acc = 0.f;
        for (int k = 0; k < HID; k += 4) {
            float4 zv = *(const float4*)(ZP + cc * HID + k);
            acc += zv.x * BB[(k + 0) * HID + hh] + zv.y * BB[(k + 1) * HID + hh]
                 + zv.z * BB[(k + 2) * HID + hh] + zv.w * BB[(k + 3) * HID + hh];
        }
        BA[cc * HID + hh] = acc * DISP[cc];
    }
    __syncthreads();

    // ---------- Phase M: Hp = relu(disp[i]*sum_c (Ap+I)[i][c]*BA[c][h] + bp) -> ZP ----------
    for (int idx = tid; idx < CL * HID; idx += TPB) {
        int i = idx >> 6, hh = idx & 63;
        float acc = 0.f;
#pragma unroll
        for (int cc = 0; cc < CL; ++cc) {
            float av = AP[i * CP + cc] + ((i == cc) ? 1.f : 0.f);
            acc += av * BA[cc * HID + hh];
        }
        ZP[i * HID + hh] = fmaxf(DISP[i] * acc + bp[hh], 0.f);
    }
    __syncthreads();

    // ---------- Phase N: readout ----------
    if (tid < HID) {
        float s = 0.f;
#pragma unroll
        for (int i = 0; i < CL; ++i) s += ZP[i * HID + tid];
        GV[tid] = s;
    }
    __syncthreads();

    // ---------- Phase O: logits (rank 0 writes) ----------
    if (rank == 0 && tid < NCLS) {
        float acc = bc[tid];
#pragma unroll
        for (int k = 0; k < HID; ++k) acc += GV[k] * Wc[k * NCLS + tid];
        out[g * NCLS + tid] = acc;
    }
}

extern "C" void kernel_launch(void* const* d_in, const int* in_sizes, int n_in,
                              void* d_out, int out_size)
{
    const float* x  = (const float*)d_in[0];
    const float* a  = (const float*)d_in[1];
    const float* W1 = (const float*)d_in[4];
    const float* b1 = (const float*)d_in[5];
    const float* W2 = (const float*)d_in[6];
    const float* b2 = (const float*)d_in[7];
    const float* Wa = (const float*)d_in[8];
    const float* ba = (const float*)d_in[9];
    const float* Wp = (const float*)d_in[10];
    const float* bp = (const float*)d_in[11];
    const float* Wc = (const float*)d_in[12];
    const float* bc = (const float*)d_in[13];
    float* out = (float*)d_out;

    int B = out_size / NCLS;   // 64 graphs
    size_t smem = (size_t)SMEM_FLOATS * sizeof(float);
    cudaFuncSetAttribute(gcn_diffpool, cudaFuncAttributeMaxDynamicSharedMemorySize, (int)smem);
    gcn_diffpool<<<B * 2, TPB, smem>>>(x, a, W1, b1, W2, b2, Wa, ba, Wp, bp, Wc, bc, out);
}

// round 11
// speedup vs baseline: 2.3982x; 1.0442x over previous
#include <cuda_runtime.h>
#include <cstdint>

#define TPB    1024
#define NPG    150      // nodes per graph
#define HALF   75       // rows per CTA (2 CTAs per graph)
#define HID    64
#define CL     25
#define CP     26       // padded cluster stride
#define NFEAT  128
#define NCLS   10
#define NTOT   9600
#define MAXC   48       // max neighbors+self per row (multiple of 4 for int4 reads)

// ---- shared memory layout (float offsets) ----
#define OFF_COLS  0                          // 75*48 ints = 3600
#define OFF_WKM   (OFF_COLS + HALF*MAXC)     // 32 ints (per-warp kmax, 3-row map)
#define OFF_RC    (OFF_WKM + 32)             // 80 ints (per-row nnz count)
#define OFF_DIS   (OFF_RC + 80)              // 80 floats
#define OFF_BUFA  (OFF_DIS + 80)             // 152*64 = 9728 (pad rows zero)
#define OFF_BUFB  (OFF_BUFA + 152*HID)       // 152*64 = 9728 (x staging in B)
#define OFF_SMT   (OFF_BUFB + 152*HID)       // 152*26 = 3952 (scratch with ST/ZP)
#define OFF_ST    (OFF_SMT + 152*CP)         // 25*152 = 3800 (S transposed)
#define OFF_ZP    (OFF_ST + CL*152)          // 25*64 = 1600
#define OFF_AP    (OFF_ZP + CL*HID)          // 25*26+6 = 656
#define OFF_DISP  (OFF_AP + CL*CP + 6)       // 32
#define OFF_GV    (OFF_DISP + 32)            // 64
#define SMEM_FLOATS (OFF_GV + 64)            // ~33352 floats = ~133.4 KB

#define CLUSTER_SYNC() do { \
    asm volatile("barrier.cluster.arrive.aligned;" ::: "memory"); \
    asm volatile("barrier.cluster.wait.aligned;"   ::: "memory"); } while (0)

__device__ __forceinline__ unsigned int smem_u32(const void* p) {
    unsigned int a;
    asm("{ .reg .u64 t; cvta.to.shared.u64 t, %1; cvt.u32.u64 %0, t; }"
        : "=r"(a) : "l"(p));
    return a;
}
__device__ __forceinline__ void st_rem(unsigned int addr, float v) {
    asm volatile("st.shared::cluster.f32 [%0], %1;" :: "r"(addr), "f"(v));
}
__device__ __forceinline__ void st_rem2(unsigned int addr, float vx, float vy) {
    unsigned long long p;
    asm("mov.b64 %0, {%1,%2};" : "=l"(p) : "f"(vx), "f"(vy));
    asm volatile("st.shared::cluster.b64 [%0], %1;" :: "r"(addr), "l"(p));
}
// acc(f32x2) += (a,a) * b(f32x2)
__device__ __forceinline__ void fma2(unsigned long long& acc, float a, unsigned long long b) {
    asm("{\n\t.reg .b64 t;\n\tmov.b64 t, {%1, %1};\n\tfma.rn.f32x2 %0, t, %2, %0;\n\t}"
        : "+l"(acc) : "f"(a), "l"(b));
}
__device__ __forceinline__ float2 unpack2(unsigned long long v) {
    float2 r;
    asm("mov.b64 {%0, %1}, %2;" : "=f"(r.x), "=f"(r.y) : "l"(v));
    return r;
}

// Sparse aggregate: out[i][h] = act(dis[i]*sum_{c in cols[i]} in[c][h] + bias[h]).
// 32 warps x 3 rows, float2 per lane, int4 column reads.
template<bool RELU, bool REMOTE>
__device__ __forceinline__ void agg_sp(float* sm, const int* COLS, const int* WKM,
                                       const float* DISL, int in_off, int out_off,
                                       const float* __restrict__ bias,
                                       int tid, int row0, unsigned int rbase)
{
    const int lane = tid & 31, w = tid >> 5;
    const int kmax = WKM[w];
    int rl[3];
#pragma unroll
    for (int r = 0; r < 3; ++r) rl[r] = min(w + 32 * r, HALF - 1) * MAXC;
    float2 acc[3];
#pragma unroll
    for (int r = 0; r < 3; ++r) acc[r] = make_float2(0.f, 0.f);
    const float2* IN2 = (const float2*)(sm + in_off);
    for (int k = 0; k < kmax; k += 4) {
        int4 c0 = *(const int4*)(COLS + rl[0] + k);
        int4 c1 = *(const int4*)(COLS + rl[1] + k);
        int4 c2 = *(const int4*)(COLS + rl[2] + k);
        float2 v;
        v = IN2[c0.x * 32 + lane]; acc[0].x += v.x; acc[0].y += v.y;
        v = IN2[c0.y * 32 + lane]; acc[0].x += v.x; acc[0].y += v.y;
        v = IN2[c0.z * 32 + lane]; acc[0].x += v.x; acc[0].y += v.y;
        v = IN2[c0.w * 32 + lane]; acc[0].x += v.x; acc[0].y += v.y;
        v = IN2[c1.x * 32 + lane]; acc[1].x += v.x; acc[1].y += v.y;
        v = IN2[c1.y * 32 + lane]; acc[1].x += v.x; acc[1].y += v.y;
        v = IN2[c1.z * 32 + lane]; acc[1].x += v.x; acc[1].y += v.y;
        v = IN2[c1.w * 32 + lane]; acc[1].x += v.x; acc[1].y += v.y;
        v = IN2[c2.x * 32 + lane]; acc[2].x += v.x; acc[2].y += v.y;
        v = IN2[c2.y * 32 + lane]; acc[2].x += v.x; acc[2].y += v.y;
        v = IN2[c2.z * 32 + lane]; acc[2].x += v.x; acc[2].y += v.y;
        v = IN2[c2.w * 32 + lane]; acc[2].x += v.x; acc[2].y += v.y;
    }
    float2 bv = *(const float2*)(bias + 2 * lane);
#pragma unroll
    for (int r = 0; r < 3; ++r) {
        int l = w + 32 * r;
        if (l < HALF) {
            float d = DISL[l];
            float vx = d * acc[r].x + bv.x;
            float vy = d * acc[r].y + bv.y;
            if (RELU) { vx = fmaxf(vx, 0.f); vy = fmaxf(vy, 0.f); }
            int fo = out_off + (row0 + l) * HID + 2 * lane;
            *(float2*)(sm + fo) = make_float2(vx, vy);
            if (REMOTE) st_rem2(rbase + 4u * (unsigned int)fo, vx, vy);
        }
    }
}

__global__ void __launch_bounds__(TPB, 1) __cluster_dims__(2, 1, 1)
gcn_diffpool(const float* __restrict__ x,  const float* __restrict__ a,
             const float* __restrict__ W1, const float* __restrict__ b1,
             const float* __restrict__ W2, const float* __restrict__ b2,
             const float* __restrict__ Wa, const float* __restrict__ ba,
             const float* __restrict__ Wp, const float* __restrict__ bp,
             const float* __restrict__ Wc, const float* __restrict__ bc,
             float* __restrict__ out)
{
    extern __shared__ float sm[];
    int*   COLS = (int*)(sm + OFF_COLS);
    int*   WKM  = (int*)(sm + OFF_WKM);
    int*   RCNT = (int*)(sm + OFF_RC);
    float* DISL = sm + OFF_DIS;
    float* BA   = sm + OFF_BUFA;
    float* BB   = sm + OFF_BUFB;
    float* SMT  = sm + OFF_SMT;
    float* ST   = sm + OFF_ST;
    float* ZP   = sm + OFF_ZP;
    float* AP   = sm + OFF_AP;
    float* DISP = sm + OFF_DISP;
    float* GV   = sm + OFF_GV;

    const int tid  = threadIdx.x;
    const int g    = blockIdx.x >> 1;
    const int base = g * NPG;
    const int lane = tid & 31;
    const int w    = tid >> 5;              // 0..31
    const int c32  = lane;

    unsigned int rank;
    asm("mov.u32 %0, %%cluster_ctarank;" : "=r"(rank));
    const int row0 = (int)rank * HALF;
    unsigned int rbase;
    {
        unsigned int lbase = smem_u32(sm);
        unsigned int peer = rank ^ 1u;
        asm("mapa.shared::cluster.u32 %0, %1, %2;" : "=r"(rbase) : "r"(lbase), "r"(peer));
    }

    // ---------- Stage x (BUFB) and W1 (SMT scratch) early: latency hides under A ----------
    {
        float* wst = sm + OFF_SMT;
        float* xs  = BB;
        for (int idx = tid; idx < HALF * NFEAT; idx += TPB)
            xs[idx] = x[(size_t)(base + row0 + (idx >> 7)) * NFEAT + (idx & 127)];
        for (int idx = tid; idx < NFEAT * HID; idx += TPB) wst[idx] = W1[idx];
    }
    if (tid < 128) { BA[NPG * HID + tid] = 0.f; BB[NPG * HID + tid] = 0.f; }

    // ---------- Phase A: build CSR (neighbors + self), degrees; 3 rows/warp ----------
    {
        float vv[3][5];
#pragma unroll
        for (int r = 0; r < 3; ++r) {
            int l = min(w + 32 * r, HALF - 1);
            const float* arow = a + (size_t)(base + row0 + l) * NTOT + base;
#pragma unroll
            for (int ch = 0; ch < 5; ++ch) {
                int col = ch * 32 + lane;
                vv[r][ch] = (col < NPG) ? arow[col] : 0.f;
            }
        }
        int wkm = 0;
#pragma unroll
        for (int r = 0; r < 3; ++r) {
            int l = w + 32 * r;
            if (l < HALF) {
                int self = row0 + l;
                int cnt = 0;
#pragma unroll
                for (int ch = 0; ch < 5; ++ch) {
                    int col = ch * 32 + lane;
                    bool nz = (col < NPG) && (vv[r][ch] != 0.f || col == self);
                    unsigned m = __ballot_sync(0xffffffffu, nz);
                    if (nz) {
                        int p = cnt + __popc(m & ((1u << lane) - 1u));
                        if (p < MAXC) COLS[l * MAXC + p] = col;
                    }
                    cnt += __popc(m);
                }
                int cc = min(cnt, MAXC);
                for (int kk = cc + lane; kk < MAXC; kk += 32) COLS[l * MAXC + kk] = NPG;
                if (lane == 0) { DISL[l] = rsqrtf((float)cnt); RCNT[l] = cc; }
                wkm = max(wkm, cc);
            }
        }
        if (lane == 0) WKM[w] = wkm;
    }
    __syncthreads();

    // ---------- Phase B: BA[j][h] = dis[j]*(x[j].W1[:,h]) own rows, FFMA2, k-split ----------
    {
        float* wst = sm + OFF_SMT;
        float* xs  = BB;
        const int kg = w >> 4;        // k-group 0/1
        const int wl = w & 15;        // 0..15
        const bool act = (wl < 15);
        const int r0 = wl * 5;
        unsigned long long acc[5] = {0ull, 0ull, 0ull, 0ull, 0ull};
        if (act) {
            const int k0 = kg * 64;
            for (int kk = 0; kk < 64; kk += 4) {
                int k = k0 + kk;
                unsigned long long w0 = *(const unsigned long long*)(wst + (k + 0) * HID + 2 * lane);
                unsigned long long w1 = *(const unsigned long long*)(wst + (k + 1) * HID + 2 * lane);
                unsigned long long w2 = *(const unsigned long long*)(wst + (k + 2) * HID + 2 * lane);
                unsigned long long w3 = *(const unsigned long long*)(wst + (k + 3) * HID + 2 * lane);
#pragma unroll
                for (int r = 0; r < 5; ++r) {
                    float4 xv = *(const float4*)(xs + (r0 + r) * NFEAT + k);
                    fma2(acc[r], xv.x, w0);
                    fma2(acc[r], xv.y, w1);
                    fma2(acc[r], xv.z, w2);
                    fma2(acc[r], xv.w, w3);
                }
            }
        }
        __syncthreads();   // W1 scratch dead
        float* P1 = sm + OFF_SMT;   // 75*64 partials
        if (act && kg == 1) {
#pragma unroll
            for (int r = 0; r < 5; ++r)
                *(float2*)(P1 + (r0 + r) * 64 + 2 * lane) = unpack2(acc[r]);
        }
        __syncthreads();
        if (act && kg == 0) {
#pragma unroll
            for (int r = 0; r < 5; ++r) {
                int l = r0 + r;
                float2 p = *(const float2*)(P1 + l * 64 + 2 * lane);
                float2 m = unpack2(acc[r]);
                float d = DISL[l];
                float vx = (m.x + p.x) * d;
                float vy = (m.y + p.y) * d;
                int fo = OFF_BUFA + (row0 + l) * HID + 2 * lane;
                *(float2*)(sm + fo) = make_float2(vx, vy);
                st_rem2(rbase + 4u * (unsigned int)fo, vx, vy);
            }
        }
    }
    CLUSTER_SYNC();

    // ---------- Phase C1: Z1 = relu(sparse agg(BA)) -> BB (LOCAL; D is row-local) ----------
    agg_sp<true, false>(sm, COLS, WKM, DISL, OFF_BUFA, OFF_BUFB, b1, tid, row0, rbase);
    __syncthreads();

    // ---------- Phase D: BA[j][h] = dis[j]*(Z1[j].W2[:,h]) own rows, FFMA2, k-split ----------
    {
        float* wfl = sm + OFF_SMT;          // W2 64*64 = 4096
        float* P1  = sm + OFF_SMT + 4096;   // 75*64 partials (disjoint, in ST scratch)
        for (int idx = tid; idx < HID * HID; idx += TPB) wfl[idx] = W2[idx];
        __syncthreads();

        const int kg = w >> 4;
        const int wl = w & 15;
        const bool act = (wl < 15);
        const int r0 = wl * 5;
        unsigned long long acc[5] = {0ull, 0ull, 0ull, 0ull, 0ull};
        if (act) {
            const int k0 = kg * 32;
            for (int kk = 0; kk < 32; kk += 4) {
                int k = k0 + kk;
                unsigned long long w0 = *(const unsigned long long*)(wfl + (k + 0) * HID + 2 * lane);
                unsigned long long w1 = *(const unsigned long long*)(wfl + (k + 1) * HID + 2 * lane);
                unsigned long long w2 = *(const unsigned long long*)(wfl + (k + 2) * HID + 2 * lane);
                unsigned long long w3 = *(const unsigned long long*)(wfl + (k + 3) * HID + 2 * lane);
#pragma unroll
                for (int r = 0; r < 5; ++r) {
                    float4 zv = *(const float4*)(BB + (row0 + r0 + r) * HID + k);
                    fma2(acc[r], zv.x, w0);
                    fma2(acc[r], zv.y, w1);
                    fma2(acc[r], zv.z, w2);
                    fma2(acc[r], zv.w, w3);
                }
            }
            if (kg == 1) {
#pragma unroll
                for (int r = 0; r < 5; ++r)
                    *(float2*)(P1 + (r0 + r) * 64 + 2 * lane) = unpack2(acc[r]);
            }
        }
        __syncthreads();
        if (act && kg == 0) {
#pragma unroll
            for (int r = 0; r < 5; ++r) {
                int l = r0 + r;
                float2 p = *(const float2*)(P1 + l * 64 + 2 * lane);
                float2 m = unpack2(acc[r]);
                float d = DISL[l];
                float vx = (m.x + p.x) * d;
                float vy = (m.y + p.y) * d;
                int fo = OFF_BUFA + (row0 + l) * HID + 2 * lane;
                *(float2*)(sm + fo) = make_float2(vx, vy);
                st_rem2(rbase + 4u * (unsigned int)fo, vx, vy);
            }
        }
    }
    CLUSTER_SYNC();

    // ---------- Phase C2: Z2 = relu(sparse agg(BA)) -> BB both (H needs full Z2) ----------
    agg_sp<true, true>(sm, COLS, WKM, DISL, OFF_BUFA, OFF_BUFB, b2, tid, row0, rbase);
    __syncthreads();

    // ---------- Phase E: tmpS[j][c] = dis[j]*(Z2[j].Wa[:,c]) own rows -> SMT both ----------
    if (tid < 2 * CP) SMT[NPG * CP + tid] = 0.f;
    if (tid < 2 * CL) ST[(tid >> 1) * 152 + NPG + (tid & 1)] = 0.f;
    for (int idx = tid; idx < HID * CL; idx += TPB) ZP[idx] = Wa[idx];
    __syncthreads();
    {
        const int cidx = min(c32, CL - 1);
        int lz[3];
#pragma unroll
        for (int r = 0; r < 3; ++r) lz[r] = (row0 + min(w + 32 * r, HALF - 1)) * HID;
        float acc[3] = {0.f, 0.f, 0.f};
        for (int k = 0; k < HID; k += 4) {
            float w0 = ZP[(k + 0) * CL + cidx];
            float w1 = ZP[(k + 1) * CL + cidx];
            float w2 = ZP[(k + 2) * CL + cidx];
            float w3 = ZP[(k + 3) * CL + cidx];
#pragma unroll
            for (int r = 0; r < 3; ++r) {
                float4 zv = *(const float4*)(BB + lz[r] + k);
                acc[r] += zv.x * w0 + zv.y * w1 + zv.z * w2 + zv.w * w3;
            }
        }
        if (c32 < CL) {
#pragma unroll
            for (int r = 0; r < 3; ++r) {
                int l = w + 32 * r;
                if (l < HALF) {
                    float v = acc[r] * DISL[l];
                    int fo = OFF_SMT + (row0 + l) * CP + c32;
                    sm[fo] = v;
                    st_rem(rbase + 4u * (unsigned int)fo, v);
                }
            }
        }
    }
    CLUSTER_SYNC();

    // ---------- Phase F+G: logits (sparse over tmpS) + warp softmax -> S into BA both + ST both ----------
    {
        const int kmax = WKM[w];
        const int cidx = min(c32, CL - 1);
        int lrow[3], rl[3];
#pragma unroll
        for (int r = 0; r < 3; ++r) {
            lrow[r] = w + 32 * r;
            rl[r] = min(lrow[r], HALF - 1) * MAXC;
        }
        float acc[3] = {0.f, 0.f, 0.f};
        for (int k = 0; k < kmax; k += 4) {
#pragma unroll
            for (int r = 0; r < 3; ++r) {
                int4 c4 = *(const int4*)(COLS + rl[r] + k);
                acc[r] += SMT[c4.x * CP + c32] + SMT[c4.y * CP + c32]
                        + SMT[c4.z * CP + c32] + SMT[c4.w * CP + c32];
            }
        }
        float bac = ba[cidx];
#pragma unroll
        for (int r = 0; r < 3; ++r) {
            int lc = min(lrow[r], HALF - 1);
            float logit = DISL[lc] * acc[r] + bac;
            float mv = (c32 < CL) ? logit : -3.0e38f;
#pragma unroll
            for (int off = 16; off; off >>= 1)
                mv = fmaxf(mv, __shfl_xor_sync(0xffffffffu, mv, off));
            float e = (c32 < CL) ? expf(logit - mv) : 0.f;
            float s = e;
#pragma unroll
            for (int off = 16; off; off >>= 1)
                s += __shfl_xor_sync(0xffffffffu, s, off);
            float sv = e * (1.f / s);
            if (lrow[r] < HALF && c32 < CL) {
                int gi = row0 + lrow[r];
                int fo = OFF_BUFA + gi * HID + c32;
                sm[fo] = sv;
                st_rem(rbase + 4u * (unsigned int)fo, sv);
                int ft = OFF_ST + c32 * 152 + gi;
                sm[ft] = sv;
                st_rem(rbase + 4u * (unsigned int)ft, sv);
            }
        }
    }
    CLUSTER_SYNC();

    // ---------- Phase I (warps 0-14) ∥ Phase H (warps 16+): concurrent ----------
    if (w < 15) {
        // I: AS[i][c] = sum_cols S[col][c] - S[i][c] (S in BA) -> SMT both. 5 rows/warp.
        int rl[5], kmax = 0;
#pragma unroll
        for (int r = 0; r < 5; ++r) {
            int l = w * 5 + r;
            rl[r] = l * MAXC;
            kmax = max(kmax, RCNT[l]);
        }
        float acc[5] = {0.f, 0.f, 0.f, 0.f, 0.f};
        for (int k = 0; k < kmax; k += 4) {
#pragma unroll
            for (int r = 0; r < 5; ++r) {
                int4 c4 = *(const int4*)(COLS + rl[r] + k);
                acc[r] += BA[c4.x * HID + c32] + BA[c4.y * HID + c32]
                        + BA[c4.z * HID + c32] + BA[c4.w * HID + c32];
            }
        }
        if (c32 < CL) {
#pragma unroll
            for (int r = 0; r < 5; ++r) {
                int gi = row0 + w * 5 + r;
                float v = acc[r] - BA[gi * HID + c32];
                int fo = OFF_SMT + gi * CP + c32;
                sm[fo] = v;
                st_rem(rbase + 4u * (unsigned int)fo, v);
            }
        }
    } else if (rank == 0) {
        // H part 1: c = 0..15 (warps 16-23)
        if (w >= 16 && w < 24) {
            int wh = w - 16;
            const int hh = (wh & 1) * 32 + lane;
            const int cb = (wh >> 1) * 4;
            float acc[4] = {0.f, 0.f, 0.f, 0.f};
            for (int j = 0; j < 152; j += 4) {
                float z0 = BB[(j + 0) * HID + hh];
                float z1 = BB[(j + 1) * HID + hh];
                float z2 = BB[(j + 2) * HID + hh];
                float z3 = BB[(j + 3) * HID + hh];
#pragma unroll
                for (int o = 0; o < 4; ++o) {
                    float4 s = *(const float4*)(ST + (cb + o) * 152 + j);
                    acc[o] += s.x * z0 + s.y * z1 + s.z * z2 + s.w * z3;
                }
            }
#pragma unroll
            for (int o = 0; o < 4; ++o) {
                int fo = OFF_ZP + (cb + o) * HID + hh;
                sm[fo] = acc[o];
                st_rem(rbase + 4u * (unsigned int)fo, acc[o]);
            }
        }
    } else {
        // H part 2: c = 16..24 (warps 16-21)
        if (w >= 16 && w < 22) {
            int wh = w - 16;
            const int hh = (wh & 1) * 32 + lane;
            const int cb = 16 + (wh >> 1) * 4;
            float acc[4] = {0.f, 0.f, 0.f, 0.f};
            for (int j = 0; j < 152; j += 4) {
                float z0 = BB[(j + 0) * HID + hh];
                float z1 = BB[(j + 1) * HID + hh];
                float z2 = BB[(j + 2) * HID + hh];
                float z3 = BB[(j + 3) * HID + hh];
#pragma unroll
                for (int o = 0; o < 4; ++o) {
                    int c = cb + o;
                    if (c < CL) {
                        float4 s = *(const float4*)(ST + c * 152 + j);
                        acc[o] += s.x * z0 + s.y * z1 + s.z * z2 + s.w * z3;
                    }
                }
            }
#pragma unroll
            for (int o = 0; o < 4; ++o) {
                int c = cb + o;
                if (c < CL) {
                    int fo = OFF_ZP + c * HID + hh;
                    sm[fo] = acc[o];
                    st_rem(rbase + 4u * (unsigned int)fo, acc[o]);
                }
            }
        }
    }
    CLUSTER_SYNC();

    // ---------- Phase J (redundant, local): Ap[cc][d] = sum_j S_T[cc][j] * AS[j][d] ----------
    if (tid < CL * CL) {
        int cc = tid / CL, d = tid - cc * CL;
        float acc = 0.f;
        for (int j = 0; j < 152; j += 4) {
            float4 s = *(const float4*)(ST + cc * 152 + j);
            acc += s.x * SMT[(j + 0) * CP + d] + s.y * SMT[(j + 1) * CP + d]
                 + s.z * SMT[(j + 2) * CP + d] + s.w * SMT[(j + 3) * CP + d];
        }
        AP[cc * CP + d] = acc;
    }
    __syncthreads();

    // ---------- Phase K: pooled degrees (redundant) ----------
    if (tid < CL) {
        float s = 1.0f;
        for (int d = 0; d < CL; ++d) s += AP[tid * CP + d];
        DISP[tid] = rsqrtf(fmaxf(s, 1e-12f));
    }
    __syncthreads();

    // ---------- Phase L: BA[c][h] = disp[c]*(Zp[c].Wp[:,h]) (redundant) ----------
    for (int idx = tid; idx < HID * HID; idx += TPB) BB[idx] = Wp[idx];
    __syncthreads();
    for (int idx = tid; idx < CL * HID; idx += TPB) {
        int cc = idx >> 6, hh = idx & 63;
        float acc = 0.f;
        for (int k = 0; k < HID; k += 4) {
            float4 zv = *(const float4*)(ZP + cc * HID + k);
            acc += zv.x * BB[(k + 0) * HID + hh] + zv.y * BB[(k + 1) * HID + hh]
                 + zv.z * BB[(k + 2) * HID + hh] + zv.w * BB[(k + 3) * HID + hh];
        }
        BA[cc * HID + hh] = acc * DISP[cc];
    }
    __syncthreads();

    // ---------- Phase M: Hp = relu(disp[i]*sum_c (Ap+I)[i][c]*BA[c][h] + bp) -> ZP ----------
    for (int idx = tid; idx < CL * HID; idx += TPB) {
        int i = idx >> 6, hh = idx & 63;
        float acc = 0.f;
#pragma unroll
        for (int cc = 0; cc < CL; ++cc) {
            float av = AP[i * CP + cc] + ((i == cc) ? 1.f : 0.f);
            acc += av * BA[cc * HID + hh];
        }
        ZP[i * HID + hh] = fmaxf(DISP[i] * acc + bp[hh], 0.f);
    }
    __syncthreads();

    // ---------- Phase N: readout ----------
    if (tid < HID) {
        float s = 0.f;
#pragma unroll
        for (int i = 0; i < CL; ++i) s += ZP[i * HID + tid];
        GV[tid] = s;
    }
    __syncthreads();

    // ---------- Phase O: logits (rank 0 writes) ----------
    if (rank == 0 && tid < NCLS) {
        float acc = bc[tid];
#pragma unroll
        for (int k = 0; k < HID; ++k) acc += GV[k] * Wc[k * NCLS + tid];
        out[g * NCLS + tid] = acc;
    }
}

extern "C" void kernel_launch(void* const* d_in, const int* in_sizes, int n_in,
                              void* d_out, int out_size)
{
    const float* x  = (const float*)d_in[0];
    const float* a  = (const float*)d_in[1];
    const float* W1 = (const float*)d_in[4];
    const float* b1 = (const float*)d_in[5];
    const float* W2 = (const float*)d_in[6];
    const float* b2 = (const float*)d_in[7];
    const float* Wa = (const float*)d_in[8];
    const float* ba = (const float*)d_in[9];
    const float* Wp = (const float*)d_in[10];
    const float* bp = (const float*)d_in[11];
    const float* Wc = (const float*)d_in[12];
    const float* bc = (const float*)d_in[13];
    float* out = (float*)d_out;

    int B = out_size / NCLS;   // 64 graphs
    size_t smem = (size_t)SMEM_FLOATS * sizeof(float);
    cudaFuncSetAttribute(gcn_diffpool, cudaFuncAttributeMaxDynamicSharedMemorySize, (int)smem);
    gcn_diffpool<<<B * 2, TPB, smem>>>(x, a, W1, b1, W2, b2, Wa, ba, Wp, bp, Wc, bc, out);
}

// round 12
// speedup vs baseline: 2.4982x; 1.0417x over previous
#include <cuda_runtime.h>
#include <cstdint>

#define TPB    1024
#define NPG    150      // nodes per graph
#define HALF   75       // rows per CTA (2 CTAs per graph)
#define HID    64
#define CL     25
#define CP     26       // padded cluster stride
#define NFEAT  128
#define NCLS   10
#define NTOT   9600
#define MAXC   48       // max neighbors+self per row (multiple of 4 for int4 reads)

// ---- shared memory layout (float offsets) ----
#define OFF_COLS  0                          // 75*48 ints = 3600
#define OFF_WKM   (OFF_COLS + HALF*MAXC)     // 32 ints (unused, layout keep)
#define OFF_RC    (OFF_WKM + 32)             // 80 ints (per-row nnz count)
#define OFF_DIS   (OFF_RC + 80)              // 80 floats
#define OFF_BUFA  (OFF_DIS + 80)             // 152*64 = 9728 (pad rows zero)
#define OFF_BUFB  (OFF_BUFA + 152*HID)       // 152*64 = 9728 (x staging in B)
#define OFF_SMT   (OFF_BUFB + 152*HID)       // 152*26 = 3952 (scratch with ST/ZP)
#define OFF_ST    (OFF_SMT + 152*CP)         // 25*152 = 3800 (S transposed)
#define OFF_ZP    (OFF_ST + CL*152)          // 25*64 = 1600
#define OFF_AP    (OFF_ZP + CL*HID)          // 25*26+6 = 656
#define OFF_DISP  (OFF_AP + CL*CP + 6)       // 32
#define OFF_GV    (OFF_DISP + 32)            // 64
#define SMEM_FLOATS (OFF_GV + 64)            // ~33352 floats = ~133.4 KB

#define CLUSTER_SYNC() do { \
    asm volatile("barrier.cluster.arrive.aligned;" ::: "memory"); \
    asm volatile("barrier.cluster.wait.aligned;"   ::: "memory"); } while (0)

__device__ __forceinline__ unsigned int smem_u32(const void* p) {
    unsigned int a;
    asm("{ .reg .u64 t; cvta.to.shared.u64 t, %1; cvt.u32.u64 %0, t; }"
        : "=r"(a) : "l"(p));
    return a;
}
__device__ __forceinline__ void st_rem(unsigned int addr, float v) {
    asm volatile("st.shared::cluster.f32 [%0], %1;" :: "r"(addr), "f"(v));
}
__device__ __forceinline__ void st_rem2(unsigned int addr, float vx, float vy) {
    unsigned long long p;
    asm("mov.b64 %0, {%1,%2};" : "=l"(p) : "f"(vx), "f"(vy));
    asm volatile("st.shared::cluster.b64 [%0], %1;" :: "r"(addr), "l"(p));
}
// acc(f32x2) += (a,a) * b(f32x2)
__device__ __forceinline__ void fma2(unsigned long long& acc, float a, unsigned long long b) {
    asm("{\n\t.reg .b64 t;\n\tmov.b64 t, {%1, %1};\n\tfma.rn.f32x2 %0, t, %2, %0;\n\t}"
        : "+l"(acc) : "f"(a), "l"(b));
}
__device__ __forceinline__ float2 unpack2(unsigned long long v) {
    float2 r;
    asm("mov.b64 {%0, %1}, %2;" : "=f"(r.x), "=f"(r.y) : "l"(v));
    return r;
}

// Sparse aggregate: out[i][h] = act(dis[i]*sum_{c in cols[i]} in[c][h] + bias[h]).
// 25 warps x 3 contiguous rows (exact cover), float2 per lane, int4 column reads.
template<bool RELU, bool REMOTE>
__device__ __forceinline__ void agg_sp(float* sm, const int* COLS, const int* RCNT,
                                       const float* DISL, int in_off, int out_off,
                                       const float* __restrict__ bias,
                                       int tid, int row0, unsigned int rbase)
{
    const int lane = tid & 31, w = tid >> 5;
    if (w >= 25) return;
    const int l0 = w * 3;
    const int kmax = max(RCNT[l0], max(RCNT[l0 + 1], RCNT[l0 + 2]));
    float2 acc[3];
#pragma unroll
    for (int r = 0; r < 3; ++r) acc[r] = make_float2(0.f, 0.f);
    const float2* IN2 = (const float2*)(sm + in_off);
    const int rb = l0 * MAXC;
    for (int k = 0; k < kmax; k += 4) {
        int4 c0 = *(const int4*)(COLS + rb + k);
        int4 c1 = *(const int4*)(COLS + rb + MAXC + k);
        int4 c2 = *(const int4*)(COLS + rb + 2 * MAXC + k);
        float2 v;
        v = IN2[c0.x * 32 + lane]; acc[0].x += v.x; acc[0].y += v.y;
        v = IN2[c0.y * 32 + lane]; acc[0].x += v.x; acc[0].y += v.y;
        v = IN2[c0.z * 32 + lane]; acc[0].x += v.x; acc[0].y += v.y;
        v = IN2[c0.w * 32 + lane]; acc[0].x += v.x; acc[0].y += v.y;
        v = IN2[c1.x * 32 + lane]; acc[1].x += v.x; acc[1].y += v.y;
        v = IN2[c1.y * 32 + lane]; acc[1].x += v.x; acc[1].y += v.y;
        v = IN2[c1.z * 32 + lane]; acc[1].x += v.x; acc[1].y += v.y;
        v = IN2[c1.w * 32 + lane]; acc[1].x += v.x; acc[1].y += v.y;
        v = IN2[c2.x * 32 + lane]; acc[2].x += v.x; acc[2].y += v.y;
        v = IN2[c2.y * 32 + lane]; acc[2].x += v.x; acc[2].y += v.y;
        v = IN2[c2.z * 32 + lane]; acc[2].x += v.x; acc[2].y += v.y;
        v = IN2[c2.w * 32 + lane]; acc[2].x += v.x; acc[2].y += v.y;
    }
    float2 bv = *(const float2*)(bias + 2 * lane);
#pragma unroll
    for (int r = 0; r < 3; ++r) {
        int l = l0 + r;
        float d = DISL[l];
        float vx = d * acc[r].x + bv.x;
        float vy = d * acc[r].y + bv.y;
        if (RELU) { vx = fmaxf(vx, 0.f); vy = fmaxf(vy, 0.f); }
        int fo = out_off + (row0 + l) * HID + 2 * lane;
        *(float2*)(sm + fo) = make_float2(vx, vy);
        if (REMOTE) st_rem2(rbase + 4u * (unsigned int)fo, vx, vy);
    }
}

__global__ void __launch_bounds__(TPB, 1) __cluster_dims__(2, 1, 1)
gcn_diffpool(const float* __restrict__ x,  const float* __restrict__ a,
             const float* __restrict__ W1, const float* __restrict__ b1,
             const float* __restrict__ W2, const float* __restrict__ b2,
             const float* __restrict__ Wa, const float* __restrict__ ba,
             const float* __restrict__ Wp, const float* __restrict__ bp,
             const float* __restrict__ Wc, const float* __restrict__ bc,
             float* __restrict__ out)
{
    extern __shared__ float sm[];
    int*   COLS = (int*)(sm + OFF_COLS);
    int*   RCNT = (int*)(sm + OFF_RC);
    float* DISL = sm + OFF_DIS;
    float* BA   = sm + OFF_BUFA;
    float* BB   = sm + OFF_BUFB;
    float* SMT  = sm + OFF_SMT;
    float* ST   = sm + OFF_ST;
    float* ZP   = sm + OFF_ZP;
    float* AP   = sm + OFF_AP;
    float* DISP = sm + OFF_DISP;
    float* GV   = sm + OFF_GV;

    const int tid  = threadIdx.x;
    const int g    = blockIdx.x >> 1;
    const int base = g * NPG;
    const int lane = tid & 31;
    const int w    = tid >> 5;              // 0..31
    const int c32  = lane;

    unsigned int rank;
    asm("mov.u32 %0, %%cluster_ctarank;" : "=r"(rank));
    const int row0 = (int)rank * HALF;
    unsigned int rbase;
    {
        unsigned int lbase = smem_u32(sm);
        unsigned int peer = rank ^ 1u;
        asm("mapa.shared::cluster.u32 %0, %1, %2;" : "=r"(rbase) : "r"(lbase), "r"(peer));
    }

    // ---------- Stage x (BUFB) and W1 (SMT scratch) early ----------
    {
        float* wst = sm + OFF_SMT;
        float* xs  = BB;
        for (int idx = tid; idx < HALF * NFEAT; idx += TPB)
            xs[idx] = x[(size_t)(base + row0 + (idx >> 7)) * NFEAT + (idx & 127)];
        for (int idx = tid; idx < NFEAT * HID; idx += TPB) wst[idx] = W1[idx];
    }
    if (tid < 128) { BA[NPG * HID + tid] = 0.f; BB[NPG * HID + tid] = 0.f; }

    // ---------- Phase A: build CSR (neighbors + self), degrees; 3 rows/warp ----------
    {
        float vv[3][5];
#pragma unroll
        for (int r = 0; r < 3; ++r) {
            int l = min(w + 32 * r, HALF - 1);
            const float* arow = a + (size_t)(base + row0 + l) * NTOT + base;
#pragma unroll
            for (int ch = 0; ch < 5; ++ch) {
                int col = ch * 32 + lane;
                vv[r][ch] = (col < NPG) ? arow[col] : 0.f;
            }
        }
#pragma unroll
        for (int r = 0; r < 3; ++r) {
            int l = w + 32 * r;
            if (l < HALF) {
                int self = row0 + l;
                int cnt = 0;
#pragma unroll
                for (int ch = 0; ch < 5; ++ch) {
                    int col = ch * 32 + lane;
                    bool nz = (col < NPG) && (vv[r][ch] != 0.f || col == self);
                    unsigned m = __ballot_sync(0xffffffffu, nz);
                    if (nz) {
                        int p = cnt + __popc(m & ((1u << lane) - 1u));
                        if (p < MAXC) COLS[l * MAXC + p] = col;
                    }
                    cnt += __popc(m);
                }
                int cc = min(cnt, MAXC);
                for (int kk = cc + lane; kk < MAXC; kk += 32) COLS[l * MAXC + kk] = NPG;
                if (lane == 0) { DISL[l] = rsqrtf((float)cnt); RCNT[l] = cc; }
            }
        }
    }
    __syncthreads();

    // ---------- Phase B: BA[j][h] = dis[j]*(x[j].W1[:,h]); 15 warps x 5 rows, full k ----------
    if (w < 15) {
        float* wst = sm + OFF_SMT;
        float* xs  = BB;
        const int r0 = w * 5;
        unsigned long long acc[5] = {0ull, 0ull, 0ull, 0ull, 0ull};
        for (int k = 0; k < NFEAT; k += 4) {
            unsigned long long w0 = *(const unsigned long long*)(wst + (k + 0) * HID + 2 * lane);
            unsigned long long w1 = *(const unsigned long long*)(wst + (k + 1) * HID + 2 * lane);
            unsigned long long w2 = *(const unsigned long long*)(wst + (k + 2) * HID + 2 * lane);
            unsigned long long w3 = *(const unsigned long long*)(wst + (k + 3) * HID + 2 * lane);
#pragma unroll
            for (int r = 0; r < 5; ++r) {
                float4 xv = *(const float4*)(xs + (r0 + r) * NFEAT + k);
                fma2(acc[r], xv.x, w0);
                fma2(acc[r], xv.y, w1);
                fma2(acc[r], xv.z, w2);
                fma2(acc[r], xv.w, w3);
            }
        }
#pragma unroll
        for (int r = 0; r < 5; ++r) {
            int l = r0 + r;
            float2 m = unpack2(acc[r]);
            float d = DISL[l];
            float vx = m.x * d, vy = m.y * d;
            int fo = OFF_BUFA + (row0 + l) * HID + 2 * lane;
            *(float2*)(sm + fo) = make_float2(vx, vy);
            st_rem2(rbase + 4u * (unsigned int)fo, vx, vy);
        }
    }
    CLUSTER_SYNC();

    // ---------- Phase C1 (warps 0-24) ∥ stage W2 (warps 25-31) ----------
    agg_sp<true, false>(sm, COLS, RCNT, DISL, OFF_BUFA, OFF_BUFB, b1, tid, row0, rbase);
    if (w >= 25) {
        float* wfl = sm + OFF_SMT;   // W2 64*64 = 4096 (scratch free: B done)
        for (int idx = tid - 800; idx < HID * HID; idx += 224) wfl[idx] = W2[idx];
    }
    __syncthreads();

    // ---------- Phase D: BA[j][h] = dis[j]*(Z1[j].W2[:,h]); 15 warps x 5 rows, full k ----------
    if (w < 15) {
        float* wfl = sm + OFF_SMT;
        const int r0 = w * 5;
        unsigned long long acc[5] = {0ull, 0ull, 0ull, 0ull, 0ull};
        for (int k = 0; k < HID; k += 4) {
            unsigned long long w0 = *(const unsigned long long*)(wfl + (k + 0) * HID + 2 * lane);
            unsigned long long w1 = *(const unsigned long long*)(wfl + (k + 1) * HID + 2 * lane);
            unsigned long long w2 = *(const unsigned long long*)(wfl + (k + 2) * HID + 2 * lane);
            unsigned long long w3 = *(const unsigned long long*)(wfl + (k + 3) * HID + 2 * lane);
#pragma unroll
            for (int r = 0; r < 5; ++r) {
                float4 zv = *(const float4*)(BB + (row0 + r0 + r) * HID + k);
                fma2(acc[r], zv.x, w0);
                fma2(acc[r], zv.y, w1);
                fma2(acc[r], zv.z, w2);
                fma2(acc[r], zv.w, w3);
            }
        }
#pragma unroll
        for (int r = 0; r < 5; ++r) {
            int l = r0 + r;
            float2 m = unpack2(acc[r]);
            float d = DISL[l];
            float vx = m.x * d, vy = m.y * d;
            int fo = OFF_BUFA + (row0 + l) * HID + 2 * lane;
            *(float2*)(sm + fo) = make_float2(vx, vy);
            st_rem2(rbase + 4u * (unsigned int)fo, vx, vy);
        }
    }
    CLUSTER_SYNC();

    // ---------- Phase C2 (warps 0-24, remote) ∥ stage Wa + zero pads (warps 25-31) ----------
    agg_sp<true, true>(sm, COLS, RCNT, DISL, OFF_BUFA, OFF_BUFB, b2, tid, row0, rbase);
    if (w >= 25) {
        int t = tid - 800;
        for (int idx = t; idx < HID * CL; idx += 224) ZP[idx] = Wa[idx];
        if (t < 2 * CP) SMT[NPG * CP + t] = 0.f;
        if (t < 2 * CL) ST[(t >> 1) * 152 + NPG + (t & 1)] = 0.f;
    }
    __syncthreads();

    // ---------- Phase E: tmpS[j][c] = dis[j]*(Z2[j].Wa[:,c]); 25 warps x 3 rows -> SMT both ----------
    if (w < 25) {
        const int cidx = min(c32, CL - 1);
        const int l0 = w * 3;
        float acc[3] = {0.f, 0.f, 0.f};
        for (int k = 0; k < HID; k += 4) {
            float w0 = ZP[(k + 0) * CL + cidx];
            float w1 = ZP[(k + 1) * CL + cidx];
            float w2 = ZP[(k + 2) * CL + cidx];
            float w3 = ZP[(k + 3) * CL + cidx];
#pragma unroll
            for (int r = 0; r < 3; ++r) {
                float4 zv = *(const float4*)(BB + (row0 + l0 + r) * HID + k);
                acc[r] += zv.x * w0 + zv.y * w1 + zv.z * w2 + zv.w * w3;
            }
        }
        if (c32 < CL) {
#pragma unroll
            for (int r = 0; r < 3; ++r) {
                int l = l0 + r;
                float v = acc[r] * DISL[l];
                int fo = OFF_SMT + (row0 + l) * CP + c32;
                sm[fo] = v;
                st_rem(rbase + 4u * (unsigned int)fo, v);
            }
        }
    }
    CLUSTER_SYNC();

    // ---------- Phase F+G: logits (sparse over tmpS) + warp softmax; 25 warps x 3 rows ----------
    if (w < 25) {
        const int cidx = min(c32, CL - 1);
        const int l0 = w * 3;
        const int kmax = max(RCNT[l0], max(RCNT[l0 + 1], RCNT[l0 + 2]));
        const int rb = l0 * MAXC;
        float acc[3] = {0.f, 0.f, 0.f};
        for (int k = 0; k < kmax; k += 4) {
#pragma unroll
            for (int r = 0; r < 3; ++r) {
                int4 c4 = *(const int4*)(COLS + rb + r * MAXC + k);
                acc[r] += SMT[c4.x * CP + c32] + SMT[c4.y * CP + c32]
                        + SMT[c4.z * CP + c32] + SMT[c4.w * CP + c32];
            }
        }
        float bac = ba[cidx];
#pragma unroll
        for (int r = 0; r < 3; ++r) {
            int l = l0 + r;
            float logit = DISL[l] * acc[r] + bac;
            float mv = (c32 < CL) ? logit : -3.0e38f;
#pragma unroll
            for (int off = 16; off; off >>= 1)
                mv = fmaxf(mv, __shfl_xor_sync(0xffffffffu, mv, off));
            float e = (c32 < CL) ? expf(logit - mv) : 0.f;
            float s = e;
#pragma unroll
            for (int off = 16; off; off >>= 1)
                s += __shfl_xor_sync(0xffffffffu, s, off);
            float sv = e * (1.f / s);
            if (c32 < CL) {
                int gi = row0 + l;
                int fo = OFF_BUFA + gi * HID + c32;
                sm[fo] = sv;
                st_rem(rbase + 4u * (unsigned int)fo, sv);
                int ft = OFF_ST + c32 * 152 + gi;
                sm[ft] = sv;
                st_rem(rbase + 4u * (unsigned int)ft, sv);
            }
        }
    }
    CLUSTER_SYNC();

    // ---------- Phase I (warps 0-14) ∥ Phase H (warps 16+): concurrent ----------
    if (w < 15) {
        // I: AS[i][c] = sum_cols S[col][c] - S[i][c] (S in BA) -> SMT both. 5 rows/warp.
        int rl[5], kmax = 0;
#pragma unroll
        for (int r = 0; r < 5; ++r) {
            int l = w * 5 + r;
            rl[r] = l * MAXC;
            kmax = max(kmax, RCNT[l]);
        }
        float acc[5] = {0.f, 0.f, 0.f, 0.f, 0.f};
        for (int k = 0; k < kmax; k += 4) {
#pragma unroll
            for (int r = 0; r < 5; ++r) {
                int4 c4 = *(const int4*)(COLS + rl[r] + k);
                acc[r] += BA[c4.x * HID + c32] + BA[c4.y * HID + c32]
                        + BA[c4.z * HID + c32] + BA[c4.w * HID + c32];
            }
        }
        if (c32 < CL) {
#pragma unroll
            for (int r = 0; r < 5; ++r) {
                int gi = row0 + w * 5 + r;
                float v = acc[r] - BA[gi * HID + c32];
                int fo = OFF_SMT + gi * CP + c32;
                sm[fo] = v;
                st_rem(rbase + 4u * (unsigned int)fo, v);
            }
        }
    } else if (rank == 0) {
        // H part 1: c = 0..15 (warps 16-23)
        if (w >= 16 && w < 24) {
            int wh = w - 16;
            const int hh = (wh & 1) * 32 + lane;
            const int cb = (wh >> 1) * 4;
            float acc[4] = {0.f, 0.f, 0.f, 0.f};
            for (int j = 0; j < 152; j += 4) {
                float z0 = BB[(j + 0) * HID + hh];
                float z1 = BB[(j + 1) * HID + hh];
                float z2 = BB[(j + 2) * HID + hh];
                float z3 = BB[(j + 3) * HID + hh];
#pragma unroll
                for (int o = 0; o < 4; ++o) {
                    float4 s = *(const float4*)(ST + (cb + o) * 152 + j);
                    acc[o] += s.x * z0 + s.y * z1 + s.z * z2 + s.w * z3;
                }
            }
#pragma unroll
            for (int o = 0; o < 4; ++o) {
                int fo = OFF_ZP + (cb + o) * HID + hh;
                sm[fo] = acc[o];
                st_rem(rbase + 4u * (unsigned int)fo, acc[o]);
            }
        }
    } else {
        // H part 2: c = 16..24 (warps 16-21)
        if (w >= 16 && w < 22) {
            int wh = w - 16;
            const int hh = (wh & 1) * 32 + lane;
            const int cb = 16 + (wh >> 1) * 4;
            float acc[4] = {0.f, 0.f, 0.f, 0.f};
            for (int j = 0; j < 152; j += 4) {
                float z0 = BB[(j + 0) * HID + hh];
                float z1 = BB[(j + 1) * HID + hh];
                float z2 = BB[(j + 2) * HID + hh];
                float z3 = BB[(j + 3) * HID + hh];
#pragma unroll
                for (int o = 0; o < 4; ++o) {
                    int c = cb + o;
                    if (c < CL) {
                        float4 s = *(const float4*)(ST + c * 152 + j);
                        acc[o] += s.x * z0 + s.y * z1 + s.z * z2 + s.w * z3;
                    }
                }
            }
#pragma unroll
            for (int o = 0; o < 4; ++o) {
                int c = cb + o;
                if (c < CL) {
                    int fo = OFF_ZP + c * HID + hh;
                    sm[fo] = acc[o];
                    st_rem(rbase + 4u * (unsigned int)fo, acc[o]);
                }
            }
        }
    }
    CLUSTER_SYNC();

    // ---------- Phase J (redundant, local): Ap[cc][d] = sum_j S_T[cc][j] * AS[j][d] ----------
    if (tid < CL * CL) {
        int cc = tid / CL, d = tid - cc * CL;
        float acc = 0.f;
        for (int j = 0; j < 152; j += 4) {
            float4 s = *(const float4*)(ST + cc * 152 + j);
            acc += s.x * SMT[(j + 0) * CP + d] + s.y * SMT[(j + 1) * CP + d]
                 + s.z * SMT[(j + 2) * CP + d] + s.w * SMT[(j + 3) * CP + d];
        }
        AP[cc * CP + d] = acc;
    }
    __syncthreads();

    // ---------- Phase K: pooled degrees (redundant) ----------
    if (tid < CL) {
        float s = 1.0f;
        for (int d = 0; d < CL; ++d) s += AP[tid * CP + d];
        DISP[tid] = rsqrtf(fmaxf(s, 1e-12f));
    }
    __syncthreads();

    // ---------- Phase L: BA[c][h] = disp[c]*(Zp[c].Wp[:,h]) (redundant) ----------
    for (int idx = tid; idx < HID * HID; idx += TPB) BB[idx] = Wp[idx];
    __syncthreads();
    for (int idx = tid; idx < CL * HID; idx += TPB) {
        int cc = idx >> 6, hh = idx & 63;
        float acc = 0.f;
        for (int k = 0; k < HID; k += 4) {
            float4 zv = *(const float4*)(ZP + cc * HID + k);
            acc += zv.x * BB[(k + 0) * HID + hh] + zv.y * BB[(k + 1) * HID + hh]
                 + zv.z * BB[(k + 2) * HID + hh] + zv.w * BB[(k + 3) * HID + hh];
        }
        BA[cc * HID + hh] = acc * DISP[cc];
    }
    __syncthreads();

    // ---------- Phase M: Hp = relu(disp[i]*sum_c (Ap+I)[i][c]*BA[c][h] + bp) -> ZP ----------
    for (int idx = tid; idx < CL * HID; idx += TPB) {
        int i = idx >> 6, hh = idx & 63;
        float acc = 0.f;
#pragma unroll
        for (int cc = 0; cc < CL; ++cc) {
            float av = AP[i * CP + cc] + ((i == cc) ? 1.f : 0.f);
            acc += av * BA[cc * HID + hh];
        }
        ZP[i * HID + hh] = fmaxf(DISP[i] * acc + bp[hh], 0.f);
    }
    __syncthreads();

    // ---------- Phase N: readout ----------
    if (tid < HID) {
        float s = 0.f;
#pragma unroll
        for (int i = 0; i < CL; ++i) s += ZP[i * HID + tid];
        GV[tid] = s;
    }
    __syncthreads();

    // ---------- Phase O: logits (rank 0 writes) ----------
    if (rank == 0 && tid < NCLS) {
        float acc = bc[tid];
#pragma unroll
        for (int k = 0; k < HID; ++k) acc += GV[k] * Wc[k * NCLS + tid];
        out[g * NCLS + tid] = acc;
    }
}

extern "C" void kernel_launch(void* const* d_in, const int* in_sizes, int n_in,
                              void* d_out, int out_size)
{
    const float* x  = (const float*)d_in[0];
    const float* a  = (const float*)d_in[1];
    const float* W1 = (const float*)d_in[4];
    const float* b1 = (const float*)d_in[5];
    const float* W2 = (const float*)d_in[6];
    const float* b2 = (const float*)d_in[7];
    const float* Wa = (const float*)d_in[8];
    const float* ba = (const float*)d_in[9];
    const float* Wp = (const float*)d_in[10];
    const float* bp = (const float*)d_in[11];
    const float* Wc = (const float*)d_in[12];
    const float* bc = (const float*)d_in[13];
    float* out = (float*)d_out;

    int B = out_size / NCLS;   // 64 graphs
    size_t smem = (size_t)SMEM_FLOATS * sizeof(float);
    cudaFuncSetAttribute(gcn_diffpool, cudaFuncAttributeMaxDynamicSharedMemorySize, (int)smem);
    gcn_diffpool<<<B * 2, TPB, smem>>>(x, a, W1, b1, W2, b2, Wa, ba, Wp, bp, Wc, bc, out);
}

// round 13
// speedup vs baseline: 2.5371x; 1.0156x over previous
#include <cuda_runtime.h>
#include <cstdint>

#define TPB    768
#define NW     24
#define NPG    150      // nodes per graph
#define HALF   75       // rows per CTA (2 CTAs per graph)
#define HID    64
#define CL     25
#define CP     26       // padded cluster stride
#define NFEAT  128
#define NCLS   10
#define NTOT   9600
#define MAXC   48       // max neighbors+self per row (multiple of 4 for int4 reads)

// ---- shared memory layout (float offsets) ----
#define OFF_COLS  0                          // 75*48 ints = 3600
#define OFF_WKM   (OFF_COLS + HALF*MAXC)     // 32 ints (layout keep)
#define OFF_RC    (OFF_WKM + 32)             // 80 ints (per-row nnz count)
#define OFF_DIS   (OFF_RC + 80)              // 80 floats
#define OFF_BUFA  (OFF_DIS + 80)             // 152*64 = 9728 (pad rows zero)
#define OFF_BUFB  (OFF_BUFA + 152*HID)       // 152*64 = 9728 (x staging in B)
#define OFF_SMT   (OFF_BUFB + 152*HID)       // 152*26 = 3952 (scratch with ST/ZP)
#define OFF_ST    (OFF_SMT + 152*CP)         // 25*152 = 3800 (S transposed)
#define OFF_ZP    (OFF_ST + CL*152)          // 25*64 = 1600
#define OFF_AP    (OFF_ZP + CL*HID)          // 25*26+6 = 656
#define OFF_DISP  (OFF_AP + CL*CP + 6)       // 32
#define OFF_GV    (OFF_DISP + 32)            // 64
#define SMEM_FLOATS (OFF_GV + 64)            // ~33352 floats = ~133.4 KB

#define CLUSTER_SYNC() do { \
    asm volatile("barrier.cluster.arrive.aligned;" ::: "memory"); \
    asm volatile("barrier.cluster.wait.aligned;"   ::: "memory"); } while (0)

__device__ __forceinline__ unsigned int smem_u32(const void* p) {
    unsigned int a;
    asm("{ .reg .u64 t; cvta.to.shared.u64 t, %1; cvt.u32.u64 %0, t; }"
        : "=r"(a) : "l"(p));
    return a;
}
__device__ __forceinline__ void st_rem(unsigned int addr, float v) {
    asm volatile("st.shared::cluster.f32 [%0], %1;" :: "r"(addr), "f"(v));
}
__device__ __forceinline__ void st_rem2(unsigned int addr, float vx, float vy) {
    unsigned long long p;
    asm("mov.b64 %0, {%1,%2};" : "=l"(p) : "f"(vx), "f"(vy));
    asm volatile("st.shared::cluster.b64 [%0], %1;" :: "r"(addr), "l"(p));
}
// acc(f32x2) += (a,a) * b(f32x2)
__device__ __forceinline__ void fma2(unsigned long long& acc, float a, unsigned long long b) {
    asm("{\n\t.reg .b64 t;\n\tmov.b64 t, {%1, %1};\n\tfma.rn.f32x2 %0, t, %2, %0;\n\t}"
        : "+l"(acc) : "f"(a), "l"(b));
}
__device__ __forceinline__ float2 unpack2(unsigned long long v) {
    float2 r;
    asm("mov.b64 {%0, %1}, %2;" : "=f"(r.x), "=f"(r.y) : "l"(v));
    return r;
}

// Sparse aggregate: out[i][h] = act(dis[i]*sum_{c in cols[i]} in[c][h] + bias[h]).
// 15 warps x 5 contiguous rows (exact cover), float2 per lane, pipelined int4 col reads.
template<bool RELU, bool REMOTE>
__device__ __forceinline__ void agg_sp(float* sm, const int* COLS, const int* RCNT,
                                       const float* DISL, int in_off, int out_off,
                                       const float* __restrict__ bias,
                                       int tid, int row0, unsigned int rbase)
{
    const int lane = tid & 31, w = tid >> 5;
    if (w >= 15) return;
    const int l0 = w * 5;
    int kmax = RCNT[l0];
#pragma unroll
    for (int r = 1; r < 5; ++r) kmax = max(kmax, RCNT[l0 + r]);
    const int rb = l0 * MAXC;
    float2 acc[5];
#pragma unroll
    for (int r = 0; r < 5; ++r) acc[r] = make_float2(0.f, 0.f);
    const float2* IN2 = (const float2*)(sm + in_off);
    int4 c[5];
#pragma unroll
    for (int r = 0; r < 5; ++r) c[r] = *(const int4*)(COLS + rb + r * MAXC);
    for (int k = 0; k < kmax; k += 4) {
        const int kp = min(k + 4, MAXC - 4);   // prefetch stays within this row block
        int4 n[5];
#pragma unroll
        for (int r = 0; r < 5; ++r) n[r] = *(const int4*)(COLS + rb + r * MAXC + kp);
#pragma unroll
        for (int r = 0; r < 5; ++r) {
            float2 v;
            v = IN2[c[r].x * 32 + lane]; acc[r].x += v.x; acc[r].y += v.y;
            v = IN2[c[r].y * 32 + lane]; acc[r].x += v.x; acc[r].y += v.y;
            v = IN2[c[r].z * 32 + lane]; acc[r].x += v.x; acc[r].y += v.y;
            v = IN2[c[r].w * 32 + lane]; acc[r].x += v.x; acc[r].y += v.y;
        }
#pragma unroll
        for (int r = 0; r < 5; ++r) c[r] = n[r];
    }
    float2 bv = *(const float2*)(bias + 2 * lane);
#pragma unroll
    for (int r = 0; r < 5; ++r) {
        int l = l0 + r;
        float d = DISL[l];
        float vx = d * acc[r].x + bv.x;
        float vy = d * acc[r].y + bv.y;
        if (RELU) { vx = fmaxf(vx, 0.f); vy = fmaxf(vy, 0.f); }
        int fo = out_off + (row0 + l) * HID + 2 * lane;
        *(float2*)(sm + fo) = make_float2(vx, vy);
        if (REMOTE) st_rem2(rbase + 4u * (unsigned int)fo, vx, vy);
    }
}

__global__ void __launch_bounds__(TPB, 1) __cluster_dims__(2, 1, 1)
gcn_diffpool(const float* __restrict__ x,  const float* __restrict__ a,
             const float* __restrict__ W1, const float* __restrict__ b1,
             const float* __restrict__ W2, const float* __restrict__ b2,
             const float* __restrict__ Wa, const float* __restrict__ ba,
             const float* __restrict__ Wp, const float* __restrict__ bp,
             const float* __restrict__ Wc, const float* __restrict__ bc,
             float* __restrict__ out)
{
    extern __shared__ float sm[];
    int*   COLS = (int*)(sm + OFF_COLS);
    int*   RCNT = (int*)(sm + OFF_RC);
    float* DISL = sm + OFF_DIS;
    float* BA   = sm + OFF_BUFA;
    float* BB   = sm + OFF_BUFB;
    float* SMT  = sm + OFF_SMT;
    float* ST   = sm + OFF_ST;
    float* ZP   = sm + OFF_ZP;
    float* AP   = sm + OFF_AP;
    float* DISP = sm + OFF_DISP;
    float* GV   = sm + OFF_GV;

    const int tid  = threadIdx.x;
    const int g    = blockIdx.x >> 1;
    const int base = g * NPG;
    const int lane = tid & 31;
    const int w    = tid >> 5;              // 0..23
    const int c32  = lane;

    unsigned int rank;
    asm("mov.u32 %0, %%cluster_ctarank;" : "=r"(rank));
    const int row0 = (int)rank * HALF;
    unsigned int rbase;
    {
        unsigned int lbase = smem_u32(sm);
        unsigned int peer = rank ^ 1u;
        asm("mapa.shared::cluster.u32 %0, %1, %2;" : "=r"(rbase) : "r"(lbase), "r"(peer));
    }

    // ---------- Stage x (BUFB) and W1 (SMT scratch) early ----------
    {
        float* wst = sm + OFF_SMT;
        float* xs  = BB;
        for (int idx = tid; idx < HALF * NFEAT; idx += TPB)
            xs[idx] = x[(size_t)(base + row0 + (idx >> 7)) * NFEAT + (idx & 127)];
        for (int idx = tid; idx < NFEAT * HID; idx += TPB) wst[idx] = W1[idx];
    }
    if (tid < 128) { BA[NPG * HID + tid] = 0.f; BB[NPG * HID + tid] = 0.f; }

    // ---------- Phase A: build CSR (neighbors + self), degrees; 4 row-slots/warp ----------
    {
        float vv[4][5];
#pragma unroll
        for (int r = 0; r < 4; ++r) {
            int l = min(w + NW * r, HALF - 1);
            const float* arow = a + (size_t)(base + row0 + l) * NTOT + base;
#pragma unroll
            for (int ch = 0; ch < 5; ++ch) {
                int col = ch * 32 + lane;
                vv[r][ch] = (col < NPG) ? arow[col] : 0.f;
            }
        }
#pragma unroll
        for (int r = 0; r < 4; ++r) {
            int l = w + NW * r;
            if (l < HALF) {
                int self = row0 + l;
                int cnt = 0;
#pragma unroll
                for (int ch = 0; ch < 5; ++ch) {
                    int col = ch * 32 + lane;
                    bool nz = (col < NPG) && (vv[r][ch] != 0.f || col == self);
                    unsigned m = __ballot_sync(0xffffffffu, nz);
                    if (nz) {
                        int p = cnt + __popc(m & ((1u << lane) - 1u));
                        if (p < MAXC) COLS[l * MAXC + p] = col;
                    }
                    cnt += __popc(m);
                }
                int cc = min(cnt, MAXC);
                for (int kk = cc + lane; kk < MAXC; kk += 32) COLS[l * MAXC + kk] = NPG;
                if (lane == 0) { DISL[l] = rsqrtf((float)cnt); RCNT[l] = cc; }
            }
        }
    }
    __syncthreads();

    // ---------- Phase B: BA[j][h] = dis[j]*(x[j].W1[:,h]); 15 warps x 5 rows, full k ----------
    if (w < 15) {
        float* wst = sm + OFF_SMT;
        float* xs  = BB;
        const int r0 = w * 5;
        unsigned long long acc[5] = {0ull, 0ull, 0ull, 0ull, 0ull};
        for (int k = 0; k < NFEAT; k += 4) {
            unsigned long long w0 = *(const unsigned long long*)(wst + (k + 0) * HID + 2 * lane);
            unsigned long long w1 = *(const unsigned long long*)(wst + (k + 1) * HID + 2 * lane);
            unsigned long long w2 = *(const unsigned long long*)(wst + (k + 2) * HID + 2 * lane);
            unsigned long long w3 = *(const unsigned long long*)(wst + (k + 3) * HID + 2 * lane);
#pragma unroll
            for (int r = 0; r < 5; ++r) {
                float4 xv = *(const float4*)(xs + (r0 + r) * NFEAT + k);
                fma2(acc[r], xv.x, w0);
                fma2(acc[r], xv.y, w1);
                fma2(acc[r], xv.z, w2);
                fma2(acc[r], xv.w, w3);
            }
        }
#pragma unroll
        for (int r = 0; r < 5; ++r) {
            int l = r0 + r;
            float2 m = unpack2(acc[r]);
            float d = DISL[l];
            float vx = m.x * d, vy = m.y * d;
            int fo = OFF_BUFA + (row0 + l) * HID + 2 * lane;
            *(float2*)(sm + fo) = make_float2(vx, vy);
            st_rem2(rbase + 4u * (unsigned int)fo, vx, vy);
        }
    }
    CLUSTER_SYNC();

    // ---------- Phase C1 (warps 0-14) ∥ stage W2 (warps 15-23) ----------
    agg_sp<true, false>(sm, COLS, RCNT, DISL, OFF_BUFA, OFF_BUFB, b1, tid, row0, rbase);
    if (w >= 15) {
        float* wfl = sm + OFF_SMT;   // W2 64*64 = 4096 (scratch free: B done)
        for (int idx = tid - 480; idx < HID * HID; idx += 288) wfl[idx] = W2[idx];
    }
    __syncthreads();

    // ---------- Phase D: BA[j][h] = dis[j]*(Z1[j].W2[:,h]); 15 warps x 5 rows, full k ----------
    if (w < 15) {
        float* wfl = sm + OFF_SMT;
        const int r0 = w * 5;
        unsigned long long acc[5] = {0ull, 0ull, 0ull, 0ull, 0ull};
        for (int k = 0; k < HID; k += 4) {
            unsigned long long w0 = *(const unsigned long long*)(wfl + (k + 0) * HID + 2 * lane);
            unsigned long long w1 = *(const unsigned long long*)(wfl + (k + 1) * HID + 2 * lane);
            unsigned long long w2 = *(const unsigned long long*)(wfl + (k + 2) * HID + 2 * lane);
            unsigned long long w3 = *(const unsigned long long*)(wfl + (k + 3) * HID + 2 * lane);
#pragma unroll
            for (int r = 0; r < 5; ++r) {
                float4 zv = *(const float4*)(BB + (row0 + r0 + r) * HID + k);
                fma2(acc[r], zv.x, w0);
                fma2(acc[r], zv.y, w1);
                fma2(acc[r], zv.z, w2);
                fma2(acc[r], zv.w, w3);
            }
        }
#pragma unroll
        for (int r = 0; r < 5; ++r) {
            int l = r0 + r;
            float2 m = unpack2(acc[r]);
            float d = DISL[l];
            float vx = m.x * d, vy = m.y * d;
            int fo = OFF_BUFA + (row0 + l) * HID + 2 * lane;
            *(float2*)(sm + fo) = make_float2(vx, vy);
            st_rem2(rbase + 4u * (unsigned int)fo, vx, vy);
        }
    }
    CLUSTER_SYNC();

    // ---------- Phase C2 (warps 0-14, remote) ∥ stage Wa + zero pads (warps 15-23) ----------
    agg_sp<true, true>(sm, COLS, RCNT, DISL, OFF_BUFA, OFF_BUFB, b2, tid, row0, rbase);
    if (w >= 15) {
        int t = tid - 480;
        for (int idx = t; idx < HID * CL; idx += 288) ZP[idx] = Wa[idx];
        if (t < 2 * CP) SMT[NPG * CP + t] = 0.f;
        if (t < 2 * CL) ST[(t >> 1) * 152 + NPG + (t & 1)] = 0.f;
    }
    __syncthreads();

    // ---------- Phase E: tmpS[j][c] = dis[j]*(Z2[j].Wa[:,c]); 15 warps x 5 rows -> SMT both ----------
    if (w < 15) {
        const int cidx = min(c32, CL - 1);
        const int l0 = w * 5;
        float acc[5] = {0.f, 0.f, 0.f, 0.f, 0.f};
        for (int k = 0; k < HID; k += 4) {
            float w0 = ZP[(k + 0) * CL + cidx];
            float w1 = ZP[(k + 1) * CL + cidx];
            float w2 = ZP[(k + 2) * CL + cidx];
            float w3 = ZP[(k + 3) * CL + cidx];
#pragma unroll
            for (int r = 0; r < 5; ++r) {
                float4 zv = *(const float4*)(BB + (row0 + l0 + r) * HID + k);
                acc[r] += zv.x * w0 + zv.y * w1 + zv.z * w2 + zv.w * w3;
            }
        }
        if (c32 < CL) {
#pragma unroll
            for (int r = 0; r < 5; ++r) {
                int l = l0 + r;
                float v = acc[r] * DISL[l];
                int fo = OFF_SMT + (row0 + l) * CP + c32;
                sm[fo] = v;
                st_rem(rbase + 4u * (unsigned int)fo, v);
            }
        }
    }
    CLUSTER_SYNC();

    // ---------- Phase F+G: logits (sparse over tmpS) + warp softmax; 15 warps x 5 rows ----------
    if (w < 15) {
        const int cidx = min(c32, CL - 1);
        const int l0 = w * 5;
        int kmax = RCNT[l0];
#pragma unroll
        for (int r = 1; r < 5; ++r) kmax = max(kmax, RCNT[l0 + r]);
        const int rb = l0 * MAXC;
        float acc[5] = {0.f, 0.f, 0.f, 0.f, 0.f};
        for (int k = 0; k < kmax; k += 4) {
#pragma unroll
            for (int r = 0; r < 5; ++r) {
                int4 c4 = *(const int4*)(COLS + rb + r * MAXC + k);
                acc[r] += SMT[c4.x * CP + c32] + SMT[c4.y * CP + c32]
                        + SMT[c4.z * CP + c32] + SMT[c4.w * CP + c32];
            }
        }
        float bac = ba[cidx];
#pragma unroll
        for (int r = 0; r < 5; ++r) {
            int l = l0 + r;
            float logit = DISL[l] * acc[r] + bac;
            float mv = (c32 < CL) ? logit : -3.0e38f;
#pragma unroll
            for (int off = 16; off; off >>= 1)
                mv = fmaxf(mv, __shfl_xor_sync(0xffffffffu, mv, off));
            float e = (c32 < CL) ? expf(logit - mv) : 0.f;
            float s = e;
#pragma unroll
            for (int off = 16; off; off >>= 1)
                s += __shfl_xor_sync(0xffffffffu, s, off);
            float sv = e * (1.f / s);
            if (c32 < CL) {
                int gi = row0 + l;
                int fo = OFF_BUFA + gi * HID + c32;
                sm[fo] = sv;
                st_rem(rbase + 4u * (unsigned int)fo, sv);
                int ft = OFF_ST + c32 * 152 + gi;
                sm[ft] = sv;
                st_rem(rbase + 4u * (unsigned int)ft, sv);
            }
        }
    }
    CLUSTER_SYNC();

    // ---------- Phase I (warps 0-14) ∥ Phase H (warps 16+): concurrent ----------
    if (w < 15) {
        // I: AS[i][c] = sum_cols S[col][c] - S[i][c] (S in BA) -> SMT both. 5 rows/warp.
        int rl[5], kmax = 0;
#pragma unroll
        for (int r = 0; r < 5; ++r) {
            int l = w * 5 + r;
            rl[r] = l * MAXC;
            kmax = max(kmax, RCNT[l]);
        }
        float acc[5] = {0.f, 0.f, 0.f, 0.f, 0.f};
        for (int k = 0; k < kmax; k += 4) {
#pragma unroll
            for (int r = 0; r < 5; ++r) {
                int4 c4 = *(const int4*)(COLS + rl[r] + k);
                acc[r] += BA[c4.x * HID + c32] + BA[c4.y * HID + c32]
                        + BA[c4.z * HID + c32] + BA[c4.w * HID + c32];
            }
        }
        if (c32 < CL) {
#pragma unroll
            for (int r = 0; r < 5; ++r) {
                int gi = row0 + w * 5 + r;
                float v = acc[r] - BA[gi * HID + c32];
                int fo = OFF_SMT + gi * CP + c32;
                sm[fo] = v;
                st_rem(rbase + 4u * (unsigned int)fo, v);
            }
        }
    } else if (rank == 0) {
        // H part 1: c = 0..15 (warps 16-23)
        if (w >= 16) {
            int wh = w - 16;
            const int hh = (wh & 1) * 32 + lane;
            const int cb = (wh >> 1) * 4;
            float acc[4] = {0.f, 0.f, 0.f, 0.f};
            for (int j = 0; j < 152; j += 4) {
                float z0 = BB[(j + 0) * HID + hh];
                float z1 = BB[(j + 1) * HID + hh];
                float z2 = BB[(j + 2) * HID + hh];
                float z3 = BB[(j + 3) * HID + hh];
#pragma unroll
                for (int o = 0; o < 4; ++o) {
                    float4 s = *(const float4*)(ST + (cb + o) * 152 + j);
                    acc[o] += s.x * z0 + s.y * z1 + s.z * z2 + s.w * z3;
                }
            }
#pragma unroll
            for (int o = 0; o < 4; ++o) {
                int fo = OFF_ZP + (cb + o) * HID + hh;
                sm[fo] = acc[o];
                st_rem(rbase + 4u * (unsigned int)fo, acc[o]);
            }
        }
    } else {
        // H part 2: c = 16..24 (warps 16-21)
        if (w >= 16 && w < 22) {
            int wh = w - 16;
            const int hh = (wh & 1) * 32 + lane;
            const int cb = 16 + (wh >> 1) * 4;
            float acc[4] = {0.f, 0.f, 0.f, 0.f};
            for (int j = 0; j < 152; j += 4) {
                float z0 = BB[(j + 0) * HID + hh];
                float z1 = BB[(j + 1) * HID + hh];
                float z2 = BB[(j + 2) * HID + hh];
                float z3 = BB[(j + 3) * HID + hh];
#pragma unroll
                for (int o = 0; o < 4; ++o) {
                    int c = cb + o;
                    if (c < CL) {
                        float4 s = *(const float4*)(ST + c * 152 + j);
                        acc[o] += s.x * z0 + s.y * z1 + s.z * z2 + s.w * z3;
                    }
                }
            }
#pragma unroll
            for (int o = 0; o < 4; ++o) {
                int c = cb + o;
                if (c < CL) {
                    int fo = OFF_ZP + c * HID + hh;
                    sm[fo] = acc[o];
                    st_rem(rbase + 4u * (unsigned int)fo, acc[o]);
                }
            }
        }
    }
    CLUSTER_SYNC();

    // ---------- Phase J (redundant, local) ∥ stage Wp -> BB (BB dead after H) ----------
    if (tid < CL * CL) {
        int cc = tid / CL, d = tid - cc * CL;
        float acc = 0.f;
        for (int j = 0; j < 152; j += 4) {
            float4 s = *(const float4*)(ST + cc * 152 + j);
            acc += s.x * SMT[(j + 0) * CP + d] + s.y * SMT[(j + 1) * CP + d]
                 + s.z * SMT[(j + 2) * CP + d] + s.w * SMT[(j + 3) * CP + d];
        }
        AP[cc * CP + d] = acc;
    }
    if (tid >= 640) {
        for (int idx = tid - 640; idx < HID * HID; idx += 128) BB[idx] = Wp[idx];
    }
    __syncthreads();

    // ---------- Phase K: pooled degrees (redundant) ----------
    if (tid < CL) {
        float s = 1.0f;
        for (int d = 0; d < CL; ++d) s += AP[tid * CP + d];
        DISP[tid] = rsqrtf(fmaxf(s, 1e-12f));
    }
    __syncthreads();

    // ---------- Phase L: BA[c][h] = disp[c]*(Zp[c].Wp[:,h]) (redundant; Wp in BB) ----------
    for (int idx = tid; idx < CL * HID; idx += TPB) {
        int cc = idx >> 6, hh = idx & 63;
        float acc = 0.f;
        for (int k = 0; k < HID; k += 4) {
            float4 zv = *(const float4*)(ZP + cc * HID + k);
            acc += zv.x * BB[(k + 0) * HID + hh] + zv.y * BB[(k + 1) * HID + hh]
                 + zv.z * BB[(k + 2) * HID + hh] + zv.w * BB[(k + 3) * HID + hh];
        }
        BA[cc * HID + hh] = acc * DISP[cc];
    }
    __syncthreads();

    // ---------- Phase M: Hp = relu(disp[i]*sum_c (Ap+I)[i][c]*BA[c][h] + bp) -> ZP ----------
    for (int idx = tid; idx < CL * HID; idx += TPB) {
        int i = idx >> 6, hh = idx & 63;
        float acc = 0.f;
#pragma unroll
        for (int cc = 0; cc < CL; ++cc) {
            float av = AP[i * CP + cc] + ((i == cc) ? 1.f : 0.f);
            acc += av * BA[cc * HID + hh];
        }
        ZP[i * HID + hh] = fmaxf(DISP[i] * acc + bp[hh], 0.f);
    }
    __syncthreads();

    // ---------- Phase N: readout ----------
    if (tid < HID) {
        float s = 0.f;
#pragma unroll
        for (int i = 0; i < CL; ++i) s += ZP[i * HID + tid];
        GV[tid] = s;
    }
    __syncthreads();

    // ---------- Phase O: logits (rank 0 writes) ----------
    if (rank == 0 && tid < NCLS) {
        float acc = bc[tid];
#pragma unroll
        for (int k = 0; k < HID; ++k) acc += GV[k] * Wc[k * NCLS + tid];
        out[g * NCLS + tid] = acc;
    }
}

extern "C" void kernel_launch(void* const* d_in, const int* in_sizes, int n_in,
                              void* d_out, int out_size)
{
    const float* x  = (const float*)d_in[0];
    const float* a  = (const float*)d_in[1];
    const float* W1 = (const float*)d_in[4];
    const float* b1 = (const float*)d_in[5];
    const float* W2 = (const float*)d_in[6];
    const float* b2 = (const float*)d_in[7];
    const float* Wa = (const float*)d_in[8];
    const float* ba = (const float*)d_in[9];
    const float* Wp = (const float*)d_in[10];
    const float* bp = (const float*)d_in[11];
    const float* Wc = (const float*)d_in[12];
    const float* bc = (const float*)d_in[13];
    float* out = (float*)d_out;

    int B = out_size / NCLS;   // 64 graphs
    size_t smem = (size_t)SMEM_FLOATS * sizeof(float);
    cudaFuncSetAttribute(gcn_diffpool, cudaFuncAttributeMaxDynamicSharedMemorySize, (int)smem);
    gcn_diffpool<<<B * 2, TPB, smem>>>(x, a, W1, b1, W2, b2, Wa, ba, Wp, bp, Wc, bc, out);
}

// round 14
// speedup vs baseline: 2.6350x; 1.0386x over previous
#include <cuda_runtime.h>
#include <cstdint>

#define TPB    768
#define NW     24
#define NPG    150      // nodes per graph
#define HALF   75       // rows per CTA (2 CTAs per graph)
#define HID    64
#define CL     25
#define CP     26       // padded cluster stride
#define NFEAT  128
#define NCLS   10
#define NTOT   9600
#define MAXC   48       // max neighbors+self per row (multiple of 4 for int4 reads)

// ---- shared memory layout (float offsets) ----
#define OFF_COLS  0                          // 75*48 ints = 3600
#define OFF_RC    (OFF_COLS + HALF*MAXC)     // 80 ints (per-row nnz count)
#define OFF_DIS   (OFF_RC + 80)              // 80 floats
#define OFF_BUFA  (OFF_DIS + 80)             // 152*64 = 9728 (pad rows zero)
#define OFF_BUFB  (OFF_BUFA + 152*HID)       // 152*64 = 9728 (x staging in B)
#define OFF_SMT   (OFF_BUFB + 152*HID)       // 152*26 = 3952 (scratch with ST/ZP)
#define OFF_ST    (OFF_SMT + 152*CP)         // 25*152 = 3800 (S transposed, full)
#define OFF_ZP    (OFF_ST + CL*152)          // 25*64 = 1600
#define OFF_AP    (OFF_ZP + CL*HID)          // 25*26+6 = 656
#define OFF_DISP  (OFF_AP + CL*CP + 6)       // 32
#define OFF_GV    (OFF_DISP + 32)            // 64
#define SMEM_FLOATS (OFF_GV + 64)

#define CLUSTER_SYNC() do { \
    asm volatile("barrier.cluster.arrive.aligned;" ::: "memory"); \
    asm volatile("barrier.cluster.wait.aligned;"   ::: "memory"); } while (0)

__device__ __forceinline__ unsigned int smem_u32(const void* p) {
    unsigned int a;
    asm("{ .reg .u64 t; cvta.to.shared.u64 t, %1; cvt.u32.u64 %0, t; }"
        : "=r"(a) : "l"(p));
    return a;
}
__device__ __forceinline__ void st_rem(unsigned int addr, float v) {
    asm volatile("st.shared::cluster.f32 [%0], %1;" :: "r"(addr), "f"(v));
}
__device__ __forceinline__ void st_rem2(unsigned int addr, float vx, float vy) {
    unsigned long long p;
    asm("mov.b64 %0, {%1,%2};" : "=l"(p) : "f"(vx), "f"(vy));
    asm volatile("st.shared::cluster.b64 [%0], %1;" :: "r"(addr), "l"(p));
}
// acc(f32x2) += (a,a) * b(f32x2)
__device__ __forceinline__ void fma2(unsigned long long& acc, float a, unsigned long long b) {
    asm("{\n\t.reg .b64 t;\n\tmov.b64 t, {%1, %1};\n\tfma.rn.f32x2 %0, t, %2, %0;\n\t}"
        : "+l"(acc) : "f"(a), "l"(b));
}
__device__ __forceinline__ float2 unpack2(unsigned long long v) {
    float2 r;
    asm("mov.b64 {%0, %1}, %2;" : "=f"(r.x), "=f"(r.y) : "l"(v));
    return r;
}

// Sparse aggregate: out[i][h] = act(dis[i]*sum_{c in cols[i]} in[c][h] + bias[h]).
// 15 warps x 5 contiguous rows, per-row early-exit predication.
// remote: nrem leading rows (absolute local index < nrem) also stored to peer.
template<bool RELU, bool REMOTE_ALL>
__device__ __forceinline__ void agg_sp(float* sm, const int* COLS, const int* RCNT,
                                       const float* DISL, int in_off, int out_off,
                                       const float* __restrict__ bias,
                                       int tid, int row0, unsigned int rbase, int nrem)
{
    const int lane = tid & 31, w = tid >> 5;
    if (w >= 15) return;
    const int l0 = w * 5;
    const int rb = l0 * MAXC;
    int cnt[5];
#pragma unroll
    for (int r = 0; r < 5; ++r) cnt[r] = RCNT[l0 + r];
    int kmax = cnt[0];
#pragma unroll
    for (int r = 1; r < 5; ++r) kmax = max(kmax, cnt[r]);
    float2 acc[5];
#pragma unroll
    for (int r = 0; r < 5; ++r) acc[r] = make_float2(0.f, 0.f);
    const float2* IN2 = (const float2*)(sm + in_off);
    for (int k = 0; k < kmax; k += 4) {
#pragma unroll
        for (int r = 0; r < 5; ++r) {
            if (k < cnt[r]) {
                int4 c4 = *(const int4*)(COLS + rb + r * MAXC + k);
                float2 v;
                v = IN2[c4.x * 32 + lane]; acc[r].x += v.x; acc[r].y += v.y;
                v = IN2[c4.y * 32 + lane]; acc[r].x += v.x; acc[r].y += v.y;
                v = IN2[c4.z * 32 + lane]; acc[r].x += v.x; acc[r].y += v.y;
                v = IN2[c4.w * 32 + lane]; acc[r].x += v.x; acc[r].y += v.y;
            }
        }
    }
    float2 bv = *(const float2*)(bias + 2 * lane);
#pragma unroll
    for (int r = 0; r < 5; ++r) {
        int l = l0 + r;
        float d = DISL[l];
        float vx = d * acc[r].x + bv.x;
        float vy = d * acc[r].y + bv.y;
        if (RELU) { vx = fmaxf(vx, 0.f); vy = fmaxf(vy, 0.f); }
        int fo = out_off + (row0 + l) * HID + 2 * lane;
        *(float2*)(sm + fo) = make_float2(vx, vy);
        if (REMOTE_ALL || l < nrem)
            st_rem2(rbase + 4u * (unsigned int)fo, vx, vy);
    }
}

__global__ void __launch_bounds__(TPB, 1) __cluster_dims__(2, 1, 1)
gcn_diffpool(const float* __restrict__ x,  const float* __restrict__ a,
             const float* __restrict__ W1, const float* __restrict__ b1,
             const float* __restrict__ W2, const float* __restrict__ b2,
             const float* __restrict__ Wa, const float* __restrict__ ba,
             const float* __restrict__ Wp, const float* __restrict__ bp,
             const float* __restrict__ Wc, const float* __restrict__ bc,
             float* __restrict__ out)
{
    extern __shared__ float sm[];
    int*   COLS = (int*)(sm + OFF_COLS);
    int*   RCNT = (int*)(sm + OFF_RC);
    float* DISL = sm + OFF_DIS;
    float* BA   = sm + OFF_BUFA;
    float* BB   = sm + OFF_BUFB;
    float* SMT  = sm + OFF_SMT;
    float* ST   = sm + OFF_ST;
    float* ZP   = sm + OFF_ZP;
    float* AP   = sm + OFF_AP;
    float* DISP = sm + OFF_DISP;
    float* GV   = sm + OFF_GV;

    const int tid  = threadIdx.x;
    const int g    = blockIdx.x >> 1;
    const int base = g * NPG;
    const int lane = tid & 31;
    const int w    = tid >> 5;              // 0..23
    const int c32  = lane;

    unsigned int rank;
    asm("mov.u32 %0, %%cluster_ctarank;" : "=r"(rank));
    const int row0 = (int)rank * HALF;
    unsigned int rbase;
    {
        unsigned int lbase = smem_u32(sm);
        unsigned int peer = rank ^ 1u;
        asm("mapa.shared::cluster.u32 %0, %1, %2;" : "=r"(rbase) : "r"(lbase), "r"(peer));
    }

    // ---------- Stage x (BUFB) and W1 (SMT scratch) early ----------
    {
        float* wst = sm + OFF_SMT;
        float* xs  = BB;
        for (int idx = tid; idx < HALF * NFEAT; idx += TPB)
            xs[idx] = x[(size_t)(base + row0 + (idx >> 7)) * NFEAT + (idx & 127)];
        for (int idx = tid; idx < NFEAT * HID; idx += TPB) wst[idx] = W1[idx];
    }
    if (tid < 128) { BA[NPG * HID + tid] = 0.f; BB[NPG * HID + tid] = 0.f; }

    // ---------- Phase A: build CSR (neighbors + self), degrees; 4 row-slots/warp ----------
    {
        float vv[4][5];
#pragma unroll
        for (int r = 0; r < 4; ++r) {
            int l = min(w + NW * r, HALF - 1);
            const float* arow = a + (size_t)(base + row0 + l) * NTOT + base;
#pragma unroll
            for (int ch = 0; ch < 5; ++ch) {
                int col = ch * 32 + lane;
                vv[r][ch] = (col < NPG) ? arow[col] : 0.f;
            }
        }
#pragma unroll
        for (int r = 0; r < 4; ++r) {
            int l = w + NW * r;
            if (l < HALF) {
                int self = row0 + l;
                int cnt = 0;
#pragma unroll
                for (int ch = 0; ch < 5; ++ch) {
                    int col = ch * 32 + lane;
                    bool nz = (col < NPG) && (vv[r][ch] != 0.f || col == self);
                    unsigned m = __ballot_sync(0xffffffffu, nz);
                    if (nz) {
                        int p = cnt + __popc(m & ((1u << lane) - 1u));
                        if (p < MAXC) COLS[l * MAXC + p] = col;
                    }
                    cnt += __popc(m);
                }
                int cc = min(cnt, MAXC);
                for (int kk = cc + lane; kk < MAXC; kk += 32) COLS[l * MAXC + kk] = NPG;
                if (lane == 0) { DISL[l] = rsqrtf((float)cnt); RCNT[l] = cc; }
            }
        }
    }
    __syncthreads();

    // ---------- Phase B: BA[j][h] = dis[j]*(x[j].W1[:,h]); 15 warps x 5 rows, full k ----------
    if (w < 15) {
        float* wst = sm + OFF_SMT;
        float* xs  = BB;
        const int r0 = w * 5;
        unsigned long long acc[5] = {0ull, 0ull, 0ull, 0ull, 0ull};
        for (int k = 0; k < NFEAT; k += 4) {
            unsigned long long w0 = *(const unsigned long long*)(wst + (k + 0) * HID + 2 * lane);
            unsigned long long w1 = *(const unsigned long long*)(wst + (k + 1) * HID + 2 * lane);
            unsigned long long w2 = *(const unsigned long long*)(wst + (k + 2) * HID + 2 * lane);
            unsigned long long w3 = *(const unsigned long long*)(wst + (k + 3) * HID + 2 * lane);
#pragma unroll
            for (int r = 0; r < 5; ++r) {
                float4 xv = *(const float4*)(xs + (r0 + r) * NFEAT + k);
                fma2(acc[r], xv.x, w0);
                fma2(acc[r], xv.y, w1);
                fma2(acc[r], xv.z, w2);
                fma2(acc[r], xv.w, w3);
            }
        }
#pragma unroll
        for (int r = 0; r < 5; ++r) {
            int l = r0 + r;
            float2 m = unpack2(acc[r]);
            float d = DISL[l];
            float vx = m.x * d, vy = m.y * d;
            int fo = OFF_BUFA + (row0 + l) * HID + 2 * lane;
            *(float2*)(sm + fo) = make_float2(vx, vy);
            st_rem2(rbase + 4u * (unsigned int)fo, vx, vy);
        }
    }
    CLUSTER_SYNC();

    // ---------- Phase C1 (warps 0-14, local) ∥ stage W2 (warps 15-23) ----------
    agg_sp<true, false>(sm, COLS, RCNT, DISL, OFF_BUFA, OFF_BUFB, b1, tid, row0, rbase, 0);
    if (w >= 15) {
        float* wfl = sm + OFF_SMT;   // W2 64*64 = 4096 (scratch free: B done)
        for (int idx = tid - 480; idx < HID * HID; idx += 288) wfl[idx] = W2[idx];
    }
    __syncthreads();

    // ---------- Phase D: BA[j][h] = dis[j]*(Z1[j].W2[:,h]); 15 warps x 5 rows ----------
    if (w < 15) {
        float* wfl = sm + OFF_SMT;
        const int r0 = w * 5;
        unsigned long long acc[5] = {0ull, 0ull, 0ull, 0ull, 0ull};
        for (int k = 0; k < HID; k += 4) {
            unsigned long long w0 = *(const unsigned long long*)(wfl + (k + 0) * HID + 2 * lane);
            unsigned long long w1 = *(const unsigned long long*)(wfl + (k + 1) * HID + 2 * lane);
            unsigned long long w2 = *(const unsigned long long*)(wfl + (k + 2) * HID + 2 * lane);
            unsigned long long w3 = *(const unsigned long long*)(wfl + (k + 3) * HID + 2 * lane);
#pragma unroll
            for (int r = 0; r < 5; ++r) {
                float4 zv = *(const float4*)(BB + (row0 + r0 + r) * HID + k);
                fma2(acc[r], zv.x, w0);
                fma2(acc[r], zv.y, w1);
                fma2(acc[r], zv.z, w2);
                fma2(acc[r], zv.w, w3);
            }
        }
#pragma unroll
        for (int r = 0; r < 5; ++r) {
            int l = r0 + r;
            float2 m = unpack2(acc[r]);
            float d = DISL[l];
            float vx = m.x * d, vy = m.y * d;
            int fo = OFF_BUFA + (row0 + l) * HID + 2 * lane;
            *(float2*)(sm + fo) = make_float2(vx, vy);
            st_rem2(rbase + 4u * (unsigned int)fo, vx, vy);
        }
    }
    CLUSTER_SYNC();

    // ---------- Phase C2 (warps 0-14, local; rank1 mirrors row 75 only) ∥ stage Wa + pads ----------
    agg_sp<true, false>(sm, COLS, RCNT, DISL, OFF_BUFA, OFF_BUFB, b2, tid, row0, rbase,
                        (rank == 1) ? 1 : 0);
    if (w >= 15) {
        int t = tid - 480;
        for (int idx = t; idx < HID * CL; idx += 288) ZP[idx] = Wa[idx];
        if (t < 2 * CP) SMT[NPG * CP + t] = 0.f;
        if (t < 2 * CL) ST[(t >> 1) * 152 + NPG + (t & 1)] = 0.f;
    }
    __syncthreads();

    // ---------- Phase E: tmpS[j][c] = dis[j]*(Z2[j].Wa[:,c]); 15 warps x 5 rows -> SMT both ----------
    if (w < 15) {
        const int cidx = min(c32, CL - 1);
        const int l0 = w * 5;
        float acc[5] = {0.f, 0.f, 0.f, 0.f, 0.f};
        for (int k = 0; k < HID; k += 4) {
            float w0 = ZP[(k + 0) * CL + cidx];
            float w1 = ZP[(k + 1) * CL + cidx];
            float w2 = ZP[(k + 2) * CL + cidx];
            float w3 = ZP[(k + 3) * CL + cidx];
#pragma unroll
            for (int r = 0; r < 5; ++r) {
                float4 zv = *(const float4*)(BB + (row0 + l0 + r) * HID + k);
                acc[r] += zv.x * w0 + zv.y * w1 + zv.z * w2 + zv.w * w3;
            }
        }
        if (c32 < CL) {
#pragma unroll
            for (int r = 0; r < 5; ++r) {
                int l = l0 + r;
                float v = acc[r] * DISL[l];
                int fo = OFF_SMT + (row0 + l) * CP + c32;
                sm[fo] = v;
                st_rem(rbase + 4u * (unsigned int)fo, v);
            }
        }
    }
    CLUSTER_SYNC();

    // ---------- Phase F+G: logits (sparse, predicated) + warp softmax -> S into BA both + ST both ----------
    if (w < 15) {
        const int cidx = min(c32, CL - 1);
        const int l0 = w * 5;
        const int rb = l0 * MAXC;
        int cnt[5];
#pragma unroll
        for (int r = 0; r < 5; ++r) cnt[r] = RCNT[l0 + r];
        int kmax = cnt[0];
#pragma unroll
        for (int r = 1; r < 5; ++r) kmax = max(kmax, cnt[r]);
        float acc[5] = {0.f, 0.f, 0.f, 0.f, 0.f};
        for (int k = 0; k < kmax; k += 4) {
#pragma unroll
            for (int r = 0; r < 5; ++r) {
                if (k < cnt[r]) {
                    int4 c4 = *(const int4*)(COLS + rb + r * MAXC + k);
                    acc[r] += SMT[c4.x * CP + c32] + SMT[c4.y * CP + c32]
                            + SMT[c4.z * CP + c32] + SMT[c4.w * CP + c32];
                }
            }
        }
        float bac = ba[cidx];
#pragma unroll
        for (int r = 0; r < 5; ++r) {
            int l = l0 + r;
            float logit = DISL[l] * acc[r] + bac;
            float mv = (c32 < CL) ? logit : -3.0e38f;
#pragma unroll
            for (int off = 16; off; off >>= 1)
                mv = fmaxf(mv, __shfl_xor_sync(0xffffffffu, mv, off));
            float e = (c32 < CL) ? expf(logit - mv) : 0.f;
            float s = e;
#pragma unroll
            for (int off = 16; off; off >>= 1)
                s += __shfl_xor_sync(0xffffffffu, s, off);
            float sv = e * (1.f / s);
            if (c32 < CL) {
                int gi = row0 + l;
                int fo = OFF_BUFA + gi * HID + c32;
                sm[fo] = sv;
                st_rem(rbase + 4u * (unsigned int)fo, sv);
                int ft = OFF_ST + c32 * 152 + gi;
                sm[ft] = sv;
                st_rem(rbase + 4u * (unsigned int)ft, sv);
            }
        }
    }
    CLUSTER_SYNC();

    // ---------- Phase I (warps 0-14) ∥ Phase H-partial (warps 15-23, BOTH ranks) ----------
    float2 hacc[3];
    hacc[0] = hacc[1] = hacc[2] = make_float2(0.f, 0.f);
    const int wh = w - 15;
    const int cb = wh * 3;   // c block: wh<8 -> 3 c's, wh==8 -> c=24 only
    if (w < 15) {
        // I: AS[i][c] = sum_cols S[col][c] - S[i][c] (S in BA) -> SMT both. 5 rows, predicated.
        const int l0 = w * 5;
        const int rb = l0 * MAXC;
        int cnt[5];
#pragma unroll
        for (int r = 0; r < 5; ++r) cnt[r] = RCNT[l0 + r];
        int kmax = cnt[0];
#pragma unroll
        for (int r = 1; r < 5; ++r) kmax = max(kmax, cnt[r]);
        float acc[5] = {0.f, 0.f, 0.f, 0.f, 0.f};
        for (int k = 0; k < kmax; k += 4) {
#pragma unroll
            for (int r = 0; r < 5; ++r) {
                if (k < cnt[r]) {
                    int4 c4 = *(const int4*)(COLS + rb + r * MAXC + k);
                    acc[r] += BA[c4.x * HID + c32] + BA[c4.y * HID + c32]
                            + BA[c4.z * HID + c32] + BA[c4.w * HID + c32];
                }
            }
        }
        if (c32 < CL) {
#pragma unroll
            for (int r = 0; r < 5; ++r) {
                int gi = row0 + l0 + r;
                float v = acc[r] - BA[gi * HID + c32];
                int fo = OFF_SMT + gi * CP + c32;
                sm[fo] = v;
                st_rem(rbase + 4u * (unsigned int)fo, v);
            }
        }
    } else {
        // H-partial: Zp_part[c][h] = sum_{j in own 76-half} S_T[c][j] * Z2[j][h]
        // rank0: j=0..75 (row 75 mirrored by rank1's C2); rank1: j=76..151 (rows 150/151 zero).
        const int j0 = (rank == 0) ? 0 : 76;
        for (int jj = 0; jj < 76; jj += 4) {
            int j = j0 + jj;
            float2 z0 = *(const float2*)(BB + (j + 0) * HID + 2 * lane);
            float2 z1 = *(const float2*)(BB + (j + 1) * HID + 2 * lane);
            float2 z2 = *(const float2*)(BB + (j + 2) * HID + 2 * lane);
            float2 z3 = *(const float2*)(BB + (j + 3) * HID + 2 * lane);
#pragma unroll
            for (int o = 0; o < 3; ++o) {
                int c = cb + o;
                if (c < CL) {
                    float4 s = *(const float4*)(ST + c * 152 + j);
                    hacc[o].x += s.x * z0.x + s.y * z1.x + s.z * z2.x + s.w * z3.x;
                    hacc[o].y += s.x * z0.y + s.y * z1.y + s.z * z2.y + s.w * z3.y;
                }
            }
        }
        // write own partial into PEER's ZP
#pragma unroll
        for (int o = 0; o < 3; ++o) {
            int c = cb + o;
            if (c < CL) {
                int fo = OFF_ZP + c * HID + 2 * lane;
                st_rem2(rbase + 4u * (unsigned int)fo, hacc[o].x, hacc[o].y);
            }
        }
    }
    CLUSTER_SYNC();

    // ---------- H-add (warps 15-23): ZP = peer partial (stored) + own partial (regs) ----------
    if (w >= 15) {
#pragma unroll
        for (int o = 0; o < 3; ++o) {
            int c = cb + o;
            if (c < CL) {
                int fo = OFF_ZP + c * HID + 2 * lane;
                float2 p = *(const float2*)(sm + fo);
                *(float2*)(sm + fo) = make_float2(p.x + hacc[o].x, p.y + hacc[o].y);
            }
        }
    }
    // ---------- Phase J (redundant, local) ∥ stage Wp -> BB ----------
    if (tid < CL * CL) {
        int cc = tid / CL, d = tid - cc * CL;
        float acc = 0.f;
        for (int j = 0; j < 152; j += 4) {
            float4 s = *(const float4*)(ST + cc * 152 + j);
            acc += s.x * SMT[(j + 0) * CP + d] + s.y * SMT[(j + 1) * CP + d]
                 + s.z * SMT[(j + 2) * CP + d] + s.w * SMT[(j + 3) * CP + d];
        }
        AP[cc * CP + d] = acc;
    }
    if (tid >= 640) {
        for (int idx = tid - 640; idx < HID * HID; idx += 128) BB[idx] = Wp[idx];
    }
    __syncthreads();

    // ---------- Phase K: pooled degrees (redundant) ----------
    if (tid < CL) {
        float s = 1.0f;
        for (int d = 0; d < CL; ++d) s += AP[tid * CP + d];
        DISP[tid] = rsqrtf(fmaxf(s, 1e-12f));
    }
    __syncthreads();

    // ---------- Phase L: BA[c][h] = disp[c]*(Zp[c].Wp[:,h]) (redundant; Wp in BB) ----------
    for (int idx = tid; idx < CL * HID; idx += TPB) {
        int cc = idx >> 6, hh = idx & 63;
        float acc = 0.f;
        for (int k = 0; k < HID; k += 4) {
            float4 zv = *(const float4*)(ZP + cc * HID + k);
            acc += zv.x * BB[(k + 0) * HID + hh] + zv.y * BB[(k + 1) * HID + hh]
                 + zv.z * BB[(k + 2) * HID + hh] + zv.w * BB[(k + 3) * HID + hh];
        }
        BA[cc * HID + hh] = acc * DISP[cc];
    }
    __syncthreads();

    // ---------- Phase M: Hp = relu(disp[i]*sum_c (Ap+I)[i][c]*BA[c][h] + bp) -> ZP ----------
    for (int idx = tid; idx < CL * HID; idx += TPB) {
        int i = idx >> 6, hh = idx & 63;
        float acc = 0.f;
#pragma unroll
        for (int cc = 0; cc < CL; ++cc) {
            float av = AP[i * CP + cc] + ((i == cc) ? 1.f : 0.f);
            acc += av * BA[cc * HID + hh];
        }
        ZP[i * HID + hh] = fmaxf(DISP[i] * acc + bp[hh], 0.f);
    }
    __syncthreads();

    // ---------- Phase N: readout ----------
    if (tid < HID) {
        float s = 0.f;
#pragma unroll
        for (int i = 0; i < CL; ++i) s += ZP[i * HID + tid];
        GV[tid] = s;
    }
    __syncthreads();

    // ---------- Phase O: logits (rank 0 writes) ----------
    if (rank == 0 && tid < NCLS) {
        float acc = bc[tid];
#pragma unroll
        for (int k = 0; k < HID; ++k) acc += GV[k] * Wc[k * NCLS + tid];
        out[g * NCLS + tid] = acc;
    }
}

extern "C" void kernel_launch(void* const* d_in, const int* in_sizes, int n_in,
                              void* d_out, int out_size)
{
    const float* x  = (const float*)d_in[0];
    const float* a  = (const float*)d_in[1];
    const float* W1 = (const float*)d_in[4];
    const float* b1 = (const float*)d_in[5];
    const float* W2 = (const float*)d_in[6];
    const float* b2 = (const float*)d_in[7];
    const float* Wa = (const float*)d_in[8];
    const float* ba = (const float*)d_in[9];
    const float* Wp = (const float*)d_in[10];
    const float* bp = (const float*)d_in[11];
    const float* Wc = (const float*)d_in[12];
    const float* bc = (const float*)d_in[13];
    float* out = (float*)d_out;

    int B = out_size / NCLS;   // 64 graphs
    size_t smem = (size_t)SMEM_FLOATS * sizeof(float);
    cudaFuncSetAttribute(gcn_diffpool, cudaFuncAttributeMaxDynamicSharedMemorySize, (int)smem);
    gcn_diffpool<<<B * 2, TPB, smem>>>(x, a, W1, b1, W2, b2, Wa, ba, Wp, bp, Wc, bc, out);
}